// round 1
// baseline (speedup 1.0000x reference)
#include <cuda_runtime.h>
#include <cstdint>

#define Bdim 16
#define Sdim 256
#define Hdim 768
#define Ddim 64
#define NSLOT 128  // 16 batches * 8 slots (max aspect span is 6 rows)

// Scratch (device globals; no allocation allowed)
__device__ float g_u1[Hdim];              // Wz @ w1
__device__ float g_u2[Hdim];              // Wz @ w2
__device__ float g_c[2];                  // bz.w1, bz.w2
__device__ float g_t2[Bdim * Sdim];       // (z @ w2)[b,j]
__device__ float g_X1[2 * NSLOT * Hdim];  // rows 0..127: v (attn-weighted bert); 128..255: bert_next
__device__ float g_X2[NSLOT * (Hdim + Ddim)];  // [agg_z | agg_d]
__device__ float g_X3[NSLOT * (2 * Hdim)];     // [nrep | zrow]
__device__ int g_valid[NSLOT];
__device__ int g_rowi[NSLOT];

__device__ __forceinline__ float warpReduceSum(float v) {
#pragma unroll
  for (int o = 16; o > 0; o >>= 1) v += __shfl_down_sync(0xffffffffu, v, o);
  return v;
}

__device__ __forceinline__ float blockReduceSum(float v, float* sm) {
  v = warpReduceSum(v);
  int w = threadIdx.x >> 5;
  if ((threadIdx.x & 31) == 0) sm[w] = v;
  __syncthreads();
  if (threadIdx.x < 8) {
    float x = sm[threadIdx.x];
#pragma unroll
    for (int o = 4; o > 0; o >>= 1) x += __shfl_down_sync(0xffu, x, o);
    if (threadIdx.x == 0) sm[0] = x;
  }
  __syncthreads();
  float r = sm[0];
  __syncthreads();
  return r;
}

__device__ __forceinline__ float blockReduceMax(float v, float* sm) {
#pragma unroll
  for (int o = 16; o > 0; o >>= 1) v = fmaxf(v, __shfl_down_sync(0xffffffffu, v, o));
  int w = threadIdx.x >> 5;
  if ((threadIdx.x & 31) == 0) sm[w] = v;
  __syncthreads();
  if (threadIdx.x < 8) {
    float x = sm[threadIdx.x];
#pragma unroll
    for (int o = 4; o > 0; o >>= 1) x = fmaxf(x, __shfl_down_sync(0xffu, x, o));
    if (threadIdx.x == 0) sm[0] = x;
  }
  __syncthreads();
  float r = sm[0];
  __syncthreads();
  return r;
}

// u1 = Wz @ w1, u2 = Wz @ w2, c = (bz.w1, bz.w2). grid 769, block 256.
__global__ void k_pre(const float* __restrict__ Wz, const float* __restrict__ bz,
                      const float* __restrict__ watt) {
  __shared__ float sm[8];
  int h = blockIdx.x, tid = threadIdx.x;
  float a1 = 0.f, a2 = 0.f;
  if (h < Hdim) {
    const float* wr = Wz + (size_t)h * Hdim;
    for (int k = tid; k < Hdim; k += 256) {
      float wv = wr[k];
      a1 = fmaf(wv, watt[k], a1);
      a2 = fmaf(wv, watt[Hdim + k], a2);
    }
  } else {
    for (int k = tid; k < Hdim; k += 256) {
      float bv = bz[k];
      a1 = fmaf(bv, watt[k], a1);
      a2 = fmaf(bv, watt[Hdim + k], a2);
    }
  }
  float r1 = blockReduceSum(a1, sm);
  float r2 = blockReduceSum(a2, sm);
  if (tid == 0) {
    if (h < Hdim) {
      g_u1[h] = r1;
      g_u2[h] = r2;
    } else {
      g_c[0] = r1;
      g_c[1] = r2;
    }
  }
}

// t2[b*S+j] = bert[b,j] @ u2 + bz.w2  (equals (z@w2)[b,j]). grid 512, block 256 (warp/row).
__global__ void k_t2(const float* __restrict__ bert) {
  int r = blockIdx.x * 8 + (threadIdx.x >> 5);
  int lane = threadIdx.x & 31;
  const float* br = bert + (size_t)r * Hdim;
  float a = 0.f;
  for (int k = lane; k < Hdim; k += 32) a = fmaf(br[k], g_u2[k], a);
  a = warpReduceSum(a);
  if (lane == 0) g_t2[r] = a + g_c[1];
}

// Per needed row: logits + softmax + agg_d + v (attn-weighted bert) + bert_next.
// grid (16, 8), block 256.
__global__ void k_main(const float* __restrict__ bert, const float* __restrict__ dta,
                       const int* __restrict__ deprel, const int* __restrict__ asp_s,
                       const int* __restrict__ asp_e, const float* __restrict__ w_att,
                       const float* __restrict__ b_att) {
  int b = blockIdx.x, il = blockIdx.y;
  int slot = b * 8 + il;
  int tid = threadIdx.x;
  __shared__ float sm_s[Sdim];
  __shared__ float sm_p[Sdim];
  __shared__ float sm_red[8];
  int start = asp_s[b], endi = asp_e[b];
  int i = start + il;
  bool active = (i <= endi) && (i < Sdim);
  const int* deprow = deprel + (size_t)(b * Sdim + (active ? i : 0)) * Sdim;
  int hasn = 0;
  if (active) hasn = (deprow[tid] > 0);
  int any = __syncthreads_or(hasn);
  if (!active || !any) {
    for (int h = tid; h < Hdim; h += 256) {
      g_X1[slot * Hdim + h] = 0.f;
      g_X1[(NSLOT + slot) * Hdim + h] = 0.f;
    }
    if (tid < Ddim) g_X2[slot * (Hdim + Ddim) + Hdim + tid] = 0.f;
    if (tid == 0) {
      g_valid[slot] = 0;
      g_rowi[slot] = 0;
    }
    return;
  }

  int inext = (i + 1) & (Sdim - 1);
  const float* bi = bert + (size_t)(b * Sdim + inext) * Hdim;

  // s1 = (zs @ w1)[b,i] = bert[b,i+1] @ u1 + bz.w1
  float a = 0.f;
  for (int h = tid; h < Hdim; h += 256) a = fmaf(bi[h], g_u1[h], a);
  float s1 = blockReduceSum(a, sm_red);
  float base = s1 + g_c[0] + b_att[0];

  // logits: warp w handles j in [w*32, w*32+32)
  int w = tid >> 5, lane = tid & 31;
  float w3a = w_att[2 * Hdim + lane];
  float w3b = w_att[2 * Hdim + 32 + lane];
  const float* drow = dta + (size_t)(b * Sdim + i) * Sdim * Ddim;
  for (int j = w * 32; j < w * 32 + 32; ++j) {
    const float* dj = drow + (size_t)j * Ddim;
    float acc = dj[lane] * w3a + dj[lane + 32] * w3b;
    acc = warpReduceSum(acc);
    if (lane == 0) {
      float s = base + g_t2[b * Sdim + ((j + 1) & (Sdim - 1))] + acc;
      s = (s >= 0.f) ? s : 0.01f * s;
      if (deprow[j] <= 0) s = -1e9f;
      sm_s[j] = s;
    }
  }
  __syncthreads();

  // softmax over j
  float sv = sm_s[tid];
  float m = blockReduceMax(sv, sm_red);
  float e = expf(sv - m);
  float sum = blockReduceSum(e, sm_red);
  sm_p[tid] = e / sum;
  __syncthreads();

  // agg_d[d] = sum_j p[j] * dta[b,i,j,d]  (dta row is L2-hot from pass 1)
  {
    int d = tid & 63, part = tid >> 6;
    float ad = 0.f;
    const float* dp = drow + (size_t)(part * 64) * Ddim + d;
    for (int j = 0; j < 64; ++j) ad = fmaf(sm_p[part * 64 + j], dp[(size_t)j * Ddim], ad);
    sm_s[tid] = ad;
    __syncthreads();
    if (part == 0) {
      float t = sm_s[d] + sm_s[64 + d] + sm_s[128 + d] + sm_s[192 + d];
      g_X2[slot * (Hdim + Ddim) + Hdim + d] = t;
    }
  }

  // v[h] = sum_j p[j] * bert[b, (j+1)%S, h]
  float v0 = 0.f, v1 = 0.f, v2 = 0.f;
#pragma unroll 4
  for (int j = 0; j < Sdim; ++j) {
    float p = sm_p[j];
    const float* br = bert + (size_t)(b * Sdim + ((j + 1) & (Sdim - 1))) * Hdim;
    v0 = fmaf(p, br[tid], v0);
    v1 = fmaf(p, br[tid + 256], v1);
    v2 = fmaf(p, br[tid + 512], v2);
  }
  g_X1[slot * Hdim + tid] = v0;
  g_X1[slot * Hdim + tid + 256] = v1;
  g_X1[slot * Hdim + tid + 512] = v2;
  g_X1[(NSLOT + slot) * Hdim + tid] = bi[tid];
  g_X1[(NSLOT + slot) * Hdim + tid + 256] = bi[tid + 256];
  g_X1[(NSLOT + slot) * Hdim + tid + 512] = bi[tid + 512];
  if (tid == 0) {
    g_valid[slot] = 1;
    g_rowi[slot] = i;
  }
}

// Row-blocked GEMV chain. Block 256: 4 groups of 64 cols, each group owns 4 rows.
// MODE 0: [v; bert_next](256xH) @ Wz + bz -> agg_z (into X2 cols 0..767) / zrow (into X3 cols 768..1535)
// MODE 1: X2(128x832) @ Wf -> nrep (into X3 cols 0..767)
// MODE 2: X3(128x1536) @ Wh -> temp, scattered to out rows (i+1) for valid slots
template <int MODE>
__global__ void k_gemm(const float* __restrict__ W, const float* __restrict__ bias,
                       float* __restrict__ outp) {
  constexpr int K = (MODE == 0) ? Hdim : (MODE == 1) ? (Hdim + Ddim) : (2 * Hdim);
  const float* X = (MODE == 0) ? g_X1 : (MODE == 1) ? g_X2 : g_X3;
  int hb = blockIdx.x, rb = blockIdx.y;
  int tid = threadIdx.x;
  int col = tid & 63, g = tid >> 6;
  int h = hb * 64 + col;
  int r = rb * 16 + g * 4;
  const float* x0 = X + (size_t)r * K;
  const float* x1 = x0 + K;
  const float* x2 = x1 + K;
  const float* x3 = x2 + K;
  const float* wp = W + h;
  float a0 = 0.f, a1 = 0.f, a2 = 0.f, a3 = 0.f;
#pragma unroll 4
  for (int k = 0; k < K; ++k) {
    float wv = wp[(size_t)k * Hdim];
    a0 = fmaf(x0[k], wv, a0);
    a1 = fmaf(x1[k], wv, a1);
    a2 = fmaf(x2[k], wv, a2);
    a3 = fmaf(x3[k], wv, a3);
  }
  float acc[4] = {a0, a1, a2, a3};
  if (MODE == 0) {
    float bb = bias[h];
#pragma unroll
    for (int q = 0; q < 4; ++q) {
      int rr = r + q;
      float val = acc[q] + bb;
      if (rr < NSLOT)
        g_X2[rr * (Hdim + Ddim) + h] = val;  // agg_z
      else
        g_X3[(rr - NSLOT) * (2 * Hdim) + Hdim + h] = val;  // zrow
    }
  } else if (MODE == 1) {
#pragma unroll
    for (int q = 0; q < 4; ++q) g_X3[(r + q) * (2 * Hdim) + h] = acc[q];  // nrep
  } else {
#pragma unroll
    for (int q = 0; q < 4; ++q) {
      int rr = r + q;
      if (g_valid[rr]) {
        int bb = rr >> 3;
        int o = (g_rowi[rr] + 1) & (Sdim - 1);
        outp[((size_t)(bb * Sdim + o)) * Hdim + h] = acc[q];
      }
    }
  }
}

extern "C" void kernel_launch(void* const* d_in, const int* in_sizes, int n_in,
                              void* d_out, int out_size) {
  const float* bert = (const float*)d_in[0];
  const float* dta = (const float*)d_in[1];
  const int* deprel = (const int*)d_in[2];
  const int* asp_s = (const int*)d_in[3];
  const int* asp_e = (const int*)d_in[4];
  const float* Wz = (const float*)d_in[5];
  const float* bz = (const float*)d_in[6];
  const float* watt = (const float*)d_in[7];
  const float* batt = (const float*)d_in[8];
  const float* Wf = (const float*)d_in[9];
  const float* Wh = (const float*)d_in[10];
  float* out = (float*)d_out;

  // Bulk of the output is a verbatim copy of bert_hidden_states.
  cudaMemcpyAsync(out, bert, (size_t)Bdim * Sdim * Hdim * sizeof(float),
                  cudaMemcpyDeviceToDevice, 0);
  k_pre<<<769, 256>>>(Wz, bz, watt);
  k_t2<<<(Bdim * Sdim) / 8, 256>>>(bert);
  k_main<<<dim3(Bdim, 8), 256>>>(bert, dta, deprel, asp_s, asp_e, watt, batt);
  k_gemm<0><<<dim3(12, 16), 256>>>(Wz, bz, nullptr);
  k_gemm<1><<<dim3(12, 8), 256>>>(Wf, nullptr, nullptr);
  k_gemm<2><<<dim3(12, 8), 256>>>(Wh, nullptr, out);
}

// round 2
// speedup vs baseline: 1.0858x; 1.0858x over previous
#include <cuda_runtime.h>
#include <cstdint>

#define Bdim 16
#define Sdim 256
#define Hdim 768
#define Ddim 64
#define NSLOT 128  // 16 batches * 8 slots (max aspect span is 6 rows)

// Scratch (device globals; no allocation allowed)
__device__ float g_u1[Hdim];              // Wz @ w1
__device__ float g_u2[Hdim];              // Wz @ w2
__device__ float g_c[2];                  // bz.w1, bz.w2
__device__ float g_t2[Bdim * Sdim];       // (z @ w2)[b,j]
__device__ float g_X1[2 * NSLOT * Hdim];  // rows 0..127: v (attn-weighted bert); 128..255: bert_next
__device__ float g_X2[NSLOT * (Hdim + Ddim)];  // [agg_z | agg_d]
__device__ float g_X3[NSLOT * (2 * Hdim)];     // [nrep | zrow]
__device__ int g_valid[NSLOT];
__device__ int g_rowi[NSLOT];

__device__ __forceinline__ float warpReduceSum(float v) {
#pragma unroll
  for (int o = 16; o > 0; o >>= 1) v += __shfl_down_sync(0xffffffffu, v, o);
  return v;
}

__device__ __forceinline__ float blockReduceSum(float v, float* sm) {
  v = warpReduceSum(v);
  int w = threadIdx.x >> 5;
  if ((threadIdx.x & 31) == 0) sm[w] = v;
  __syncthreads();
  if (threadIdx.x < 8) {
    float x = sm[threadIdx.x];
#pragma unroll
    for (int o = 4; o > 0; o >>= 1) x += __shfl_down_sync(0xffu, x, o);
    if (threadIdx.x == 0) sm[0] = x;
  }
  __syncthreads();
  float r = sm[0];
  __syncthreads();
  return r;
}

__device__ __forceinline__ float blockReduceMax(float v, float* sm) {
#pragma unroll
  for (int o = 16; o > 0; o >>= 1) v = fmaxf(v, __shfl_down_sync(0xffffffffu, v, o));
  int w = threadIdx.x >> 5;
  if ((threadIdx.x & 31) == 0) sm[w] = v;
  __syncthreads();
  if (threadIdx.x < 8) {
    float x = sm[threadIdx.x];
#pragma unroll
    for (int o = 4; o > 0; o >>= 1) x = fmaxf(x, __shfl_down_sync(0xffu, x, o));
    if (threadIdx.x == 0) sm[0] = x;
  }
  __syncthreads();
  float r = sm[0];
  __syncthreads();
  return r;
}

// u1 = Wz @ w1, u2 = Wz @ w2, c = (bz.w1, bz.w2). grid 769, block 256.
__global__ void k_pre(const float* __restrict__ Wz, const float* __restrict__ bz,
                      const float* __restrict__ watt) {
  __shared__ float sm[8];
  int h = blockIdx.x, tid = threadIdx.x;
  float a1 = 0.f, a2 = 0.f;
  if (h < Hdim) {
    const float* wr = Wz + (size_t)h * Hdim;
    for (int k = tid; k < Hdim; k += 256) {
      float wv = wr[k];
      a1 = fmaf(wv, watt[k], a1);
      a2 = fmaf(wv, watt[Hdim + k], a2);
    }
  } else {
    for (int k = tid; k < Hdim; k += 256) {
      float bv = bz[k];
      a1 = fmaf(bv, watt[k], a1);
      a2 = fmaf(bv, watt[Hdim + k], a2);
    }
  }
  float r1 = blockReduceSum(a1, sm);
  float r2 = blockReduceSum(a2, sm);
  if (tid == 0) {
    if (h < Hdim) {
      g_u1[h] = r1;
      g_u2[h] = r2;
    } else {
      g_c[0] = r1;
      g_c[1] = r2;
    }
  }
}

// t2[b*S+j] = bert[b,j] @ u2 + bz.w2  (equals (z@w2)[b,j]). grid 512, block 256 (warp/row).
__global__ void k_t2(const float* __restrict__ bert) {
  int r = blockIdx.x * 8 + (threadIdx.x >> 5);
  int lane = threadIdx.x & 31;
  const float4* br = (const float4*)(bert + (size_t)r * Hdim);
  float a = 0.f;
#pragma unroll 2
  for (int k = lane; k < Hdim / 4; k += 32) {
    float4 bv = br[k];
    float4 uv = ((const float4*)g_u2)[k];
    a = fmaf(bv.x, uv.x, a);
    a = fmaf(bv.y, uv.y, a);
    a = fmaf(bv.z, uv.z, a);
    a = fmaf(bv.w, uv.w, a);
  }
  a = warpReduceSum(a);
  if (lane == 0) g_t2[r] = a + g_c[1];
}

// Per needed row: logits + softmax + agg_d + v (attn-weighted bert) + bert_next.
// grid (16, 8), block 256.
__global__ void k_main(const float* __restrict__ bert, const float* __restrict__ dta,
                       const int* __restrict__ deprel, const int* __restrict__ asp_s,
                       const int* __restrict__ asp_e, const float* __restrict__ w_att,
                       const float* __restrict__ b_att) {
  int b = blockIdx.x, il = blockIdx.y;
  int slot = b * 8 + il;
  int tid = threadIdx.x;
  __shared__ float sm_s[Sdim];
  __shared__ float sm_p[Sdim];
  __shared__ float sm_red[8];
  int start = asp_s[b], endi = asp_e[b];
  int i = start + il;
  bool active = (i <= endi) && (i < Sdim);
  const int* deprow = deprel + (size_t)(b * Sdim + (active ? i : 0)) * Sdim;
  int hasn = 0;
  if (active) hasn = (deprow[tid] > 0);
  int any = __syncthreads_or(hasn);
  if (!active || !any) {
    for (int h = tid; h < Hdim; h += 256) {
      g_X1[slot * Hdim + h] = 0.f;
      g_X1[(NSLOT + slot) * Hdim + h] = 0.f;
    }
    if (tid < Ddim) g_X2[slot * (Hdim + Ddim) + Hdim + tid] = 0.f;
    if (tid == 0) {
      g_valid[slot] = 0;
      g_rowi[slot] = 0;
    }
    return;
  }

  int inext = (i + 1) & (Sdim - 1);
  const float* bi = bert + (size_t)(b * Sdim + inext) * Hdim;

  // s1 = (zs @ w1)[b,i] = bert[b,i+1] @ u1 + bz.w1
  float a = 0.f;
  for (int h = tid; h < Hdim; h += 256) a = fmaf(bi[h], g_u1[h], a);
  float s1 = blockReduceSum(a, sm_red);
  float base = s1 + g_c[0] + b_att[0];

  // logits: warp w handles j in [w*32, w*32+32)
  int w = tid >> 5, lane = tid & 31;
  float w3a = w_att[2 * Hdim + lane];
  float w3b = w_att[2 * Hdim + 32 + lane];
  const float* drow = dta + (size_t)(b * Sdim + i) * Sdim * Ddim;
  for (int j = w * 32; j < w * 32 + 32; ++j) {
    const float* dj = drow + (size_t)j * Ddim;
    float acc = dj[lane] * w3a + dj[lane + 32] * w3b;
    acc = warpReduceSum(acc);
    if (lane == 0) {
      float s = base + g_t2[b * Sdim + ((j + 1) & (Sdim - 1))] + acc;
      s = (s >= 0.f) ? s : 0.01f * s;
      if (deprow[j] <= 0) s = -1e9f;
      sm_s[j] = s;
    }
  }
  __syncthreads();

  // softmax over j
  float sv = sm_s[tid];
  float m = blockReduceMax(sv, sm_red);
  float e = expf(sv - m);
  float sum = blockReduceSum(e, sm_red);
  sm_p[tid] = e / sum;
  __syncthreads();

  // agg_d[d] = sum_j p[j] * dta[b,i,j,d]  (dta row is L2-hot from pass 1)
  {
    int d = tid & 63, part = tid >> 6;
    float ad = 0.f;
    const float* dp = drow + (size_t)(part * 64) * Ddim + d;
    for (int j = 0; j < 64; ++j) ad = fmaf(sm_p[part * 64 + j], dp[(size_t)j * Ddim], ad);
    sm_s[tid] = ad;
    __syncthreads();
    if (part == 0) {
      float t = sm_s[d] + sm_s[64 + d] + sm_s[128 + d] + sm_s[192 + d];
      g_X2[slot * (Hdim + Ddim) + Hdim + d] = t;
    }
  }

  // v[h] = sum_j p[j] * bert[b, (j+1)%S, h]
  float v0 = 0.f, v1 = 0.f, v2 = 0.f;
#pragma unroll 4
  for (int j = 0; j < Sdim; ++j) {
    float p = sm_p[j];
    const float* br = bert + (size_t)(b * Sdim + ((j + 1) & (Sdim - 1))) * Hdim;
    v0 = fmaf(p, br[tid], v0);
    v1 = fmaf(p, br[tid + 256], v1);
    v2 = fmaf(p, br[tid + 512], v2);
  }
  g_X1[slot * Hdim + tid] = v0;
  g_X1[slot * Hdim + tid + 256] = v1;
  g_X1[slot * Hdim + tid + 512] = v2;
  g_X1[(NSLOT + slot) * Hdim + tid] = bi[tid];
  g_X1[(NSLOT + slot) * Hdim + tid + 256] = bi[tid + 256];
  g_X1[(NSLOT + slot) * Hdim + tid + 512] = bi[tid + 512];
  if (tid == 0) {
    g_valid[slot] = 1;
    g_rowi[slot] = i;
  }
}

// Vectorized row-blocked GEMV chain. Block 256 = 16 col-threads (4 cols each,
// float4 W loads) x 16 row-threads (1 row each). X consumed as float4 over k.
// MODE 0: [v; bert_next](256xH) @ Wz + bz -> agg_z (X2 cols 0..767) / zrow (X3 cols 768..1535)
// MODE 1: X2(128x832) @ Wf -> nrep (X3 cols 0..767)
// MODE 2: X3(128x1536) @ Wh -> temp, scattered to out rows (i+1) for valid slots
template <int MODE>
__global__ void __launch_bounds__(256) k_gemm(const float* __restrict__ W,
                                              const float* __restrict__ bias,
                                              float* __restrict__ outp) {
  constexpr int K = (MODE == 0) ? Hdim : (MODE == 1) ? (Hdim + Ddim) : (2 * Hdim);
  constexpr int K4 = K / 4;
  const float* X = (MODE == 0) ? g_X1 : (MODE == 1) ? g_X2 : g_X3;
  int tid = threadIdx.x;
  int ct = tid & 15;   // col-thread
  int rt = tid >> 4;   // row-thread
  int h = blockIdx.x * 64 + ct * 4;
  int r = blockIdx.y * 16 + rt;

  const float4* __restrict__ x4 = (const float4*)(X + (size_t)r * K);
  const float4* __restrict__ w4 = (const float4*)W + (h >> 2);  // stride per k-row: Hdim/4 = 192

  float4 acc = make_float4(0.f, 0.f, 0.f, 0.f);
#pragma unroll 4
  for (int k4 = 0; k4 < K4; ++k4) {
    float4 xv = x4[k4];
    const float4* wp = w4 + (size_t)k4 * 4 * (Hdim / 4);
    float4 wa = wp[0];
    float4 wb = wp[Hdim / 4];
    float4 wc = wp[2 * (Hdim / 4)];
    float4 wd = wp[3 * (Hdim / 4)];
    acc.x = fmaf(xv.x, wa.x, acc.x);
    acc.y = fmaf(xv.x, wa.y, acc.y);
    acc.z = fmaf(xv.x, wa.z, acc.z);
    acc.w = fmaf(xv.x, wa.w, acc.w);
    acc.x = fmaf(xv.y, wb.x, acc.x);
    acc.y = fmaf(xv.y, wb.y, acc.y);
    acc.z = fmaf(xv.y, wb.z, acc.z);
    acc.w = fmaf(xv.y, wb.w, acc.w);
    acc.x = fmaf(xv.z, wc.x, acc.x);
    acc.y = fmaf(xv.z, wc.y, acc.y);
    acc.z = fmaf(xv.z, wc.z, acc.z);
    acc.w = fmaf(xv.z, wc.w, acc.w);
    acc.x = fmaf(xv.w, wd.x, acc.x);
    acc.y = fmaf(xv.w, wd.y, acc.y);
    acc.z = fmaf(xv.w, wd.z, acc.z);
    acc.w = fmaf(xv.w, wd.w, acc.w);
  }

  if (MODE == 0) {
    float4 bb = *(const float4*)(bias + h);
    acc.x += bb.x;
    acc.y += bb.y;
    acc.z += bb.z;
    acc.w += bb.w;
    if (r < NSLOT)
      *(float4*)(g_X2 + (size_t)r * (Hdim + Ddim) + h) = acc;  // agg_z
    else
      *(float4*)(g_X3 + (size_t)(r - NSLOT) * (2 * Hdim) + Hdim + h) = acc;  // zrow
  } else if (MODE == 1) {
    *(float4*)(g_X3 + (size_t)r * (2 * Hdim) + h) = acc;  // nrep
  } else {
    if (g_valid[r]) {
      int bb = r >> 3;
      int o = (g_rowi[r] + 1) & (Sdim - 1);
      *(float4*)(outp + ((size_t)(bb * Sdim + o)) * Hdim + h) = acc;
    }
  }
}

extern "C" void kernel_launch(void* const* d_in, const int* in_sizes, int n_in,
                              void* d_out, int out_size) {
  const float* bert = (const float*)d_in[0];
  const float* dta = (const float*)d_in[1];
  const int* deprel = (const int*)d_in[2];
  const int* asp_s = (const int*)d_in[3];
  const int* asp_e = (const int*)d_in[4];
  const float* Wz = (const float*)d_in[5];
  const float* bz = (const float*)d_in[6];
  const float* watt = (const float*)d_in[7];
  const float* batt = (const float*)d_in[8];
  const float* Wf = (const float*)d_in[9];
  const float* Wh = (const float*)d_in[10];
  float* out = (float*)d_out;

  // Bulk of the output is a verbatim copy of bert_hidden_states.
  cudaMemcpyAsync(out, bert, (size_t)Bdim * Sdim * Hdim * sizeof(float),
                  cudaMemcpyDeviceToDevice, 0);
  k_pre<<<769, 256>>>(Wz, bz, watt);
  k_t2<<<(Bdim * Sdim) / 8, 256>>>(bert);
  k_main<<<dim3(Bdim, 8), 256>>>(bert, dta, deprel, asp_s, asp_e, watt, batt);
  k_gemm<0><<<dim3(12, 16), 256>>>(Wz, bz, nullptr);
  k_gemm<1><<<dim3(12, 8), 256>>>(Wf, nullptr, nullptr);
  k_gemm<2><<<dim3(12, 8), 256>>>(Wh, nullptr, out);
}

// round 3
// speedup vs baseline: 1.9890x; 1.8319x over previous
#include <cuda_runtime.h>
#include <cstdint>

#define Bdim 16
#define Sdim 256
#define Hdim 768
#define Ddim 64
#define NSLOT 128  // 16 batches * 8 slots (max aspect span is 6 rows)
#define H4 (Hdim / 4)

// Scratch (device globals; no allocation allowed)
__device__ __align__(16) float g_u1[Hdim];              // Wz @ w1
__device__ __align__(16) float g_u2[Hdim];              // Wz @ w2
__device__ float g_c[2];                                // bz.w1, bz.w2
__device__ __align__(16) float g_t2[Bdim * Sdim];       // (z @ w2)[b,j]
__device__ __align__(16) float g_X1[2 * NSLOT * Hdim];  // rows 0..127: v; 128..255: bert_next
__device__ __align__(16) float g_X2[NSLOT * (Hdim + Ddim)];  // [agg_z | agg_d]
__device__ __align__(16) float g_X3[NSLOT * (2 * Hdim)];     // [nrep | zrow]
__device__ int g_valid[NSLOT];
__device__ int g_rowi[NSLOT];

__device__ __forceinline__ float warpReduceSum(float v) {
#pragma unroll
  for (int o = 16; o > 0; o >>= 1) v += __shfl_down_sync(0xffffffffu, v, o);
  return v;
}

__device__ __forceinline__ float blockReduceSum(float v, float* sm) {
  v = warpReduceSum(v);
  int w = threadIdx.x >> 5;
  if ((threadIdx.x & 31) == 0) sm[w] = v;
  __syncthreads();
  if (threadIdx.x < 8) {
    float x = sm[threadIdx.x];
#pragma unroll
    for (int o = 4; o > 0; o >>= 1) x += __shfl_down_sync(0xffu, x, o);
    if (threadIdx.x == 0) sm[0] = x;
  }
  __syncthreads();
  float r = sm[0];
  __syncthreads();
  return r;
}

__device__ __forceinline__ float blockReduceMax(float v, float* sm) {
#pragma unroll
  for (int o = 16; o > 0; o >>= 1) v = fmaxf(v, __shfl_down_sync(0xffffffffu, v, o));
  int w = threadIdx.x >> 5;
  if ((threadIdx.x & 31) == 0) sm[w] = v;
  __syncthreads();
  if (threadIdx.x < 8) {
    float x = sm[threadIdx.x];
#pragma unroll
    for (int o = 4; o > 0; o >>= 1) x = fmaxf(x, __shfl_down_sync(0xffu, x, o));
    if (threadIdx.x == 0) sm[0] = x;
  }
  __syncthreads();
  float r = sm[0];
  __syncthreads();
  return r;
}

// u1 = Wz @ w1, u2 = Wz @ w2, c = (bz.w1, bz.w2). grid 769, block 256.
__global__ void k_pre(const float* __restrict__ Wz, const float* __restrict__ bz,
                      const float* __restrict__ watt) {
  __shared__ float sm[8];
  int h = blockIdx.x, tid = threadIdx.x;
  float a1 = 0.f, a2 = 0.f;
  if (h < Hdim) {
    const float* wr = Wz + (size_t)h * Hdim;
    for (int k = tid; k < Hdim; k += 256) {
      float wv = wr[k];
      a1 = fmaf(wv, watt[k], a1);
      a2 = fmaf(wv, watt[Hdim + k], a2);
    }
  } else {
    for (int k = tid; k < Hdim; k += 256) {
      float bv = bz[k];
      a1 = fmaf(bv, watt[k], a1);
      a2 = fmaf(bv, watt[Hdim + k], a2);
    }
  }
  float r1 = blockReduceSum(a1, sm);
  float r2 = blockReduceSum(a2, sm);
  if (tid == 0) {
    if (h < Hdim) {
      g_u1[h] = r1;
      g_u2[h] = r2;
    } else {
      g_c[0] = r1;
      g_c[1] = r2;
    }
  }
}

// Fused: t2[r] = bert_row[r] @ u2 + bz.w2  AND  out[r] = bert_row[r] (bulk copy).
// grid 512, block 256 (one warp per row).
__global__ void k_t2(const float* __restrict__ bert, float* __restrict__ out) {
  int r = blockIdx.x * 8 + (threadIdx.x >> 5);
  int lane = threadIdx.x & 31;
  const float4* br = (const float4*)(bert + (size_t)r * Hdim);
  float4* orow = (float4*)(out + (size_t)r * Hdim);
  const float4* u24 = (const float4*)g_u2;
  float a = 0.f;
#pragma unroll
  for (int k = lane; k < H4; k += 32) {
    float4 bv = br[k];
    orow[k] = bv;
    float4 uv = u24[k];
    a = fmaf(bv.x, uv.x, a);
    a = fmaf(bv.y, uv.y, a);
    a = fmaf(bv.z, uv.z, a);
    a = fmaf(bv.w, uv.w, a);
  }
  a = warpReduceSum(a);
  if (lane == 0) g_t2[r] = a + g_c[1];
}

// Per needed row: logits + softmax + agg_d + v (attn-weighted bert) + bert_next.
// grid (16, 8), block 256.
__global__ void k_main(const float* __restrict__ bert, const float* __restrict__ dta,
                       const int* __restrict__ deprel, const int* __restrict__ asp_s,
                       const int* __restrict__ asp_e, const float* __restrict__ w_att,
                       const float* __restrict__ b_att) {
  int b = blockIdx.x, il = blockIdx.y;
  int slot = b * 8 + il;
  int tid = threadIdx.x;
  __shared__ float sm_s[Sdim];
  __shared__ float sm_p[Sdim];
  __shared__ float sm_red[8];
  int start = asp_s[b], endi = asp_e[b];
  int i = start + il;
  bool active = (i <= endi) && (i < Sdim);
  const int* deprow = deprel + (size_t)(b * Sdim + (active ? i : 0)) * Sdim;
  int hasn = 0;
  if (active) hasn = (deprow[tid] > 0);
  int any = __syncthreads_or(hasn);
  if (!active || !any) {
    for (int h = tid; h < Hdim; h += 256) {
      g_X1[slot * Hdim + h] = 0.f;
      g_X1[(NSLOT + slot) * Hdim + h] = 0.f;
    }
    if (tid < Ddim) g_X2[slot * (Hdim + Ddim) + Hdim + tid] = 0.f;
    if (tid == 0) {
      g_valid[slot] = 0;
      g_rowi[slot] = 0;
    }
    return;
  }

  int inext = (i + 1) & (Sdim - 1);
  const float* bi = bert + (size_t)(b * Sdim + inext) * Hdim;

  // s1 = (zs @ w1)[b,i] = bert[b,i+1] @ u1 + bz.w1
  float a = 0.f;
  for (int h = tid; h < Hdim; h += 256) a = fmaf(bi[h], g_u1[h], a);
  float s1 = blockReduceSum(a, sm_red);
  float base = s1 + g_c[0] + b_att[0];

  // logits: warp w handles j in [w*32, w*32+32)
  int w = tid >> 5, lane = tid & 31;
  float w3a = w_att[2 * Hdim + lane];
  float w3b = w_att[2 * Hdim + 32 + lane];
  const float* drow = dta + (size_t)(b * Sdim + i) * Sdim * Ddim;
  for (int j = w * 32; j < w * 32 + 32; ++j) {
    const float* dj = drow + (size_t)j * Ddim;
    float acc = dj[lane] * w3a + dj[lane + 32] * w3b;
    acc = warpReduceSum(acc);
    if (lane == 0) {
      float s = base + g_t2[b * Sdim + ((j + 1) & (Sdim - 1))] + acc;
      s = (s >= 0.f) ? s : 0.01f * s;
      if (deprow[j] <= 0) s = -1e9f;
      sm_s[j] = s;
    }
  }
  __syncthreads();

  // softmax over j
  float sv = sm_s[tid];
  float m = blockReduceMax(sv, sm_red);
  float e = expf(sv - m);
  float sum = blockReduceSum(e, sm_red);
  sm_p[tid] = e / sum;
  __syncthreads();

  // agg_d[d] = sum_j p[j] * dta[b,i,j,d]  (dta row is L2-hot from pass 1)
  {
    int d = tid & 63, part = tid >> 6;
    float ad = 0.f;
    const float* dp = drow + (size_t)(part * 64) * Ddim + d;
    for (int j = 0; j < 64; ++j) ad = fmaf(sm_p[part * 64 + j], dp[(size_t)j * Ddim], ad);
    sm_s[tid] = ad;
    __syncthreads();
    if (part == 0) {
      float t = sm_s[d] + sm_s[64 + d] + sm_s[128 + d] + sm_s[192 + d];
      g_X2[slot * (Hdim + Ddim) + Hdim + d] = t;
    }
  }

  // v[h] = sum_j p[j] * bert[b, (j+1)%S, h]  — float4, threads 0..191
  if (tid < H4) {
    const float4* bb4 = (const float4*)(bert + (size_t)b * Sdim * Hdim);
    float4 acc4 = make_float4(0.f, 0.f, 0.f, 0.f);
#pragma unroll 8
    for (int j = 0; j < Sdim; ++j) {
      float p = sm_p[j];
      float4 bv = bb4[(size_t)((j + 1) & (Sdim - 1)) * H4 + tid];
      acc4.x = fmaf(p, bv.x, acc4.x);
      acc4.y = fmaf(p, bv.y, acc4.y);
      acc4.z = fmaf(p, bv.z, acc4.z);
      acc4.w = fmaf(p, bv.w, acc4.w);
    }
    ((float4*)g_X1)[slot * H4 + tid] = acc4;
    ((float4*)g_X1)[(NSLOT + slot) * H4 + tid] = ((const float4*)bi)[tid];
  }
  if (tid == 0) {
    g_valid[slot] = 1;
    g_rowi[slot] = i;
  }
}

// Software-pipelined GEMV chain. Block 256 = 16 col-threads (4 cols each, float4 W
// loads) x 8 rows x 2 K-halves. Explicit next-iter prefetch keeps 5 LDG.128 in
// flight per thread; smem reduce combines the two K-halves.
// MODE 0: [v; bert_next](256xH) @ Wz + bz -> agg_z (X2) / zrow (X3 cols 768..)
// MODE 1: X2(128x832) @ Wf -> nrep (X3 cols 0..767)
// MODE 2: X3(128x1536) @ Wh -> temp, scattered to out rows (i+1) for valid slots
template <int MODE>
__global__ void __launch_bounds__(256) k_gemm(const float* __restrict__ W,
                                              const float* __restrict__ bias,
                                              float* __restrict__ outp) {
  constexpr int K = (MODE == 0) ? Hdim : (MODE == 1) ? (Hdim + Ddim) : (2 * Hdim);
  constexpr int KH = (K / 4) / 2;  // float4 k-steps per half
  const float* X = (MODE == 0) ? g_X1 : (MODE == 1) ? g_X2 : g_X3;
  int tid = threadIdx.x;
  int ct = tid & 15;
  int rt = (tid >> 4) & 7;
  int half = tid >> 7;
  int h = blockIdx.x * 64 + ct * 4;
  int r = blockIdx.y * 8 + rt;

  const float4* __restrict__ x4 = (const float4*)(X + (size_t)r * K) + (size_t)half * KH;
  const float4* __restrict__ wp =
      (const float4*)W + (h >> 2) + (size_t)half * KH * 4 * H4;

  float4 acc = make_float4(0.f, 0.f, 0.f, 0.f);
  // prologue: load first slice
  float4 xv = x4[0];
  float4 wa = wp[0], wb = wp[H4], wc = wp[2 * H4], wd = wp[3 * H4];
#pragma unroll 2
  for (int k4 = 0; k4 < KH - 1; ++k4) {
    const float4* wn = wp + (size_t)(k4 + 1) * (4 * H4);
    float4 xn = x4[k4 + 1];
    float4 wan = wn[0];
    float4 wbn = wn[H4];
    float4 wcn = wn[2 * H4];
    float4 wdn = wn[3 * H4];
    acc.x = fmaf(xv.x, wa.x, acc.x);
    acc.y = fmaf(xv.x, wa.y, acc.y);
    acc.z = fmaf(xv.x, wa.z, acc.z);
    acc.w = fmaf(xv.x, wa.w, acc.w);
    acc.x = fmaf(xv.y, wb.x, acc.x);
    acc.y = fmaf(xv.y, wb.y, acc.y);
    acc.z = fmaf(xv.y, wb.z, acc.z);
    acc.w = fmaf(xv.y, wb.w, acc.w);
    acc.x = fmaf(xv.z, wc.x, acc.x);
    acc.y = fmaf(xv.z, wc.y, acc.y);
    acc.z = fmaf(xv.z, wc.z, acc.z);
    acc.w = fmaf(xv.z, wc.w, acc.w);
    acc.x = fmaf(xv.w, wd.x, acc.x);
    acc.y = fmaf(xv.w, wd.y, acc.y);
    acc.z = fmaf(xv.w, wd.z, acc.z);
    acc.w = fmaf(xv.w, wd.w, acc.w);
    xv = xn;
    wa = wan;
    wb = wbn;
    wc = wcn;
    wd = wdn;
  }
  // epilogue FMAs
  acc.x = fmaf(xv.x, wa.x, acc.x);
  acc.y = fmaf(xv.x, wa.y, acc.y);
  acc.z = fmaf(xv.x, wa.z, acc.z);
  acc.w = fmaf(xv.x, wa.w, acc.w);
  acc.x = fmaf(xv.y, wb.x, acc.x);
  acc.y = fmaf(xv.y, wb.y, acc.y);
  acc.z = fmaf(xv.y, wb.z, acc.z);
  acc.w = fmaf(xv.y, wb.w, acc.w);
  acc.x = fmaf(xv.z, wc.x, acc.x);
  acc.y = fmaf(xv.z, wc.y, acc.y);
  acc.z = fmaf(xv.z, wc.z, acc.z);
  acc.w = fmaf(xv.z, wc.w, acc.w);
  acc.x = fmaf(xv.w, wd.x, acc.x);
  acc.y = fmaf(xv.w, wd.y, acc.y);
  acc.z = fmaf(xv.w, wd.z, acc.z);
  acc.w = fmaf(xv.w, wd.w, acc.w);

  // combine K-halves via smem
  __shared__ float4 sred[8][16];
  if (half == 1) sred[rt][ct] = acc;
  __syncthreads();
  if (half == 1) return;
  float4 o = sred[rt][ct];
  acc.x += o.x;
  acc.y += o.y;
  acc.z += o.z;
  acc.w += o.w;

  if (MODE == 0) {
    float4 bb = *(const float4*)(bias + h);
    acc.x += bb.x;
    acc.y += bb.y;
    acc.z += bb.z;
    acc.w += bb.w;
    if (r < NSLOT)
      *(float4*)(g_X2 + (size_t)r * (Hdim + Ddim) + h) = acc;  // agg_z
    else
      *(float4*)(g_X3 + (size_t)(r - NSLOT) * (2 * Hdim) + Hdim + h) = acc;  // zrow
  } else if (MODE == 1) {
    *(float4*)(g_X3 + (size_t)r * (2 * Hdim) + h) = acc;  // nrep
  } else {
    if (g_valid[r]) {
      int bb = r >> 3;
      int o2 = (g_rowi[r] + 1) & (Sdim - 1);
      *(float4*)(outp + ((size_t)(bb * Sdim + o2)) * Hdim + h) = acc;
    }
  }
}

extern "C" void kernel_launch(void* const* d_in, const int* in_sizes, int n_in,
                              void* d_out, int out_size) {
  const float* bert = (const float*)d_in[0];
  const float* dta = (const float*)d_in[1];
  const int* deprel = (const int*)d_in[2];
  const int* asp_s = (const int*)d_in[3];
  const int* asp_e = (const int*)d_in[4];
  const float* Wz = (const float*)d_in[5];
  const float* bz = (const float*)d_in[6];
  const float* watt = (const float*)d_in[7];
  const float* batt = (const float*)d_in[8];
  const float* Wf = (const float*)d_in[9];
  const float* Wh = (const float*)d_in[10];
  float* out = (float*)d_out;

  k_pre<<<769, 256>>>(Wz, bz, watt);
  k_t2<<<(Bdim * Sdim) / 8, 256>>>(bert, out);  // also bulk-copies bert -> out
  k_main<<<dim3(Bdim, 8), 256>>>(bert, dta, deprel, asp_s, asp_e, watt, batt);
  k_gemm<0><<<dim3(12, 32), 256>>>(Wz, bz, nullptr);
  k_gemm<1><<<dim3(12, 16), 256>>>(Wf, nullptr, nullptr);
  k_gemm<2><<<dim3(12, 16), 256>>>(Wh, nullptr, out);
}

// round 4
// speedup vs baseline: 2.2487x; 1.1306x over previous
#include <cuda_runtime.h>
#include <cstdint>

#define Bdim 16
#define Sdim 256
#define Hdim 768
#define Ddim 64
#define NSLOT 128  // 16 batches * 8 slots (max aspect span is 6 rows)
#define H4 (Hdim / 4)

// Scratch (device globals; no allocation allowed)
__device__ __align__(16) float g_u1[Hdim];              // Wz @ w1
__device__ __align__(16) float g_u2[Hdim];              // Wz @ w2
__device__ float g_c[2];                                // bz.w1, bz.w2
__device__ __align__(16) float g_t2[Bdim * Sdim];       // (z @ w2)[b,j]
__device__ __align__(16) float g_X1[2 * NSLOT * Hdim];  // rows 0..127: v; 128..255: bert_next
__device__ __align__(16) float g_X2[NSLOT * (Hdim + Ddim)];  // [agg_z | agg_d]
__device__ __align__(16) float g_X3[NSLOT * (2 * Hdim)];     // [nrep | zrow]
__device__ __align__(16) float g_P[4 * 256 * Hdim];          // K-split partial sums
__device__ int g_valid[NSLOT];
__device__ int g_rowi[NSLOT];

__device__ __forceinline__ float warpReduceSum(float v) {
#pragma unroll
  for (int o = 16; o > 0; o >>= 1) v += __shfl_down_sync(0xffffffffu, v, o);
  return v;
}

__device__ __forceinline__ float blockReduceSum(float v, float* sm) {
  v = warpReduceSum(v);
  int w = threadIdx.x >> 5;
  if ((threadIdx.x & 31) == 0) sm[w] = v;
  __syncthreads();
  if (threadIdx.x < 8) {
    float x = sm[threadIdx.x];
#pragma unroll
    for (int o = 4; o > 0; o >>= 1) x += __shfl_down_sync(0xffu, x, o);
    if (threadIdx.x == 0) sm[0] = x;
  }
  __syncthreads();
  float r = sm[0];
  __syncthreads();
  return r;
}

__device__ __forceinline__ float blockReduceMax(float v, float* sm) {
#pragma unroll
  for (int o = 16; o > 0; o >>= 1) v = fmaxf(v, __shfl_down_sync(0xffffffffu, v, o));
  int w = threadIdx.x >> 5;
  if ((threadIdx.x & 31) == 0) sm[w] = v;
  __syncthreads();
  if (threadIdx.x < 8) {
    float x = sm[threadIdx.x];
#pragma unroll
    for (int o = 4; o > 0; o >>= 1) x = fmaxf(x, __shfl_down_sync(0xffu, x, o));
    if (threadIdx.x == 0) sm[0] = x;
  }
  __syncthreads();
  float r = sm[0];
  __syncthreads();
  return r;
}

// ---- packed f32x2 helpers (FFMA2 only reachable via PTX on sm_103a) ----
__device__ __forceinline__ unsigned long long splat2(float x) {
  unsigned long long r;
  asm("mov.b64 %0, {%1, %2};" : "=l"(r) : "f"(x), "f"(x));
  return r;
}
__device__ __forceinline__ void ffma2(unsigned long long& a, unsigned long long x,
                                      unsigned long long w) {
  asm("fma.rn.f32x2 %0, %1, %2, %0;" : "+l"(a) : "l"(x), "l"(w));
}
__device__ __forceinline__ float2 u2f(unsigned long long v) {
  float2 f;
  asm("mov.b64 {%0, %1}, %2;" : "=f"(f.x), "=f"(f.y) : "l"(v));
  return f;
}

// u1 = Wz @ w1, u2 = Wz @ w2, c = (bz.w1, bz.w2). grid 769, block 256.
__global__ void k_pre(const float* __restrict__ Wz, const float* __restrict__ bz,
                      const float* __restrict__ watt) {
  __shared__ float sm[8];
  int h = blockIdx.x, tid = threadIdx.x;
  float a1 = 0.f, a2 = 0.f;
  if (h < Hdim) {
    const float* wr = Wz + (size_t)h * Hdim;
    for (int k = tid; k < Hdim; k += 256) {
      float wv = wr[k];
      a1 = fmaf(wv, watt[k], a1);
      a2 = fmaf(wv, watt[Hdim + k], a2);
    }
  } else {
    for (int k = tid; k < Hdim; k += 256) {
      float bv = bz[k];
      a1 = fmaf(bv, watt[k], a1);
      a2 = fmaf(bv, watt[Hdim + k], a2);
    }
  }
  float r1 = blockReduceSum(a1, sm);
  float r2 = blockReduceSum(a2, sm);
  if (tid == 0) {
    if (h < Hdim) {
      g_u1[h] = r1;
      g_u2[h] = r2;
    } else {
      g_c[0] = r1;
      g_c[1] = r2;
    }
  }
}

// Fused: t2[r] = bert_row[r] @ u2 + bz.w2  AND  out[r] = bert_row[r] (bulk copy).
// grid 512, block 256 (one warp per row).
__global__ void k_t2(const float* __restrict__ bert, float* __restrict__ out) {
  int r = blockIdx.x * 8 + (threadIdx.x >> 5);
  int lane = threadIdx.x & 31;
  const float4* br = (const float4*)(bert + (size_t)r * Hdim);
  float4* orow = (float4*)(out + (size_t)r * Hdim);
  const float4* u24 = (const float4*)g_u2;
  float a = 0.f;
#pragma unroll
  for (int k = lane; k < H4; k += 32) {
    float4 bv = br[k];
    orow[k] = bv;
    float4 uv = u24[k];
    a = fmaf(bv.x, uv.x, a);
    a = fmaf(bv.y, uv.y, a);
    a = fmaf(bv.z, uv.z, a);
    a = fmaf(bv.w, uv.w, a);
  }
  a = warpReduceSum(a);
  if (lane == 0) g_t2[r] = a + g_c[1];
}

// Per needed row: logits + softmax + agg_d + v (attn-weighted bert) + bert_next.
// grid (16, 8), block 256.
__global__ void k_main(const float* __restrict__ bert, const float* __restrict__ dta,
                       const int* __restrict__ deprel, const int* __restrict__ asp_s,
                       const int* __restrict__ asp_e, const float* __restrict__ w_att,
                       const float* __restrict__ b_att) {
  int b = blockIdx.x, il = blockIdx.y;
  int slot = b * 8 + il;
  int tid = threadIdx.x;
  __shared__ float sm_s[Sdim];
  __shared__ float sm_p[Sdim];
  __shared__ float sm_red[8];
  int start = asp_s[b], endi = asp_e[b];
  int i = start + il;
  bool active = (i <= endi) && (i < Sdim);
  const int* deprow = deprel + (size_t)(b * Sdim + (active ? i : 0)) * Sdim;
  int hasn = 0;
  if (active) hasn = (deprow[tid] > 0);
  int any = __syncthreads_or(hasn);
  if (!active || !any) {
    for (int h = tid; h < Hdim; h += 256) {
      g_X1[slot * Hdim + h] = 0.f;
      g_X1[(NSLOT + slot) * Hdim + h] = 0.f;
    }
    if (tid < Ddim) g_X2[slot * (Hdim + Ddim) + Hdim + tid] = 0.f;
    if (tid == 0) {
      g_valid[slot] = 0;
      g_rowi[slot] = 0;
    }
    return;
  }

  int inext = (i + 1) & (Sdim - 1);
  const float* bi = bert + (size_t)(b * Sdim + inext) * Hdim;

  // s1 = (zs @ w1)[b,i] = bert[b,i+1] @ u1 + bz.w1
  float a = 0.f;
  for (int h = tid; h < Hdim; h += 256) a = fmaf(bi[h], g_u1[h], a);
  float s1 = blockReduceSum(a, sm_red);
  float base = s1 + g_c[0] + b_att[0];

  // logits: warp w handles j in [w*32, w*32+32)
  int w = tid >> 5, lane = tid & 31;
  float w3a = w_att[2 * Hdim + lane];
  float w3b = w_att[2 * Hdim + 32 + lane];
  const float* drow = dta + (size_t)(b * Sdim + i) * Sdim * Ddim;
  for (int j = w * 32; j < w * 32 + 32; ++j) {
    const float* dj = drow + (size_t)j * Ddim;
    float acc = dj[lane] * w3a + dj[lane + 32] * w3b;
    acc = warpReduceSum(acc);
    if (lane == 0) {
      float s = base + g_t2[b * Sdim + ((j + 1) & (Sdim - 1))] + acc;
      s = (s >= 0.f) ? s : 0.01f * s;
      if (deprow[j] <= 0) s = -1e9f;
      sm_s[j] = s;
    }
  }
  __syncthreads();

  // softmax over j
  float sv = sm_s[tid];
  float m = blockReduceMax(sv, sm_red);
  float e = expf(sv - m);
  float sum = blockReduceSum(e, sm_red);
  sm_p[tid] = e / sum;
  __syncthreads();

  // agg_d[d] = sum_j p[j] * dta[b,i,j,d]  (dta row is L2-hot from pass 1)
  {
    int d = tid & 63, part = tid >> 6;
    float ad = 0.f;
    const float* dp = drow + (size_t)(part * 64) * Ddim + d;
    for (int j = 0; j < 64; ++j) ad = fmaf(sm_p[part * 64 + j], dp[(size_t)j * Ddim], ad);
    sm_s[tid] = ad;
    __syncthreads();
    if (part == 0) {
      float t = sm_s[d] + sm_s[64 + d] + sm_s[128 + d] + sm_s[192 + d];
      g_X2[slot * (Hdim + Ddim) + Hdim + d] = t;
    }
  }

  // v[h] = sum_j p[j] * bert[b, (j+1)%S, h]  — float4, threads 0..191
  if (tid < H4) {
    const float4* bb4 = (const float4*)(bert + (size_t)b * Sdim * Hdim);
    float4 acc4 = make_float4(0.f, 0.f, 0.f, 0.f);
#pragma unroll 8
    for (int j = 0; j < Sdim; ++j) {
      float p = sm_p[j];
      float4 bv = bb4[(size_t)((j + 1) & (Sdim - 1)) * H4 + tid];
      acc4.x = fmaf(p, bv.x, acc4.x);
      acc4.y = fmaf(p, bv.y, acc4.y);
      acc4.z = fmaf(p, bv.z, acc4.z);
      acc4.w = fmaf(p, bv.w, acc4.w);
    }
    ((float4*)g_X1)[slot * H4 + tid] = acc4;
    ((float4*)g_X1)[(NSLOT + slot) * H4 + tid] = ((const float4*)bi)[tid];
  }
  if (tid == 0) {
    g_valid[slot] = 1;
    g_rowi[slot] = i;
  }
}

// Register-tiled outer-product partial GEMM with packed f32x2 FMAs.
// Block 256 = 16 col-threads (4 cols each) x 16 row-threads (2 rows each)
// -> 64 cols x 32 rows per block. grid = (Hdim/64, rows/32, ksplit).
// Each z computes a KS-slice partial sum into g_P[z][r][h].
template <int KS, int LDX>
__global__ void __launch_bounds__(256) k_pgemm(const float* __restrict__ X,
                                               const float* __restrict__ W,
                                               float* __restrict__ P) {
  int tid = threadIdx.x;
  int ct = tid & 15, rt = tid >> 4;
  int h = blockIdx.x * 64 + ct * 4;
  int r = blockIdx.y * 32 + rt * 2;
  int z = blockIdx.z;

  const float4* __restrict__ xa =
      (const float4*)(X + (size_t)r * LDX + (size_t)z * KS);
  const float4* __restrict__ xb =
      (const float4*)(X + (size_t)(r + 1) * LDX + (size_t)z * KS);
  // W row = 768 floats = 192 ulonglong2. Walk k downwards in rows of W.
  const ulonglong2* __restrict__ wp =
      (const ulonglong2*)(W + (size_t)z * KS * Hdim) + (h >> 2);

  unsigned long long a0l = 0, a0h = 0, a1l = 0, a1h = 0;

  // prologue
  float4 x0 = xa[0], x1 = xb[0];
  ulonglong2 w0 = wp[0], w1 = wp[192], w2 = wp[384], w3 = wp[576];

#pragma unroll 4
  for (int k4 = 0; k4 < KS / 4 - 1; ++k4) {
    const ulonglong2* wn = wp + (size_t)(k4 + 1) * 768;
    float4 nx0 = xa[k4 + 1];
    float4 nx1 = xb[k4 + 1];
    ulonglong2 nw0 = wn[0];
    ulonglong2 nw1 = wn[192];
    ulonglong2 nw2 = wn[384];
    ulonglong2 nw3 = wn[576];
    {
      unsigned long long s0, s1;
      s0 = splat2(x0.x); s1 = splat2(x1.x);
      ffma2(a0l, s0, w0.x); ffma2(a0h, s0, w0.y);
      ffma2(a1l, s1, w0.x); ffma2(a1h, s1, w0.y);
      s0 = splat2(x0.y); s1 = splat2(x1.y);
      ffma2(a0l, s0, w1.x); ffma2(a0h, s0, w1.y);
      ffma2(a1l, s1, w1.x); ffma2(a1h, s1, w1.y);
      s0 = splat2(x0.z); s1 = splat2(x1.z);
      ffma2(a0l, s0, w2.x); ffma2(a0h, s0, w2.y);
      ffma2(a1l, s1, w2.x); ffma2(a1h, s1, w2.y);
      s0 = splat2(x0.w); s1 = splat2(x1.w);
      ffma2(a0l, s0, w3.x); ffma2(a0h, s0, w3.y);
      ffma2(a1l, s1, w3.x); ffma2(a1h, s1, w3.y);
    }
    x0 = nx0; x1 = nx1;
    w0 = nw0; w1 = nw1; w2 = nw2; w3 = nw3;
  }
  // epilogue FMAs
  {
    unsigned long long s0, s1;
    s0 = splat2(x0.x); s1 = splat2(x1.x);
    ffma2(a0l, s0, w0.x); ffma2(a0h, s0, w0.y);
    ffma2(a1l, s1, w0.x); ffma2(a1h, s1, w0.y);
    s0 = splat2(x0.y); s1 = splat2(x1.y);
    ffma2(a0l, s0, w1.x); ffma2(a0h, s0, w1.y);
    ffma2(a1l, s1, w1.x); ffma2(a1h, s1, w1.y);
    s0 = splat2(x0.z); s1 = splat2(x1.z);
    ffma2(a0l, s0, w2.x); ffma2(a0h, s0, w2.y);
    ffma2(a1l, s1, w2.x); ffma2(a1h, s1, w2.y);
    s0 = splat2(x0.w); s1 = splat2(x1.w);
    ffma2(a0l, s0, w3.x); ffma2(a0h, s0, w3.y);
    ffma2(a1l, s1, w3.x); ffma2(a1h, s1, w3.y);
  }

  float2 f0l = u2f(a0l), f0h = u2f(a0h), f1l = u2f(a1l), f1h = u2f(a1h);
  float* pr = P + ((size_t)(z * 256 + r)) * Hdim + h;
  *(float4*)pr = make_float4(f0l.x, f0l.y, f0h.x, f0h.y);
  *(float4*)(pr + Hdim) = make_float4(f1l.x, f1l.y, f1h.x, f1h.y);
}

// Epilogues: combine K-split partials and place results. block 192 (float4/thread).
__global__ void k_epi0(const float* __restrict__ bias) {
  int r = blockIdx.x;
  int h = threadIdx.x * 4;
  const float4 p0 = *(const float4*)(g_P + (size_t)r * Hdim + h);
  const float4 p1 = *(const float4*)(g_P + (size_t)(256 + r) * Hdim + h);
  const float4 bb = *(const float4*)(bias + h);
  float4 v = make_float4(p0.x + p1.x + bb.x, p0.y + p1.y + bb.y,
                         p0.z + p1.z + bb.z, p0.w + p1.w + bb.w);
  if (r < NSLOT)
    *(float4*)(g_X2 + (size_t)r * (Hdim + Ddim) + h) = v;  // agg_z
  else
    *(float4*)(g_X3 + (size_t)(r - NSLOT) * (2 * Hdim) + Hdim + h) = v;  // zrow
}

__global__ void k_epi1() {
  int r = blockIdx.x;
  int h = threadIdx.x * 4;
  const float4 p0 = *(const float4*)(g_P + (size_t)r * Hdim + h);
  const float4 p1 = *(const float4*)(g_P + (size_t)(256 + r) * Hdim + h);
  *(float4*)(g_X3 + (size_t)r * (2 * Hdim) + h) =
      make_float4(p0.x + p1.x, p0.y + p1.y, p0.z + p1.z, p0.w + p1.w);  // nrep
}

__global__ void k_epi2(float* __restrict__ outp) {
  int r = blockIdx.x;
  if (!g_valid[r]) return;
  int h = threadIdx.x * 4;
  const float4 p0 = *(const float4*)(g_P + (size_t)r * Hdim + h);
  const float4 p1 = *(const float4*)(g_P + (size_t)(256 + r) * Hdim + h);
  const float4 p2 = *(const float4*)(g_P + (size_t)(512 + r) * Hdim + h);
  const float4 p3 = *(const float4*)(g_P + (size_t)(768 + r) * Hdim + h);
  float4 v = make_float4(p0.x + p1.x + p2.x + p3.x, p0.y + p1.y + p2.y + p3.y,
                         p0.z + p1.z + p2.z + p3.z, p0.w + p1.w + p2.w + p3.w);
  int bb = r >> 3;
  int o = (g_rowi[r] + 1) & (Sdim - 1);
  *(float4*)(outp + ((size_t)(bb * Sdim + o)) * Hdim + h) = v;
}

extern "C" void kernel_launch(void* const* d_in, const int* in_sizes, int n_in,
                              void* d_out, int out_size) {
  const float* bert = (const float*)d_in[0];
  const float* dta = (const float*)d_in[1];
  const int* deprel = (const int*)d_in[2];
  const int* asp_s = (const int*)d_in[3];
  const int* asp_e = (const int*)d_in[4];
  const float* Wz = (const float*)d_in[5];
  const float* bz = (const float*)d_in[6];
  const float* watt = (const float*)d_in[7];
  const float* batt = (const float*)d_in[8];
  const float* Wf = (const float*)d_in[9];
  const float* Wh = (const float*)d_in[10];
  float* out = (float*)d_out;

  float* P;
  cudaGetSymbolAddress((void**)&P, g_P);

  k_pre<<<769, 256>>>(Wz, bz, watt);
  k_t2<<<(Bdim * Sdim) / 8, 256>>>(bert, out);  // also bulk-copies bert -> out
  k_main<<<dim3(Bdim, 8), 256>>>(bert, dta, deprel, asp_s, asp_e, watt, batt);

  float* X1;
  float* X2;
  float* X3;
  cudaGetSymbolAddress((void**)&X1, g_X1);
  cudaGetSymbolAddress((void**)&X2, g_X2);
  cudaGetSymbolAddress((void**)&X3, g_X3);

  // mode 0: [v; bert_next](256 x 768) @ Wz  (K=768, split 2)
  k_pgemm<384, Hdim><<<dim3(12, 8, 2), 256>>>(X1, Wz, P);
  k_epi0<<<256, 192>>>(bz);
  // mode 1: X2(128 x 832) @ Wf  (K=832, split 2)
  k_pgemm<416, Hdim + Ddim><<<dim3(12, 4, 2), 256>>>(X2, Wf, P);
  k_epi1<<<128, 192>>>();
  // mode 2: X3(128 x 1536) @ Wh  (K=1536, split 4)
  k_pgemm<384, 2 * Hdim><<<dim3(12, 4, 4), 256>>>(X3, Wh, P);
  k_epi2<<<128, 192>>>(out);
}

// round 5
// speedup vs baseline: 2.7420x; 1.2193x over previous
#include <cuda_runtime.h>
#include <cstdint>

#define Bdim 16
#define Sdim 256
#define Hdim 768
#define Ddim 64
#define NSLOT 128  // 16 batches * 8 slots (max aspect span is 6 rows)
#define H4 (Hdim / 4)

// Scratch (device globals; no allocation allowed)
__device__ __align__(16) float g_u1[Hdim];              // Wz @ w1
__device__ __align__(16) float g_u2[Hdim];              // Wz @ w2
__device__ float g_c[2];                                // bz.w1, bz.w2
__device__ __align__(16) float g_t2[Bdim * Sdim];       // (z @ w2)[b,j]
__device__ __align__(16) float g_X1[2 * NSLOT * Hdim];  // rows 0..127: v; 128..255: bert_next
__device__ __align__(16) float g_X2[NSLOT * (Hdim + Ddim)];  // [agg_z | agg_d]
__device__ __align__(16) float g_X3[NSLOT * (2 * Hdim)];     // [nrep | zrow]
__device__ __align__(16) float g_P[8 * 256 * Hdim];          // K-split partial sums
__device__ int g_valid[NSLOT];
__device__ int g_rowi[NSLOT];

__device__ __forceinline__ float warpReduceSum(float v) {
#pragma unroll
  for (int o = 16; o > 0; o >>= 1) v += __shfl_down_sync(0xffffffffu, v, o);
  return v;
}

__device__ __forceinline__ float blockReduceSum(float v, float* sm) {
  v = warpReduceSum(v);
  int w = threadIdx.x >> 5;
  if ((threadIdx.x & 31) == 0) sm[w] = v;
  __syncthreads();
  if (threadIdx.x < 8) {
    float x = sm[threadIdx.x];
#pragma unroll
    for (int o = 4; o > 0; o >>= 1) x += __shfl_down_sync(0xffu, x, o);
    if (threadIdx.x == 0) sm[0] = x;
  }
  __syncthreads();
  float r = sm[0];
  __syncthreads();
  return r;
}

__device__ __forceinline__ float blockReduceMax(float v, float* sm) {
#pragma unroll
  for (int o = 16; o > 0; o >>= 1) v = fmaxf(v, __shfl_down_sync(0xffffffffu, v, o));
  int w = threadIdx.x >> 5;
  if ((threadIdx.x & 31) == 0) sm[w] = v;
  __syncthreads();
  if (threadIdx.x < 8) {
    float x = sm[threadIdx.x];
#pragma unroll
    for (int o = 4; o > 0; o >>= 1) x = fmaxf(x, __shfl_down_sync(0xffu, x, o));
    if (threadIdx.x == 0) sm[0] = x;
  }
  __syncthreads();
  float r = sm[0];
  __syncthreads();
  return r;
}

// ---- packed f32x2 helpers (FFMA2 only reachable via PTX on sm_103a) ----
__device__ __forceinline__ unsigned long long splat2(float x) {
  unsigned long long r;
  asm("mov.b64 %0, {%1, %2};" : "=l"(r) : "f"(x), "f"(x));
  return r;
}
__device__ __forceinline__ void ffma2(unsigned long long& a, unsigned long long x,
                                      unsigned long long w) {
  asm("fma.rn.f32x2 %0, %1, %2, %0;" : "+l"(a) : "l"(x), "l"(w));
}
__device__ __forceinline__ float2 u2f(unsigned long long v) {
  float2 f;
  asm("mov.b64 {%0, %1}, %2;" : "=f"(f.x), "=f"(f.y) : "l"(v));
  return f;
}

// u1 = Wz @ w1, u2 = Wz @ w2, c = (bz.w1, bz.w2). grid 769, block 256.
__global__ void k_pre(const float* __restrict__ Wz, const float* __restrict__ bz,
                      const float* __restrict__ watt) {
  __shared__ float sm[8];
  int h = blockIdx.x, tid = threadIdx.x;
  float a1 = 0.f, a2 = 0.f;
  if (h < Hdim) {
    const float* wr = Wz + (size_t)h * Hdim;
    for (int k = tid; k < Hdim; k += 256) {
      float wv = wr[k];
      a1 = fmaf(wv, watt[k], a1);
      a2 = fmaf(wv, watt[Hdim + k], a2);
    }
  } else {
    for (int k = tid; k < Hdim; k += 256) {
      float bv = bz[k];
      a1 = fmaf(bv, watt[k], a1);
      a2 = fmaf(bv, watt[Hdim + k], a2);
    }
  }
  float r1 = blockReduceSum(a1, sm);
  float r2 = blockReduceSum(a2, sm);
  if (tid == 0) {
    if (h < Hdim) {
      g_u1[h] = r1;
      g_u2[h] = r2;
    } else {
      g_c[0] = r1;
      g_c[1] = r2;
    }
  }
}

// Fused: t2[r] = bert_row[r] @ u2 + bz.w2  AND  out[r] = bert_row[r] (bulk copy).
// grid 512, block 256 (one warp per row).
__global__ void k_t2(const float* __restrict__ bert, float* __restrict__ out) {
  int r = blockIdx.x * 8 + (threadIdx.x >> 5);
  int lane = threadIdx.x & 31;
  const float4* br = (const float4*)(bert + (size_t)r * Hdim);
  float4* orow = (float4*)(out + (size_t)r * Hdim);
  const float4* u24 = (const float4*)g_u2;
  float a = 0.f;
#pragma unroll
  for (int k = lane; k < H4; k += 32) {
    float4 bv = br[k];
    orow[k] = bv;
    float4 uv = u24[k];
    a = fmaf(bv.x, uv.x, a);
    a = fmaf(bv.y, uv.y, a);
    a = fmaf(bv.z, uv.z, a);
    a = fmaf(bv.w, uv.w, a);
  }
  a = warpReduceSum(a);
  if (lane == 0) g_t2[r] = a + g_c[1];
}

// Per needed row: logits + softmax + agg_d + v (attn-weighted bert) + bert_next.
// grid (16, 8), block 256.
__global__ void k_main(const float* __restrict__ bert, const float* __restrict__ dta,
                       const int* __restrict__ deprel, const int* __restrict__ asp_s,
                       const int* __restrict__ asp_e, const float* __restrict__ w_att,
                       const float* __restrict__ b_att) {
  int b = blockIdx.x, il = blockIdx.y;
  int slot = b * 8 + il;
  int tid = threadIdx.x;
  __shared__ float sm_s[Sdim];
  __shared__ float sm_p[Sdim];
  __shared__ float sm_red[8];
  int start = asp_s[b], endi = asp_e[b];
  int i = start + il;
  bool active = (i <= endi) && (i < Sdim);
  const int* deprow = deprel + (size_t)(b * Sdim + (active ? i : 0)) * Sdim;
  int hasn = 0;
  if (active) hasn = (deprow[tid] > 0);
  int any = __syncthreads_or(hasn);
  if (!active || !any) {
    for (int h = tid; h < Hdim; h += 256) {
      g_X1[slot * Hdim + h] = 0.f;
      g_X1[(NSLOT + slot) * Hdim + h] = 0.f;
    }
    if (tid < Ddim) g_X2[slot * (Hdim + Ddim) + Hdim + tid] = 0.f;
    if (tid == 0) {
      g_valid[slot] = 0;
      g_rowi[slot] = 0;
    }
    return;
  }

  int inext = (i + 1) & (Sdim - 1);
  const float* bi = bert + (size_t)(b * Sdim + inext) * Hdim;

  // s1 = (zs @ w1)[b,i] = bert[b,i+1] @ u1 + bz.w1
  float a = 0.f;
  for (int h = tid; h < Hdim; h += 256) a = fmaf(bi[h], g_u1[h], a);
  float s1 = blockReduceSum(a, sm_red);
  float base = s1 + g_c[0] + b_att[0];

  // logits: warp w handles j in [w*32, w*32+32)
  int w = tid >> 5, lane = tid & 31;
  float w3a = w_att[2 * Hdim + lane];
  float w3b = w_att[2 * Hdim + 32 + lane];
  const float* drow = dta + (size_t)(b * Sdim + i) * Sdim * Ddim;
  for (int j = w * 32; j < w * 32 + 32; ++j) {
    const float* dj = drow + (size_t)j * Ddim;
    float acc = dj[lane] * w3a + dj[lane + 32] * w3b;
    acc = warpReduceSum(acc);
    if (lane == 0) {
      float s = base + g_t2[b * Sdim + ((j + 1) & (Sdim - 1))] + acc;
      s = (s >= 0.f) ? s : 0.01f * s;
      if (deprow[j] <= 0) s = -1e9f;
      sm_s[j] = s;
    }
  }
  __syncthreads();

  // softmax over j
  float sv = sm_s[tid];
  float m = blockReduceMax(sv, sm_red);
  float e = expf(sv - m);
  float sum = blockReduceSum(e, sm_red);
  sm_p[tid] = e / sum;
  __syncthreads();

  // agg_d[d] = sum_j p[j] * dta[b,i,j,d]  (dta row is L2-hot from pass 1)
  {
    int d = tid & 63, part = tid >> 6;
    float ad = 0.f;
    const float* dp = drow + (size_t)(part * 64) * Ddim + d;
    for (int j = 0; j < 64; ++j) ad = fmaf(sm_p[part * 64 + j], dp[(size_t)j * Ddim], ad);
    sm_s[tid] = ad;
    __syncthreads();
    if (part == 0) {
      float t = sm_s[d] + sm_s[64 + d] + sm_s[128 + d] + sm_s[192 + d];
      g_X2[slot * (Hdim + Ddim) + Hdim + d] = t;
    }
  }

  // v[h] = sum_j p[j] * bert[b, (j+1)%S, h]  — float4, threads 0..191
  if (tid < H4) {
    const float4* bb4 = (const float4*)(bert + (size_t)b * Sdim * Hdim);
    float4 acc4 = make_float4(0.f, 0.f, 0.f, 0.f);
#pragma unroll 8
    for (int j = 0; j < Sdim; ++j) {
      float p = sm_p[j];
      float4 bv = bb4[(size_t)((j + 1) & (Sdim - 1)) * H4 + tid];
      acc4.x = fmaf(p, bv.x, acc4.x);
      acc4.y = fmaf(p, bv.y, acc4.y);
      acc4.z = fmaf(p, bv.z, acc4.z);
      acc4.w = fmaf(p, bv.w, acc4.w);
    }
    ((float4*)g_X1)[slot * H4 + tid] = acc4;
    ((float4*)g_X1)[(NSLOT + slot) * H4 + tid] = ((const float4*)bi)[tid];
  }
  if (tid == 0) {
    g_valid[slot] = 1;
    g_rowi[slot] = i;
  }
}

// 16 FFMA2 on 2 rows x 4 cols from one k4 slice.
#define FMAB(X0, X1, W0, W1, W2, W3)                  \
  do {                                                \
    unsigned long long s0, s1;                        \
    s0 = splat2((X0).x);                              \
    s1 = splat2((X1).x);                              \
    ffma2(a0l, s0, (W0).x);                           \
    ffma2(a0h, s0, (W0).y);                           \
    ffma2(a1l, s1, (W0).x);                           \
    ffma2(a1h, s1, (W0).y);                           \
    s0 = splat2((X0).y);                              \
    s1 = splat2((X1).y);                              \
    ffma2(a0l, s0, (W1).x);                           \
    ffma2(a0h, s0, (W1).y);                           \
    ffma2(a1l, s1, (W1).x);                           \
    ffma2(a1h, s1, (W1).y);                           \
    s0 = splat2((X0).z);                              \
    s1 = splat2((X1).z);                              \
    ffma2(a0l, s0, (W2).x);                           \
    ffma2(a0h, s0, (W2).y);                           \
    ffma2(a1l, s1, (W2).x);                           \
    ffma2(a1h, s1, (W2).y);                           \
    s0 = splat2((X0).w);                              \
    s1 = splat2((X1).w);                              \
    ffma2(a0l, s0, (W3).x);                           \
    ffma2(a0h, s0, (W3).y);                           \
    ffma2(a1l, s1, (W3).x);                           \
    ffma2(a1h, s1, (W3).y);                           \
  } while (0)

#define LOADS(st, k4)                                 \
  do {                                                \
    xA##st = xa[(k4)];                                \
    xB##st = xb[(k4)];                                \
    const ulonglong2* wn = wp + (size_t)(k4) * 768;   \
    wA##st = wn[0];                                   \
    wB##st = wn[192];                                 \
    wC##st = wn[384];                                 \
    wD##st = wn[576];                                 \
  } while (0)

// Register-tiled outer-product partial GEMM with packed f32x2 FMAs and a true
// 2-stage double-buffered pipeline (12 LDG.128 in flight per thread).
// Block 256 = 16 col-threads (4 cols) x 16 row-threads (2 rows) -> 64x32 tile.
// grid = (Hdim/64, rows/32, ksplit); each z writes partials to g_P[z][r][h].
template <int KS, int LDX>
__global__ void __launch_bounds__(256) k_pgemm(const float* __restrict__ X,
                                               const float* __restrict__ W,
                                               float* __restrict__ P) {
  constexpr int NSTEPS = KS / 4;
  static_assert(NSTEPS % 2 == 0 && NSTEPS >= 4, "");
  int tid = threadIdx.x;
  int ct = tid & 15, rt = tid >> 4;
  int h = blockIdx.x * 64 + ct * 4;
  int r = blockIdx.y * 32 + rt * 2;
  int z = blockIdx.z;

  const float4* __restrict__ xa =
      (const float4*)(X + (size_t)r * LDX + (size_t)z * KS);
  const float4* __restrict__ xb =
      (const float4*)(X + (size_t)(r + 1) * LDX + (size_t)z * KS);
  const ulonglong2* __restrict__ wp =
      (const ulonglong2*)(W + (size_t)z * KS * Hdim) + (h >> 2);

  unsigned long long a0l = 0, a0h = 0, a1l = 0, a1h = 0;

  float4 xA0, xB0, xA1, xB1;
  ulonglong2 wA0, wB0, wC0, wD0, wA1, wB1, wC1, wD1;

  LOADS(0, 0);
  LOADS(1, 1);

#pragma unroll 1
  for (int k4 = 0; k4 <= NSTEPS - 4; k4 += 2) {
    FMAB(xA0, xB0, wA0, wB0, wC0, wD0);
    LOADS(0, k4 + 2);
    FMAB(xA1, xB1, wA1, wB1, wC1, wD1);
    LOADS(1, k4 + 3);
  }
  FMAB(xA0, xB0, wA0, wB0, wC0, wD0);
  FMAB(xA1, xB1, wA1, wB1, wC1, wD1);

  float2 f0l = u2f(a0l), f0h = u2f(a0h), f1l = u2f(a1l), f1h = u2f(a1h);
  float* pr = P + ((size_t)(z * 256 + r)) * Hdim + h;
  *(float4*)pr = make_float4(f0l.x, f0l.y, f0h.x, f0h.y);
  *(float4*)(pr + Hdim) = make_float4(f1l.x, f1l.y, f1h.x, f1h.y);
}

// Epilogue: combine NZ K-split partials and route per MODE. block 192.
// MODE 0: +bias -> agg_z (X2) / zrow (X3 cols 768..); MODE 1: -> nrep (X3);
// MODE 2: scatter valid rows to out[(i+1)].
template <int NZ, int MODE>
__global__ void k_epi(const float* __restrict__ bias, float* __restrict__ outp) {
  int r = blockIdx.x;
  if (MODE == 2 && !g_valid[r]) return;
  int h = threadIdx.x * 4;
  float4 v = make_float4(0.f, 0.f, 0.f, 0.f);
#pragma unroll
  for (int zz = 0; zz < NZ; ++zz) {
    const float4 p = *(const float4*)(g_P + (size_t)(zz * 256 + r) * Hdim + h);
    v.x += p.x;
    v.y += p.y;
    v.z += p.z;
    v.w += p.w;
  }
  if (MODE == 0) {
    const float4 bb = *(const float4*)(bias + h);
    v.x += bb.x;
    v.y += bb.y;
    v.z += bb.z;
    v.w += bb.w;
    if (r < NSLOT)
      *(float4*)(g_X2 + (size_t)r * (Hdim + Ddim) + h) = v;  // agg_z
    else
      *(float4*)(g_X3 + (size_t)(r - NSLOT) * (2 * Hdim) + Hdim + h) = v;  // zrow
  } else if (MODE == 1) {
    *(float4*)(g_X3 + (size_t)r * (2 * Hdim) + h) = v;  // nrep
  } else {
    int bb = r >> 3;
    int o = (g_rowi[r] + 1) & (Sdim - 1);
    *(float4*)(outp + ((size_t)(bb * Sdim + o)) * Hdim + h) = v;
  }
}

extern "C" void kernel_launch(void* const* d_in, const int* in_sizes, int n_in,
                              void* d_out, int out_size) {
  const float* bert = (const float*)d_in[0];
  const float* dta = (const float*)d_in[1];
  const int* deprel = (const int*)d_in[2];
  const int* asp_s = (const int*)d_in[3];
  const int* asp_e = (const int*)d_in[4];
  const float* Wz = (const float*)d_in[5];
  const float* bz = (const float*)d_in[6];
  const float* watt = (const float*)d_in[7];
  const float* batt = (const float*)d_in[8];
  const float* Wf = (const float*)d_in[9];
  const float* Wh = (const float*)d_in[10];
  float* out = (float*)d_out;

  float* P;
  float* X1;
  float* X2;
  float* X3;
  cudaGetSymbolAddress((void**)&P, g_P);
  cudaGetSymbolAddress((void**)&X1, g_X1);
  cudaGetSymbolAddress((void**)&X2, g_X2);
  cudaGetSymbolAddress((void**)&X3, g_X3);

  k_pre<<<769, 256>>>(Wz, bz, watt);
  k_t2<<<(Bdim * Sdim) / 8, 256>>>(bert, out);  // also bulk-copies bert -> out
  k_main<<<dim3(Bdim, 8), 256>>>(bert, dta, deprel, asp_s, asp_e, watt, batt);

  // mode 0: [v; bert_next](256 x 768) @ Wz   K=768 split 6 -> 576 blocks
  k_pgemm<128, Hdim><<<dim3(12, 8, 6), 256>>>(X1, Wz, P);
  k_epi<6, 0><<<256, 192>>>(bz, nullptr);
  // mode 1: X2(128 x 832) @ Wf   K=832 split 8 -> 384 blocks
  k_pgemm<104, Hdim + Ddim><<<dim3(12, 4, 8), 256>>>(X2, Wf, P);
  k_epi<8, 1><<<128, 192>>>(nullptr, nullptr);
  // mode 2: X3(128 x 1536) @ Wh   K=1536 split 8 -> 384 blocks
  k_pgemm<192, 2 * Hdim><<<dim3(12, 4, 8), 256>>>(X3, Wh, P);
  k_epi<8, 2><<<128, 192>>>(nullptr, out);
}

// round 6
// speedup vs baseline: 3.1600x; 1.1525x over previous
#include <cuda_runtime.h>
#include <cstdint>

#define Bdim 16
#define Sdim 256
#define Hdim 768
#define Ddim 64
#define NSLOT 128  // 16 batches * 8 slots (max aspect span is 6 rows)
#define H4 (Hdim / 4)

// Scratch (device globals; no allocation allowed)
__device__ __align__(16) float g_u1[Hdim];              // Wz @ w1
__device__ __align__(16) float g_u2[Hdim];              // Wz @ w2
__device__ float g_c[2];                                // bz.w1, bz.w2
__device__ __align__(16) float g_t2[Bdim * Sdim];       // (z @ w2)[b,j]
__device__ __align__(16) float g_X1[2 * NSLOT * Hdim];  // rows 0..127: v; 128..255: bert_next
__device__ __align__(16) float g_X2[NSLOT * (Hdim + Ddim)];  // [agg_z | agg_d]
__device__ __align__(16) float g_X3[NSLOT * (2 * Hdim)];     // [nrep | zrow]
__device__ __align__(16) float g_P[8 * 256 * Hdim];          // K-split partial sums
__device__ int g_valid[NSLOT];
__device__ int g_rowi[NSLOT];

__device__ __forceinline__ float warpReduceSum(float v) {
#pragma unroll
  for (int o = 16; o > 0; o >>= 1) v += __shfl_down_sync(0xffffffffu, v, o);
  return v;
}

__device__ __forceinline__ float blockReduceSum(float v, float* sm) {
  v = warpReduceSum(v);
  int w = threadIdx.x >> 5;
  if ((threadIdx.x & 31) == 0) sm[w] = v;
  __syncthreads();
  if (threadIdx.x < 8) {
    float x = sm[threadIdx.x];
#pragma unroll
    for (int o = 4; o > 0; o >>= 1) x += __shfl_down_sync(0xffu, x, o);
    if (threadIdx.x == 0) sm[0] = x;
  }
  __syncthreads();
  float r = sm[0];
  __syncthreads();
  return r;
}

__device__ __forceinline__ float blockReduceMax(float v, float* sm) {
#pragma unroll
  for (int o = 16; o > 0; o >>= 1) v = fmaxf(v, __shfl_down_sync(0xffffffffu, v, o));
  int w = threadIdx.x >> 5;
  if ((threadIdx.x & 31) == 0) sm[w] = v;
  __syncthreads();
  if (threadIdx.x < 8) {
    float x = sm[threadIdx.x];
#pragma unroll
    for (int o = 4; o > 0; o >>= 1) x = fmaxf(x, __shfl_down_sync(0xffu, x, o));
    if (threadIdx.x == 0) sm[0] = x;
  }
  __syncthreads();
  float r = sm[0];
  __syncthreads();
  return r;
}

// ---- packed f32x2 helpers (FFMA2 only reachable via PTX on sm_103a) ----
__device__ __forceinline__ unsigned long long splat2(float x) {
  unsigned long long r;
  asm("mov.b64 %0, {%1, %2};" : "=l"(r) : "f"(x), "f"(x));
  return r;
}
__device__ __forceinline__ void ffma2(unsigned long long& a, unsigned long long x,
                                      unsigned long long w) {
  asm("fma.rn.f32x2 %0, %1, %2, %0;" : "+l"(a) : "l"(x), "l"(w));
}
__device__ __forceinline__ float2 u2f(unsigned long long v) {
  float2 f;
  asm("mov.b64 {%0, %1}, %2;" : "=f"(f.x), "=f"(f.y) : "l"(v));
  return f;
}

// ---- cp.async helpers ----
__device__ __forceinline__ unsigned int saddr_of(const void* p) {
  return (unsigned int)__cvta_generic_to_shared(p);
}
__device__ __forceinline__ void cpasync16(unsigned int saddr, const void* g) {
  asm volatile("cp.async.ca.shared.global [%0], [%1], 16;" ::"r"(saddr), "l"(g));
}
__device__ __forceinline__ void cpasync_commit() {
  asm volatile("cp.async.commit_group;" ::: "memory");
}
__device__ __forceinline__ void cpasync_wait1() {
  asm volatile("cp.async.wait_group 1;" ::: "memory");
}
__device__ __forceinline__ void cpasync_wait0() {
  asm volatile("cp.async.wait_group 0;" ::: "memory");
}

// u1 = Wz @ w1, u2 = Wz @ w2, c = (bz.w1, bz.w2). grid 769, block 256.
__global__ void k_pre(const float* __restrict__ Wz, const float* __restrict__ bz,
                      const float* __restrict__ watt) {
  __shared__ float sm[8];
  int h = blockIdx.x, tid = threadIdx.x;
  float a1 = 0.f, a2 = 0.f;
  if (h < Hdim) {
    const float* wr = Wz + (size_t)h * Hdim;
    for (int k = tid; k < Hdim; k += 256) {
      float wv = wr[k];
      a1 = fmaf(wv, watt[k], a1);
      a2 = fmaf(wv, watt[Hdim + k], a2);
    }
  } else {
    for (int k = tid; k < Hdim; k += 256) {
      float bv = bz[k];
      a1 = fmaf(bv, watt[k], a1);
      a2 = fmaf(bv, watt[Hdim + k], a2);
    }
  }
  float r1 = blockReduceSum(a1, sm);
  float r2 = blockReduceSum(a2, sm);
  if (tid == 0) {
    if (h < Hdim) {
      g_u1[h] = r1;
      g_u2[h] = r2;
    } else {
      g_c[0] = r1;
      g_c[1] = r2;
    }
  }
}

// Fused: t2[r] = bert_row[r] @ u2 + bz.w2  AND  out[r] = bert_row[r] (bulk copy).
// grid 512, block 256 (one warp per row).
__global__ void k_t2(const float* __restrict__ bert, float* __restrict__ out) {
  int r = blockIdx.x * 8 + (threadIdx.x >> 5);
  int lane = threadIdx.x & 31;
  const float4* br = (const float4*)(bert + (size_t)r * Hdim);
  float4* orow = (float4*)(out + (size_t)r * Hdim);
  const float4* u24 = (const float4*)g_u2;
  float a = 0.f;
#pragma unroll
  for (int k = lane; k < H4; k += 32) {
    float4 bv = br[k];
    orow[k] = bv;
    float4 uv = u24[k];
    a = fmaf(bv.x, uv.x, a);
    a = fmaf(bv.y, uv.y, a);
    a = fmaf(bv.z, uv.z, a);
    a = fmaf(bv.w, uv.w, a);
  }
  a = warpReduceSum(a);
  if (lane == 0) g_t2[r] = a + g_c[1];
}

// Per needed row: logits + softmax + agg_d + v (attn-weighted bert) + bert_next.
// grid (16, 8), block 256.
__global__ void k_main(const float* __restrict__ bert, const float* __restrict__ dta,
                       const int* __restrict__ deprel, const int* __restrict__ asp_s,
                       const int* __restrict__ asp_e, const float* __restrict__ w_att,
                       const float* __restrict__ b_att) {
  int b = blockIdx.x, il = blockIdx.y;
  int slot = b * 8 + il;
  int tid = threadIdx.x;
  __shared__ float sm_s[Sdim];
  __shared__ float sm_p[Sdim];
  __shared__ float sm_red[8];
  int start = asp_s[b], endi = asp_e[b];
  int i = start + il;
  bool active = (i <= endi) && (i < Sdim);
  const int* deprow = deprel + (size_t)(b * Sdim + (active ? i : 0)) * Sdim;
  int hasn = 0;
  if (active) hasn = (deprow[tid] > 0);
  int any = __syncthreads_or(hasn);
  if (!active || !any) {
    for (int h = tid; h < Hdim; h += 256) {
      g_X1[slot * Hdim + h] = 0.f;
      g_X1[(NSLOT + slot) * Hdim + h] = 0.f;
    }
    if (tid < Ddim) g_X2[slot * (Hdim + Ddim) + Hdim + tid] = 0.f;
    if (tid == 0) {
      g_valid[slot] = 0;
      g_rowi[slot] = 0;
    }
    return;
  }

  int inext = (i + 1) & (Sdim - 1);
  const float* bi = bert + (size_t)(b * Sdim + inext) * Hdim;

  // s1 = (zs @ w1)[b,i] = bert[b,i+1] @ u1 + bz.w1
  float a = 0.f;
  for (int h = tid; h < Hdim; h += 256) a = fmaf(bi[h], g_u1[h], a);
  float s1 = blockReduceSum(a, sm_red);
  float base = s1 + g_c[0] + b_att[0];

  // logits: warp w handles j in [w*32, w*32+32)
  int w = tid >> 5, lane = tid & 31;
  float w3a = w_att[2 * Hdim + lane];
  float w3b = w_att[2 * Hdim + 32 + lane];
  const float* drow = dta + (size_t)(b * Sdim + i) * Sdim * Ddim;
  for (int j = w * 32; j < w * 32 + 32; ++j) {
    const float* dj = drow + (size_t)j * Ddim;
    float acc = dj[lane] * w3a + dj[lane + 32] * w3b;
    acc = warpReduceSum(acc);
    if (lane == 0) {
      float s = base + g_t2[b * Sdim + ((j + 1) & (Sdim - 1))] + acc;
      s = (s >= 0.f) ? s : 0.01f * s;
      if (deprow[j] <= 0) s = -1e9f;
      sm_s[j] = s;
    }
  }
  __syncthreads();

  // softmax over j
  float sv = sm_s[tid];
  float m = blockReduceMax(sv, sm_red);
  float e = expf(sv - m);
  float sum = blockReduceSum(e, sm_red);
  sm_p[tid] = e / sum;
  __syncthreads();

  // agg_d[d] = sum_j p[j] * dta[b,i,j,d]  (dta row is L2-hot from pass 1)
  {
    int d = tid & 63, part = tid >> 6;
    float ad = 0.f;
    const float* dp = drow + (size_t)(part * 64) * Ddim + d;
    for (int j = 0; j < 64; ++j) ad = fmaf(sm_p[part * 64 + j], dp[(size_t)j * Ddim], ad);
    sm_s[tid] = ad;
    __syncthreads();
    if (part == 0) {
      float t = sm_s[d] + sm_s[64 + d] + sm_s[128 + d] + sm_s[192 + d];
      g_X2[slot * (Hdim + Ddim) + Hdim + d] = t;
    }
  }

  // v[h] = sum_j p[j] * bert[b, (j+1)%S, h]  — float4, threads 0..191
  if (tid < H4) {
    const float4* bb4 = (const float4*)(bert + (size_t)b * Sdim * Hdim);
    float4 acc4 = make_float4(0.f, 0.f, 0.f, 0.f);
#pragma unroll 8
    for (int j = 0; j < Sdim; ++j) {
      float p = sm_p[j];
      float4 bv = bb4[(size_t)((j + 1) & (Sdim - 1)) * H4 + tid];
      acc4.x = fmaf(p, bv.x, acc4.x);
      acc4.y = fmaf(p, bv.y, acc4.y);
      acc4.z = fmaf(p, bv.z, acc4.z);
      acc4.w = fmaf(p, bv.w, acc4.w);
    }
    ((float4*)g_X1)[slot * H4 + tid] = acc4;
    ((float4*)g_X1)[(NSLOT + slot) * H4 + tid] = ((const float4*)bi)[tid];
  }
  if (tid == 0) {
    g_valid[slot] = 1;
    g_rowi[slot] = i;
  }
}

// 16 FFMA2 on 2 rows x 4 cols from one k4 slice.
#define FMAB(X0, X1, W0, W1, W2, W3)                  \
  do {                                                \
    unsigned long long s0, s1;                        \
    s0 = splat2((X0).x);                              \
    s1 = splat2((X1).x);                              \
    ffma2(a0l, s0, (W0).x);                           \
    ffma2(a0h, s0, (W0).y);                           \
    ffma2(a1l, s1, (W0).x);                           \
    ffma2(a1h, s1, (W0).y);                           \
    s0 = splat2((X0).y);                              \
    s1 = splat2((X1).y);                              \
    ffma2(a0l, s0, (W1).x);                           \
    ffma2(a0h, s0, (W1).y);                           \
    ffma2(a1l, s1, (W1).x);                           \
    ffma2(a1h, s1, (W1).y);                           \
    s0 = splat2((X0).z);                              \
    s1 = splat2((X1).z);                              \
    ffma2(a0l, s0, (W2).x);                           \
    ffma2(a0h, s0, (W2).y);                           \
    ffma2(a1l, s1, (W2).x);                           \
    ffma2(a1h, s1, (W2).y);                           \
    s0 = splat2((X0).w);                              \
    s1 = splat2((X1).w);                              \
    ffma2(a0l, s0, (W3).x);                           \
    ffma2(a0h, s0, (W3).y);                           \
    ffma2(a1l, s1, (W3).x);                           \
    ffma2(a1h, s1, (W3).y);                           \
  } while (0)

// cp.async smem-staged partial GEMM with packed f32x2 FMAs.
// Block 256 = 16 col-threads (4 cols) x 16 row-threads (2 rows) -> 64x32 tile.
// K-tile 32, double-buffered (W 8KB + X 4KB per stage).
// grid = (Hdim/64, rows/32, ksplit); z writes partials to P[(z*NROWS + r)*Hdim + h].
template <int KS, int LDX, int NIT, int NROWS>
__global__ void __launch_bounds__(256) k_sgemm(const float* __restrict__ X,
                                               const float* __restrict__ W,
                                               float* __restrict__ P) {
  static_assert(KS == NIT * 32, "");
  __shared__ __align__(16) float sW[2][32 * 64];
  __shared__ __align__(16) float sX[2][32 * 32];

  int tid = threadIdx.x;
  int ct = tid & 15, rt = tid >> 4;
  int hb = blockIdx.x * 64;
  int rb = blockIdx.y * 32;
  int z = blockIdx.z;

  const float* Wg = W + (size_t)z * KS * Hdim + hb;
  const float* Xg = X + (size_t)rb * LDX + (size_t)z * KS;

  // stage loader: W tile 32x64 (512 float4), X tile 32x32 (256 float4)
  int wi = tid >> 4, wj = (tid & 15) * 4;          // W: thread's first float4
  int xi = tid >> 3, xj = (tid & 7) * 4;           // X row, col
  unsigned int sw0 = saddr_of(&sW[0][0]);
  unsigned int sx0 = saddr_of(&sX[0][0]);

#define LOAD_STAGE(stage, buf)                                                  \
  do {                                                                          \
    int k0 = (stage) * 32;                                                      \
    unsigned int swb = sw0 + (buf) * (32 * 64 * 4);                             \
    unsigned int sxb = sx0 + (buf) * (32 * 32 * 4);                             \
    cpasync16(swb + (wi * 64 + wj) * 4, Wg + (size_t)(k0 + wi) * Hdim + wj);    \
    cpasync16(swb + ((wi + 16) * 64 + wj) * 4,                                  \
              Wg + (size_t)(k0 + wi + 16) * Hdim + wj);                         \
    cpasync16(sxb + (xi * 32 + xj) * 4, Xg + (size_t)xi * LDX + k0 + xj);       \
    cpasync_commit();                                                           \
  } while (0)

  LOAD_STAGE(0, 0);
  if (NIT > 1) LOAD_STAGE(1, 1);

  unsigned long long a0l = 0, a0h = 0, a1l = 0, a1h = 0;
  int r0 = rt * 2;

#pragma unroll 1
  for (int it = 0; it < NIT; ++it) {
    if (it < NIT - 1)
      cpasync_wait1();
    else
      cpasync_wait0();
    __syncthreads();
    int buf = it & 1;
    const float4* xr0 = (const float4*)&sX[buf][r0 * 32];
    const float4* xr1 = (const float4*)&sX[buf][(r0 + 1) * 32];
    const float* wb = &sW[buf][ct * 4];
#pragma unroll
    for (int k4 = 0; k4 < 8; ++k4) {
      float4 x0 = xr0[k4];
      float4 x1 = xr1[k4];
      ulonglong2 w0 = *(const ulonglong2*)(wb + (k4 * 4 + 0) * 64);
      ulonglong2 w1 = *(const ulonglong2*)(wb + (k4 * 4 + 1) * 64);
      ulonglong2 w2 = *(const ulonglong2*)(wb + (k4 * 4 + 2) * 64);
      ulonglong2 w3 = *(const ulonglong2*)(wb + (k4 * 4 + 3) * 64);
      FMAB(x0, x1, w0, w1, w2, w3);
    }
    __syncthreads();
    if (it + 2 < NIT) LOAD_STAGE(it + 2, buf);
  }
#undef LOAD_STAGE

  float2 f0l = u2f(a0l), f0h = u2f(a0h), f1l = u2f(a1l), f1h = u2f(a1h);
  int r = rb + r0;
  float* pr = P + ((size_t)(z * NROWS + r)) * Hdim + hb + ct * 4;
  *(float4*)pr = make_float4(f0l.x, f0l.y, f0h.x, f0h.y);
  *(float4*)(pr + Hdim) = make_float4(f1l.x, f1l.y, f1h.x, f1h.y);
}

// Epilogue: combine NZ K-split partials and route per MODE. block 192.
// MODE 0: +bias -> agg_z (X2) / zrow (X3 cols 768..); MODE 1: -> nrep (X3);
// MODE 2: scatter valid rows to out[(i+1)].
template <int NZ, int NROWS, int MODE>
__global__ void k_epi(const float* __restrict__ bias, float* __restrict__ outp) {
  int r = blockIdx.x;
  if (MODE == 2 && !g_valid[r]) return;
  int h = threadIdx.x * 4;
  float4 v = make_float4(0.f, 0.f, 0.f, 0.f);
#pragma unroll
  for (int zz = 0; zz < NZ; ++zz) {
    const float4 p = *(const float4*)(g_P + (size_t)(zz * NROWS + r) * Hdim + h);
    v.x += p.x;
    v.y += p.y;
    v.z += p.z;
    v.w += p.w;
  }
  if (MODE == 0) {
    const float4 bb = *(const float4*)(bias + h);
    v.x += bb.x;
    v.y += bb.y;
    v.z += bb.z;
    v.w += bb.w;
    if (r < NSLOT)
      *(float4*)(g_X2 + (size_t)r * (Hdim + Ddim) + h) = v;  // agg_z
    else
      *(float4*)(g_X3 + (size_t)(r - NSLOT) * (2 * Hdim) + Hdim + h) = v;  // zrow
  } else if (MODE == 1) {
    *(float4*)(g_X3 + (size_t)r * (2 * Hdim) + h) = v;  // nrep
  } else {
    int bb = r >> 3;
    int o = (g_rowi[r] + 1) & (Sdim - 1);
    *(float4*)(outp + ((size_t)(bb * Sdim + o)) * Hdim + h) = v;
  }
}

extern "C" void kernel_launch(void* const* d_in, const int* in_sizes, int n_in,
                              void* d_out, int out_size) {
  const float* bert = (const float*)d_in[0];
  const float* dta = (const float*)d_in[1];
  const int* deprel = (const int*)d_in[2];
  const int* asp_s = (const int*)d_in[3];
  const int* asp_e = (const int*)d_in[4];
  const float* Wz = (const float*)d_in[5];
  const float* bz = (const float*)d_in[6];
  const float* watt = (const float*)d_in[7];
  const float* batt = (const float*)d_in[8];
  const float* Wf = (const float*)d_in[9];
  const float* Wh = (const float*)d_in[10];
  float* out = (float*)d_out;

  float* P;
  float* X1;
  float* X2;
  float* X3;
  cudaGetSymbolAddress((void**)&P, g_P);
  cudaGetSymbolAddress((void**)&X1, g_X1);
  cudaGetSymbolAddress((void**)&X2, g_X2);
  cudaGetSymbolAddress((void**)&X3, g_X3);

  k_pre<<<769, 256>>>(Wz, bz, watt);
  k_t2<<<(Bdim * Sdim) / 8, 256>>>(bert, out);  // also bulk-copies bert -> out
  k_main<<<dim3(Bdim, 8), 256>>>(bert, dta, deprel, asp_s, asp_e, watt, batt);

  // mode 0: [v; bert_next](256 x 768) @ Wz   K=768 split 6 -> 576 blocks
  k_sgemm<128, Hdim, 4, 256><<<dim3(12, 8, 6), 256>>>(X1, Wz, P);
  k_epi<6, 256, 0><<<256, 192>>>(bz, nullptr);
  // mode 1: X2(128 x 832) @ Wf   K=832 split 13 -> 624 blocks
  k_sgemm<64, Hdim + Ddim, 2, 128><<<dim3(12, 4, 13), 256>>>(X2, Wf, P);
  k_epi<13, 128, 1><<<128, 192>>>(nullptr, nullptr);
  // mode 2: X3(128 x 1536) @ Wh   K=1536 split 8 -> 384 blocks
  k_sgemm<192, 2 * Hdim, 6, 128><<<dim3(12, 4, 8), 256>>>(X3, Wh, P);
  k_epi<8, 128, 2><<<128, 192>>>(nullptr, out);
}

// round 7
// speedup vs baseline: 3.2586x; 1.0312x over previous
#include <cuda_runtime.h>
#include <cstdint>

#define Bdim 16
#define Sdim 256
#define Hdim 768
#define Ddim 64
#define NSLOT 128  // 16 batches * 8 slots (max aspect span is 6 rows)
#define H4 (Hdim / 4)

// Scratch (device globals; no allocation allowed)
__device__ __align__(16) float g_u1[Hdim];              // Wz @ w1
__device__ __align__(16) float g_u2[Hdim];              // Wz @ w2
__device__ float g_c[2];                                // bz.w1, bz.w2
__device__ __align__(16) float g_t2[Bdim * Sdim];       // (z @ w2)[b,j]
__device__ __align__(16) float g_X1[2 * NSLOT * Hdim];  // rows 0..127: v; 128..255: bert_next
__device__ __align__(16) float g_X2[NSLOT * (Hdim + Ddim)];  // [agg_z | agg_d]
__device__ __align__(16) float g_X3[NSLOT * (2 * Hdim)];     // [nrep | zrow]
__device__ __align__(16) float g_P[3072 * Hdim];             // K-split partial sums
__device__ int g_valid[NSLOT];
__device__ int g_rowi[NSLOT];

__device__ __forceinline__ float warpReduceSum(float v) {
#pragma unroll
  for (int o = 16; o > 0; o >>= 1) v += __shfl_down_sync(0xffffffffu, v, o);
  return v;
}

__device__ __forceinline__ float blockReduceSum(float v, float* sm) {
  v = warpReduceSum(v);
  int w = threadIdx.x >> 5;
  if ((threadIdx.x & 31) == 0) sm[w] = v;
  __syncthreads();
  if (threadIdx.x < 8) {
    float x = sm[threadIdx.x];
#pragma unroll
    for (int o = 4; o > 0; o >>= 1) x += __shfl_down_sync(0xffu, x, o);
    if (threadIdx.x == 0) sm[0] = x;
  }
  __syncthreads();
  float r = sm[0];
  __syncthreads();
  return r;
}

__device__ __forceinline__ float blockReduceMax(float v, float* sm) {
#pragma unroll
  for (int o = 16; o > 0; o >>= 1) v = fmaxf(v, __shfl_down_sync(0xffffffffu, v, o));
  int w = threadIdx.x >> 5;
  if ((threadIdx.x & 31) == 0) sm[w] = v;
  __syncthreads();
  if (threadIdx.x < 8) {
    float x = sm[threadIdx.x];
#pragma unroll
    for (int o = 4; o > 0; o >>= 1) x = fmaxf(x, __shfl_down_sync(0xffu, x, o));
    if (threadIdx.x == 0) sm[0] = x;
  }
  __syncthreads();
  float r = sm[0];
  __syncthreads();
  return r;
}

// ---- packed f32x2 helpers (FFMA2 only reachable via PTX on sm_103a) ----
__device__ __forceinline__ unsigned long long splat2(float x) {
  unsigned long long r;
  asm("mov.b64 %0, {%1, %2};" : "=l"(r) : "f"(x), "f"(x));
  return r;
}
__device__ __forceinline__ void ffma2(unsigned long long& a, unsigned long long x,
                                      unsigned long long w) {
  asm("fma.rn.f32x2 %0, %1, %2, %0;" : "+l"(a) : "l"(x), "l"(w));
}
__device__ __forceinline__ float2 u2f(unsigned long long v) {
  float2 f;
  asm("mov.b64 {%0, %1}, %2;" : "=f"(f.x), "=f"(f.y) : "l"(v));
  return f;
}

// ---- cp.async helpers ----
__device__ __forceinline__ unsigned int saddr_of(const void* p) {
  return (unsigned int)__cvta_generic_to_shared(p);
}
__device__ __forceinline__ void cpasync16(unsigned int saddr, const void* g) {
  asm volatile("cp.async.ca.shared.global [%0], [%1], 16;" ::"r"(saddr), "l"(g));
}
__device__ __forceinline__ void cpasync_commit() {
  asm volatile("cp.async.commit_group;" ::: "memory");
}
__device__ __forceinline__ void cpasync_wait1() {
  asm volatile("cp.async.wait_group 1;" ::: "memory");
}
__device__ __forceinline__ void cpasync_wait0() {
  asm volatile("cp.async.wait_group 0;" ::: "memory");
}

// u1 = Wz @ w1, u2 = Wz @ w2, c = (bz.w1, bz.w2). grid 769, block 256.
__global__ void k_pre(const float* __restrict__ Wz, const float* __restrict__ bz,
                      const float* __restrict__ watt) {
  __shared__ float sm[8];
  int h = blockIdx.x, tid = threadIdx.x;
  float a1 = 0.f, a2 = 0.f;
  if (h < Hdim) {
    const float* wr = Wz + (size_t)h * Hdim;
    for (int k = tid; k < Hdim; k += 256) {
      float wv = wr[k];
      a1 = fmaf(wv, watt[k], a1);
      a2 = fmaf(wv, watt[Hdim + k], a2);
    }
  } else {
    for (int k = tid; k < Hdim; k += 256) {
      float bv = bz[k];
      a1 = fmaf(bv, watt[k], a1);
      a2 = fmaf(bv, watt[Hdim + k], a2);
    }
  }
  float r1 = blockReduceSum(a1, sm);
  float r2 = blockReduceSum(a2, sm);
  if (tid == 0) {
    if (h < Hdim) {
      g_u1[h] = r1;
      g_u2[h] = r2;
    } else {
      g_c[0] = r1;
      g_c[1] = r2;
    }
  }
}

// Fused: t2[r] = bert_row[r] @ u2 + bz.w2  AND  out[r] = bert_row[r] (bulk copy).
// grid 512, block 256 (one warp per row).
__global__ void k_t2(const float* __restrict__ bert, float* __restrict__ out) {
  int r = blockIdx.x * 8 + (threadIdx.x >> 5);
  int lane = threadIdx.x & 31;
  const float4* br = (const float4*)(bert + (size_t)r * Hdim);
  float4* orow = (float4*)(out + (size_t)r * Hdim);
  const float4* u24 = (const float4*)g_u2;
  float a = 0.f;
#pragma unroll
  for (int k = lane; k < H4; k += 32) {
    float4 bv = br[k];
    orow[k] = bv;
    float4 uv = u24[k];
    a = fmaf(bv.x, uv.x, a);
    a = fmaf(bv.y, uv.y, a);
    a = fmaf(bv.z, uv.z, a);
    a = fmaf(bv.w, uv.w, a);
  }
  a = warpReduceSum(a);
  if (lane == 0) g_t2[r] = a + g_c[1];
}

// Per needed row: logits + softmax + agg_d + v (attn-weighted bert) + bert_next.
// grid (16, 8), block 256.
__global__ void k_main(const float* __restrict__ bert, const float* __restrict__ dta,
                       const int* __restrict__ deprel, const int* __restrict__ asp_s,
                       const int* __restrict__ asp_e, const float* __restrict__ w_att,
                       const float* __restrict__ b_att) {
  int b = blockIdx.x, il = blockIdx.y;
  int slot = b * 8 + il;
  int tid = threadIdx.x;
  __shared__ float sm_s[Sdim];
  __shared__ float sm_p[Sdim];
  __shared__ float sm_red[8];
  int start = asp_s[b], endi = asp_e[b];
  int i = start + il;
  bool active = (i <= endi) && (i < Sdim);
  const int* deprow = deprel + (size_t)(b * Sdim + (active ? i : 0)) * Sdim;
  int hasn = 0;
  if (active) hasn = (deprow[tid] > 0);
  int any = __syncthreads_or(hasn);
  if (!active || !any) {
    for (int h = tid; h < Hdim; h += 256) {
      g_X1[slot * Hdim + h] = 0.f;
      g_X1[(NSLOT + slot) * Hdim + h] = 0.f;
    }
    if (tid < Ddim) g_X2[slot * (Hdim + Ddim) + Hdim + tid] = 0.f;
    if (tid == 0) {
      g_valid[slot] = 0;
      g_rowi[slot] = 0;
    }
    return;
  }

  int inext = (i + 1) & (Sdim - 1);
  const float* bi = bert + (size_t)(b * Sdim + inext) * Hdim;

  // s1 = (zs @ w1)[b,i] = bert[b,i+1] @ u1 + bz.w1
  float a = 0.f;
  for (int h = tid; h < Hdim; h += 256) a = fmaf(bi[h], g_u1[h], a);
  float s1 = blockReduceSum(a, sm_red);
  float base = s1 + g_c[0] + b_att[0];

  // logits: warp w handles j in [w*32, w*32+32)
  int w = tid >> 5, lane = tid & 31;
  float w3a = w_att[2 * Hdim + lane];
  float w3b = w_att[2 * Hdim + 32 + lane];
  const float* drow = dta + (size_t)(b * Sdim + i) * Sdim * Ddim;
  for (int j = w * 32; j < w * 32 + 32; ++j) {
    const float* dj = drow + (size_t)j * Ddim;
    float acc = dj[lane] * w3a + dj[lane + 32] * w3b;
    acc = warpReduceSum(acc);
    if (lane == 0) {
      float s = base + g_t2[b * Sdim + ((j + 1) & (Sdim - 1))] + acc;
      s = (s >= 0.f) ? s : 0.01f * s;
      if (deprow[j] <= 0) s = -1e9f;
      sm_s[j] = s;
    }
  }
  __syncthreads();

  // softmax over j
  float sv = sm_s[tid];
  float m = blockReduceMax(sv, sm_red);
  float e = expf(sv - m);
  float sum = blockReduceSum(e, sm_red);
  sm_p[tid] = e / sum;
  __syncthreads();

  // agg_d[d] = sum_j p[j] * dta[b,i,j,d]  (dta row is L2-hot from pass 1)
  {
    int d = tid & 63, part = tid >> 6;
    float ad = 0.f;
    const float* dp = drow + (size_t)(part * 64) * Ddim + d;
    for (int j = 0; j < 64; ++j) ad = fmaf(sm_p[part * 64 + j], dp[(size_t)j * Ddim], ad);
    sm_s[tid] = ad;
    __syncthreads();
    if (part == 0) {
      float t = sm_s[d] + sm_s[64 + d] + sm_s[128 + d] + sm_s[192 + d];
      g_X2[slot * (Hdim + Ddim) + Hdim + d] = t;
    }
  }

  // v[h] = sum_j p[j] * bert[b, (j+1)%S, h]  — float4, threads 0..191
  if (tid < H4) {
    const float4* bb4 = (const float4*)(bert + (size_t)b * Sdim * Hdim);
    float4 acc4 = make_float4(0.f, 0.f, 0.f, 0.f);
#pragma unroll 8
    for (int j = 0; j < Sdim; ++j) {
      float p = sm_p[j];
      float4 bv = bb4[(size_t)((j + 1) & (Sdim - 1)) * H4 + tid];
      acc4.x = fmaf(p, bv.x, acc4.x);
      acc4.y = fmaf(p, bv.y, acc4.y);
      acc4.z = fmaf(p, bv.z, acc4.z);
      acc4.w = fmaf(p, bv.w, acc4.w);
    }
    ((float4*)g_X1)[slot * H4 + tid] = acc4;
    ((float4*)g_X1)[(NSLOT + slot) * H4 + tid] = ((const float4*)bi)[tid];
  }
  if (tid == 0) {
    g_valid[slot] = 1;
    g_rowi[slot] = i;
  }
}

// One k-component: splat X[row] and feed 2 FFMA2 (4 cols) per row, 4 rows.
#define FMAK(C, WV)                                   \
  do {                                                \
    unsigned long long s;                             \
    s = splat2(x0.C);                                 \
    ffma2(a0l, s, (WV).x);                            \
    ffma2(a0h, s, (WV).y);                            \
    s = splat2(x1.C);                                 \
    ffma2(a1l, s, (WV).x);                            \
    ffma2(a1h, s, (WV).y);                            \
    s = splat2(x2.C);                                 \
    ffma2(a2l, s, (WV).x);                            \
    ffma2(a2h, s, (WV).y);                            \
    s = splat2(x3.C);                                 \
    ffma2(a3l, s, (WV).x);                            \
    ffma2(a3h, s, (WV).y);                            \
  } while (0)

// cp.async smem-staged partial GEMM, packed f32x2, 4 rows x 4 cols per thread.
// Block 256 = 16 ct x 16 rt -> tile 64 cols x 64 rows. K-tile 32, double-buffered.
// grid = (Hdim/64, rows/64, ksplit); z writes partials to P[(z*NROWS + r)*Hdim + h].
template <int KS, int LDX, int NIT, int NROWS>
__global__ void __launch_bounds__(256) k_sgemm(const float* __restrict__ X,
                                               const float* __restrict__ W,
                                               float* __restrict__ P) {
  static_assert(KS == NIT * 32, "");
  __shared__ __align__(16) float sW[2][32 * 64];
  __shared__ __align__(16) float sX[2][64 * 32];

  int tid = threadIdx.x;
  int ct = tid & 15, rt = tid >> 4;
  int hb = blockIdx.x * 64;
  int rb = blockIdx.y * 64;
  int z = blockIdx.z;

  const float* Wg = W + (size_t)z * KS * Hdim + hb;
  const float* Xg = X + (size_t)rb * LDX + (size_t)z * KS;

  // stage loader: W tile 32x64 (512 float4), X tile 64x32 (512 float4)
  int wi = tid >> 4, wj = (tid & 15) * 4;  // W row, first col
  int xi = tid >> 3, xj = (tid & 7) * 4;   // X row, col
  unsigned int sw0 = saddr_of(&sW[0][0]);
  unsigned int sx0 = saddr_of(&sX[0][0]);

#define LOAD_STAGE(stage, buf)                                                  \
  do {                                                                          \
    int k0 = (stage) * 32;                                                      \
    unsigned int swb = sw0 + (buf) * (32 * 64 * 4);                             \
    unsigned int sxb = sx0 + (buf) * (64 * 32 * 4);                             \
    cpasync16(swb + (wi * 64 + wj) * 4, Wg + (size_t)(k0 + wi) * Hdim + wj);    \
    cpasync16(swb + ((wi + 16) * 64 + wj) * 4,                                  \
              Wg + (size_t)(k0 + wi + 16) * Hdim + wj);                         \
    cpasync16(sxb + (xi * 32 + xj) * 4, Xg + (size_t)xi * LDX + k0 + xj);       \
    cpasync16(sxb + ((xi + 32) * 32 + xj) * 4,                                  \
              Xg + (size_t)(xi + 32) * LDX + k0 + xj);                          \
    cpasync_commit();                                                           \
  } while (0)

  LOAD_STAGE(0, 0);
  if (NIT > 1) LOAD_STAGE(1, 1);

  unsigned long long a0l = 0, a0h = 0, a1l = 0, a1h = 0;
  unsigned long long a2l = 0, a2h = 0, a3l = 0, a3h = 0;
  int r0 = rt * 4;

#pragma unroll 1
  for (int it = 0; it < NIT; ++it) {
    if (it < NIT - 1)
      cpasync_wait1();
    else
      cpasync_wait0();
    __syncthreads();
    int buf = it & 1;
    const float4* xr0 = (const float4*)&sX[buf][(r0 + 0) * 32];
    const float4* xr1 = (const float4*)&sX[buf][(r0 + 1) * 32];
    const float4* xr2 = (const float4*)&sX[buf][(r0 + 2) * 32];
    const float4* xr3 = (const float4*)&sX[buf][(r0 + 3) * 32];
    const float* wb = &sW[buf][ct * 4];
#pragma unroll
    for (int k4 = 0; k4 < 8; ++k4) {
      float4 x0 = xr0[k4];
      float4 x1 = xr1[k4];
      float4 x2 = xr2[k4];
      float4 x3 = xr3[k4];
      ulonglong2 w0 = *(const ulonglong2*)(wb + (k4 * 4 + 0) * 64);
      ulonglong2 w1 = *(const ulonglong2*)(wb + (k4 * 4 + 1) * 64);
      ulonglong2 w2 = *(const ulonglong2*)(wb + (k4 * 4 + 2) * 64);
      ulonglong2 w3 = *(const ulonglong2*)(wb + (k4 * 4 + 3) * 64);
      FMAK(x, w0);
      FMAK(y, w1);
      FMAK(z, w2);
      FMAK(w, w3);
    }
    __syncthreads();
    if (it + 2 < NIT) LOAD_STAGE(it + 2, buf);
  }
#undef LOAD_STAGE

  int r = rb + r0;
  float* pr = P + ((size_t)(z * NROWS + r)) * Hdim + hb + ct * 4;
  {
    float2 fl = u2f(a0l), fh = u2f(a0h);
    *(float4*)pr = make_float4(fl.x, fl.y, fh.x, fh.y);
  }
  {
    float2 fl = u2f(a1l), fh = u2f(a1h);
    *(float4*)(pr + Hdim) = make_float4(fl.x, fl.y, fh.x, fh.y);
  }
  {
    float2 fl = u2f(a2l), fh = u2f(a2h);
    *(float4*)(pr + 2 * Hdim) = make_float4(fl.x, fl.y, fh.x, fh.y);
  }
  {
    float2 fl = u2f(a3l), fh = u2f(a3h);
    *(float4*)(pr + 3 * Hdim) = make_float4(fl.x, fl.y, fh.x, fh.y);
  }
}

// Epilogue: combine NZ K-split partials and route per MODE. block 192.
// MODE 0: +bias -> agg_z (X2) / zrow (X3 cols 768..); MODE 1: -> nrep (X3);
// MODE 2: scatter valid rows to out[(i+1)].
template <int NZ, int NROWS, int MODE>
__global__ void k_epi(const float* __restrict__ bias, float* __restrict__ outp) {
  int r = blockIdx.x;
  if (MODE == 2 && !g_valid[r]) return;
  int h = threadIdx.x * 4;
  float4 v = make_float4(0.f, 0.f, 0.f, 0.f);
#pragma unroll
  for (int zz = 0; zz < NZ; ++zz) {
    const float4 p = *(const float4*)(g_P + (size_t)(zz * NROWS + r) * Hdim + h);
    v.x += p.x;
    v.y += p.y;
    v.z += p.z;
    v.w += p.w;
  }
  if (MODE == 0) {
    const float4 bb = *(const float4*)(bias + h);
    v.x += bb.x;
    v.y += bb.y;
    v.z += bb.z;
    v.w += bb.w;
    if (r < NSLOT)
      *(float4*)(g_X2 + (size_t)r * (Hdim + Ddim) + h) = v;  // agg_z
    else
      *(float4*)(g_X3 + (size_t)(r - NSLOT) * (2 * Hdim) + Hdim + h) = v;  // zrow
  } else if (MODE == 1) {
    *(float4*)(g_X3 + (size_t)r * (2 * Hdim) + h) = v;  // nrep
  } else {
    int bb = r >> 3;
    int o = (g_rowi[r] + 1) & (Sdim - 1);
    *(float4*)(outp + ((size_t)(bb * Sdim + o)) * Hdim + h) = v;
  }
}

extern "C" void kernel_launch(void* const* d_in, const int* in_sizes, int n_in,
                              void* d_out, int out_size) {
  const float* bert = (const float*)d_in[0];
  const float* dta = (const float*)d_in[1];
  const int* deprel = (const int*)d_in[2];
  const int* asp_s = (const int*)d_in[3];
  const int* asp_e = (const int*)d_in[4];
  const float* Wz = (const float*)d_in[5];
  const float* bz = (const float*)d_in[6];
  const float* watt = (const float*)d_in[7];
  const float* batt = (const float*)d_in[8];
  const float* Wf = (const float*)d_in[9];
  const float* Wh = (const float*)d_in[10];
  float* out = (float*)d_out;

  float* P;
  float* X1;
  float* X2;
  float* X3;
  cudaGetSymbolAddress((void**)&P, g_P);
  cudaGetSymbolAddress((void**)&X1, g_X1);
  cudaGetSymbolAddress((void**)&X2, g_X2);
  cudaGetSymbolAddress((void**)&X3, g_X3);

  k_pre<<<769, 256>>>(Wz, bz, watt);
  k_t2<<<(Bdim * Sdim) / 8, 256>>>(bert, out);  // also bulk-copies bert -> out
  k_main<<<dim3(Bdim, 8), 256>>>(bert, dta, deprel, asp_s, asp_e, watt, batt);

  // mode 0: [v; bert_next](256 x 768) @ Wz   K=768 split 12 -> 576 blocks
  k_sgemm<64, Hdim, 2, 256><<<dim3(12, 4, 12), 256>>>(X1, Wz, P);
  k_epi<12, 256, 0><<<256, 192>>>(bz, nullptr);
  // mode 1: X2(128 x 832) @ Wf   K=832 split 13 -> 312 blocks
  k_sgemm<64, Hdim + Ddim, 2, 128><<<dim3(12, 2, 13), 256>>>(X2, Wf, P);
  k_epi<13, 128, 1><<<128, 192>>>(nullptr, nullptr);
  // mode 2: X3(128 x 1536) @ Wh   K=1536 split 24 -> 576 blocks
  k_sgemm<64, 2 * Hdim, 2, 128><<<dim3(12, 2, 24), 256>>>(X3, Wh, P);
  k_epi<24, 128, 2><<<128, 192>>>(nullptr, out);
}

// round 8
// speedup vs baseline: 3.7163x; 1.1404x over previous
#include <cuda_runtime.h>
#include <cstdint>

#define Bdim 16
#define Sdim 256
#define Hdim 768
#define Ddim 64
#define NSLOT 128  // 16 batches * 8 slots (max aspect span is 6 rows)
#define H4 (Hdim / 4)

// Scratch (device globals; no allocation allowed)
__device__ __align__(16) float g_u1[Hdim];              // Wz @ w1
__device__ __align__(16) float g_u2[Hdim];              // Wz @ w2
__device__ float g_c[2];                                // bz.w1, bz.w2
__device__ __align__(16) float g_t2[Bdim * Sdim];       // (z @ w2)[b,j]
__device__ __align__(16) float g_X1[2 * NSLOT * Hdim];  // rows 0..127: v; 128..255: bert_next
__device__ __align__(16) float g_X2[NSLOT * (Hdim + Ddim)];  // [agg_z | agg_d]
__device__ __align__(16) float g_X3[NSLOT * (2 * Hdim)];     // [nrep | zrow]
__device__ __align__(16) float g_P[3328 * Hdim];             // K-split partial sums
__device__ int g_valid[NSLOT];
__device__ int g_rowi[NSLOT];

__device__ __forceinline__ float warpReduceSum(float v) {
#pragma unroll
  for (int o = 16; o > 0; o >>= 1) v += __shfl_down_sync(0xffffffffu, v, o);
  return v;
}

__device__ __forceinline__ float blockReduceSum(float v, float* sm) {
  v = warpReduceSum(v);
  int w = threadIdx.x >> 5;
  if ((threadIdx.x & 31) == 0) sm[w] = v;
  __syncthreads();
  if (threadIdx.x < 8) {
    float x = sm[threadIdx.x];
#pragma unroll
    for (int o = 4; o > 0; o >>= 1) x += __shfl_down_sync(0xffu, x, o);
    if (threadIdx.x == 0) sm[0] = x;
  }
  __syncthreads();
  float r = sm[0];
  __syncthreads();
  return r;
}

__device__ __forceinline__ float blockReduceMax(float v, float* sm) {
#pragma unroll
  for (int o = 16; o > 0; o >>= 1) v = fmaxf(v, __shfl_down_sync(0xffffffffu, v, o));
  int w = threadIdx.x >> 5;
  if ((threadIdx.x & 31) == 0) sm[w] = v;
  __syncthreads();
  if (threadIdx.x < 8) {
    float x = sm[threadIdx.x];
#pragma unroll
    for (int o = 4; o > 0; o >>= 1) x = fmaxf(x, __shfl_down_sync(0xffu, x, o));
    if (threadIdx.x == 0) sm[0] = x;
  }
  __syncthreads();
  float r = sm[0];
  __syncthreads();
  return r;
}

// ---- packed f32x2 helpers (FFMA2 only reachable via PTX on sm_103a) ----
__device__ __forceinline__ unsigned long long splat2(float x) {
  unsigned long long r;
  asm("mov.b64 %0, {%1, %2};" : "=l"(r) : "f"(x), "f"(x));
  return r;
}
__device__ __forceinline__ void ffma2(unsigned long long& a, unsigned long long x,
                                      unsigned long long w) {
  asm("fma.rn.f32x2 %0, %1, %2, %0;" : "+l"(a) : "l"(x), "l"(w));
}
__device__ __forceinline__ float2 u2f(unsigned long long v) {
  float2 f;
  asm("mov.b64 {%0, %1}, %2;" : "=f"(f.x), "=f"(f.y) : "l"(v));
  return f;
}

// ---- cp.async helpers ----
__device__ __forceinline__ unsigned int saddr_of(const void* p) {
  return (unsigned int)__cvta_generic_to_shared(p);
}
__device__ __forceinline__ void cpasync16(unsigned int saddr, const void* g) {
  asm volatile("cp.async.ca.shared.global [%0], [%1], 16;" ::"r"(saddr), "l"(g));
}
__device__ __forceinline__ void cpasync_commit() {
  asm volatile("cp.async.commit_group;" ::: "memory");
}
__device__ __forceinline__ void cpasync_wait1() {
  asm volatile("cp.async.wait_group 1;" ::: "memory");
}
__device__ __forceinline__ void cpasync_wait0() {
  asm volatile("cp.async.wait_group 0;" ::: "memory");
}

// u1 = Wz @ w1, u2 = Wz @ w2, c = (bz.w1, bz.w2). grid 769, block 256.
__global__ void k_pre(const float* __restrict__ Wz, const float* __restrict__ bz,
                      const float* __restrict__ watt) {
  __shared__ float sm[8];
  int h = blockIdx.x, tid = threadIdx.x;
  float a1 = 0.f, a2 = 0.f;
  if (h < Hdim) {
    const float* wr = Wz + (size_t)h * Hdim;
    for (int k = tid; k < Hdim; k += 256) {
      float wv = wr[k];
      a1 = fmaf(wv, watt[k], a1);
      a2 = fmaf(wv, watt[Hdim + k], a2);
    }
  } else {
    for (int k = tid; k < Hdim; k += 256) {
      float bv = bz[k];
      a1 = fmaf(bv, watt[k], a1);
      a2 = fmaf(bv, watt[Hdim + k], a2);
    }
  }
  float r1 = blockReduceSum(a1, sm);
  float r2 = blockReduceSum(a2, sm);
  if (tid == 0) {
    if (h < Hdim) {
      g_u1[h] = r1;
      g_u2[h] = r2;
    } else {
      g_c[0] = r1;
      g_c[1] = r2;
    }
  }
}

// Fused: t2[r] = bert_row[r] @ u2 + bz.w2  AND  out[r] = bert_row[r] (bulk copy).
// grid 512, block 256 (one warp per row).
__global__ void k_t2(const float* __restrict__ bert, float* __restrict__ out) {
  int r = blockIdx.x * 8 + (threadIdx.x >> 5);
  int lane = threadIdx.x & 31;
  const float4* br = (const float4*)(bert + (size_t)r * Hdim);
  float4* orow = (float4*)(out + (size_t)r * Hdim);
  const float4* u24 = (const float4*)g_u2;
  float a = 0.f;
#pragma unroll
  for (int k = lane; k < H4; k += 32) {
    float4 bv = br[k];
    orow[k] = bv;
    float4 uv = u24[k];
    a = fmaf(bv.x, uv.x, a);
    a = fmaf(bv.y, uv.y, a);
    a = fmaf(bv.z, uv.z, a);
    a = fmaf(bv.w, uv.w, a);
  }
  a = warpReduceSum(a);
  if (lane == 0) g_t2[r] = a + g_c[1];
}

// Per needed row: logits + softmax + agg_d + v (attn-weighted bert) + bert_next.
// grid (16, 8), block 256.
__global__ void k_main(const float* __restrict__ bert, const float* __restrict__ dta,
                       const int* __restrict__ deprel, const int* __restrict__ asp_s,
                       const int* __restrict__ asp_e, const float* __restrict__ w_att,
                       const float* __restrict__ b_att) {
  int b = blockIdx.x, il = blockIdx.y;
  int slot = b * 8 + il;
  int tid = threadIdx.x;
  __shared__ float sm_s[Sdim];
  __shared__ float sm_p[Sdim];
  __shared__ float sm_red[8];
  int start = asp_s[b], endi = asp_e[b];
  int i = start + il;
  bool active = (i <= endi) && (i < Sdim);
  const int* deprow = deprel + (size_t)(b * Sdim + (active ? i : 0)) * Sdim;
  int hasn = 0;
  if (active) hasn = (deprow[tid] > 0);
  int any = __syncthreads_or(hasn);
  if (!active || !any) {
    for (int h = tid; h < Hdim; h += 256) {
      g_X1[slot * Hdim + h] = 0.f;
      g_X1[(NSLOT + slot) * Hdim + h] = 0.f;
    }
    if (tid < Ddim) g_X2[slot * (Hdim + Ddim) + Hdim + tid] = 0.f;
    if (tid == 0) {
      g_valid[slot] = 0;
      g_rowi[slot] = 0;
    }
    return;
  }

  int inext = (i + 1) & (Sdim - 1);
  const float* bi = bert + (size_t)(b * Sdim + inext) * Hdim;

  // s1 = (zs @ w1)[b,i] = bert[b,i+1] @ u1 + bz.w1
  float a = 0.f;
  for (int h = tid; h < Hdim; h += 256) a = fmaf(bi[h], g_u1[h], a);
  float s1 = blockReduceSum(a, sm_red);
  float base = s1 + g_c[0] + b_att[0];

  // logits: thread j computes dta[b,i,j,:] . w3 with 16 independent LDG.128
  const float* drow = dta + (size_t)(b * Sdim + i) * Sdim * Ddim;
  {
    int j = tid;
    const float4* dj = (const float4*)(drow + (size_t)j * Ddim);
    const float4* w34 = (const float4*)(w_att + 2 * Hdim);
    float acc = 0.f;
#pragma unroll
    for (int k = 0; k < 16; ++k) {
      float4 d = dj[k];
      float4 w = w34[k];
      acc = fmaf(d.x, w.x, acc);
      acc = fmaf(d.y, w.y, acc);
      acc = fmaf(d.z, w.z, acc);
      acc = fmaf(d.w, w.w, acc);
    }
    float s = base + g_t2[b * Sdim + ((j + 1) & (Sdim - 1))] + acc;
    s = (s >= 0.f) ? s : 0.01f * s;
    if (deprow[j] <= 0) s = -1e9f;
    sm_s[j] = s;
  }
  __syncthreads();

  // softmax over j
  float sv = sm_s[tid];
  float m = blockReduceMax(sv, sm_red);
  float e = expf(sv - m);
  float sum = blockReduceSum(e, sm_red);
  sm_p[tid] = e / sum;
  __syncthreads();

  // agg_d[d] = sum_j p[j] * dta[b,i,j,d]  (dta row is L2-hot from pass 1)
  {
    int d = tid & 63, part = tid >> 6;
    float ad = 0.f;
    const float* dp = drow + (size_t)(part * 64) * Ddim + d;
    for (int j = 0; j < 64; ++j) ad = fmaf(sm_p[part * 64 + j], dp[(size_t)j * Ddim], ad);
    sm_s[tid] = ad;
    __syncthreads();
    if (part == 0) {
      float t = sm_s[d] + sm_s[64 + d] + sm_s[128 + d] + sm_s[192 + d];
      g_X2[slot * (Hdim + Ddim) + Hdim + d] = t;
    }
  }

  // v[h] = sum_j p[j] * bert[b, (j+1)%S, h]  — float4, threads 0..191
  if (tid < H4) {
    const float4* bb4 = (const float4*)(bert + (size_t)b * Sdim * Hdim);
    float4 acc4 = make_float4(0.f, 0.f, 0.f, 0.f);
#pragma unroll 8
    for (int j = 0; j < Sdim; ++j) {
      float p = sm_p[j];
      float4 bv = bb4[(size_t)((j + 1) & (Sdim - 1)) * H4 + tid];
      acc4.x = fmaf(p, bv.x, acc4.x);
      acc4.y = fmaf(p, bv.y, acc4.y);
      acc4.z = fmaf(p, bv.z, acc4.z);
      acc4.w = fmaf(p, bv.w, acc4.w);
    }
    ((float4*)g_X1)[slot * H4 + tid] = acc4;
    ((float4*)g_X1)[(NSLOT + slot) * H4 + tid] = ((const float4*)bi)[tid];
  }
  if (tid == 0) {
    g_valid[slot] = 1;
    g_rowi[slot] = i;
  }
}

// One k-component into 4 accumulator rows: splat X rows, 2 FFMA2 (4 cols) each.
#define FMAK4(C, WV, A0, A1, A2, A3)  \
  do {                                \
    unsigned long long s;             \
    s = splat2(x0.C);                 \
    ffma2(A0##l, s, (WV).x);          \
    ffma2(A0##h, s, (WV).y);          \
    s = splat2(x1.C);                 \
    ffma2(A1##l, s, (WV).x);          \
    ffma2(A1##h, s, (WV).y);          \
    s = splat2(x2.C);                 \
    ffma2(A2##l, s, (WV).x);          \
    ffma2(A2##h, s, (WV).y);          \
    s = splat2(x3.C);                 \
    ffma2(A3##l, s, (WV).x);          \
    ffma2(A3##h, s, (WV).y);          \
  } while (0)

// cp.async smem-staged partial GEMM, packed f32x2, 4 cols x 8 rows per thread.
// Block 256 = 16 ct x 16 rt -> tile 64 cols x 128 rows. K-tile 32, double-buffered.
// grid = (Hdim/64, rows/128, ksplit); z writes partials to P[(z*NROWS + r)*Hdim + h].
template <int KS, int LDX, int NIT, int NROWS>
__global__ void __launch_bounds__(256) k_sgemm(const float* __restrict__ X,
                                               const float* __restrict__ W,
                                               float* __restrict__ P) {
  static_assert(KS == NIT * 32, "");
  __shared__ __align__(16) float sW[2][32 * 64];   // 16 KB
  __shared__ __align__(16) float sX[2][128 * 32];  // 32 KB

  int tid = threadIdx.x;
  int ct = tid & 15, rt = tid >> 4;
  int hb = blockIdx.x * 64;
  int rb = blockIdx.y * 128;
  int z = blockIdx.z;

  const float* Wg = W + (size_t)z * KS * Hdim + hb;
  const float* Xg = X + (size_t)rb * LDX + (size_t)z * KS;

  // stage loader: W tile 32x64 (512 float4, 2/thread), X tile 128x32 (1024 float4, 4/thread)
  int wi = tid >> 4, wj = (tid & 15) * 4;  // W row, first col
  int xi = tid >> 3, xj = (tid & 7) * 4;   // X row, col
  unsigned int sw0 = saddr_of(&sW[0][0]);
  unsigned int sx0 = saddr_of(&sX[0][0]);

#define LOAD_STAGE(stage, buf)                                                  \
  do {                                                                          \
    int k0 = (stage) * 32;                                                      \
    unsigned int swb = sw0 + (buf) * (32 * 64 * 4);                             \
    unsigned int sxb = sx0 + (buf) * (128 * 32 * 4);                            \
    cpasync16(swb + (wi * 64 + wj) * 4, Wg + (size_t)(k0 + wi) * Hdim + wj);    \
    cpasync16(swb + ((wi + 16) * 64 + wj) * 4,                                  \
              Wg + (size_t)(k0 + wi + 16) * Hdim + wj);                         \
    cpasync16(sxb + (xi * 32 + xj) * 4, Xg + (size_t)xi * LDX + k0 + xj);       \
    cpasync16(sxb + ((xi + 32) * 32 + xj) * 4,                                  \
              Xg + (size_t)(xi + 32) * LDX + k0 + xj);                          \
    cpasync16(sxb + ((xi + 64) * 32 + xj) * 4,                                  \
              Xg + (size_t)(xi + 64) * LDX + k0 + xj);                          \
    cpasync16(sxb + ((xi + 96) * 32 + xj) * 4,                                  \
              Xg + (size_t)(xi + 96) * LDX + k0 + xj);                          \
    cpasync_commit();                                                           \
  } while (0)

  LOAD_STAGE(0, 0);
  if (NIT > 1) LOAD_STAGE(1, 1);

  unsigned long long a0l = 0, a0h = 0, a1l = 0, a1h = 0;
  unsigned long long a2l = 0, a2h = 0, a3l = 0, a3h = 0;
  unsigned long long a4l = 0, a4h = 0, a5l = 0, a5h = 0;
  unsigned long long a6l = 0, a6h = 0, a7l = 0, a7h = 0;
  int r0 = rt * 8;

#pragma unroll 1
  for (int it = 0; it < NIT; ++it) {
    if (it < NIT - 1)
      cpasync_wait1();
    else
      cpasync_wait0();
    __syncthreads();
    int buf = it & 1;
    const float* xbase = &sX[buf][0];
    const float* wb = &sW[buf][ct * 4];
#pragma unroll
    for (int k4 = 0; k4 < 8; ++k4) {
      ulonglong2 w0 = *(const ulonglong2*)(wb + (k4 * 4 + 0) * 64);
      ulonglong2 w1 = *(const ulonglong2*)(wb + (k4 * 4 + 1) * 64);
      ulonglong2 w2 = *(const ulonglong2*)(wb + (k4 * 4 + 2) * 64);
      ulonglong2 w3 = *(const ulonglong2*)(wb + (k4 * 4 + 3) * 64);
      {
        float4 x0 = *(const float4*)(xbase + (r0 + 0) * 32 + k4 * 4);
        float4 x1 = *(const float4*)(xbase + (r0 + 1) * 32 + k4 * 4);
        float4 x2 = *(const float4*)(xbase + (r0 + 2) * 32 + k4 * 4);
        float4 x3 = *(const float4*)(xbase + (r0 + 3) * 32 + k4 * 4);
        FMAK4(x, w0, a0, a1, a2, a3);
        FMAK4(y, w1, a0, a1, a2, a3);
        FMAK4(z, w2, a0, a1, a2, a3);
        FMAK4(w, w3, a0, a1, a2, a3);
      }
      {
        float4 x0 = *(const float4*)(xbase + (r0 + 4) * 32 + k4 * 4);
        float4 x1 = *(const float4*)(xbase + (r0 + 5) * 32 + k4 * 4);
        float4 x2 = *(const float4*)(xbase + (r0 + 6) * 32 + k4 * 4);
        float4 x3 = *(const float4*)(xbase + (r0 + 7) * 32 + k4 * 4);
        FMAK4(x, w0, a4, a5, a6, a7);
        FMAK4(y, w1, a4, a5, a6, a7);
        FMAK4(z, w2, a4, a5, a6, a7);
        FMAK4(w, w3, a4, a5, a6, a7);
      }
    }
    __syncthreads();
    if (it + 2 < NIT) LOAD_STAGE(it + 2, buf);
  }
#undef LOAD_STAGE

  int r = rb + r0;
  float* pr = P + ((size_t)(z * NROWS + r)) * Hdim + hb + ct * 4;
#define STORE_ROW(q, A)                                 \
  {                                                     \
    float2 fl = u2f(A##l), fh = u2f(A##h);              \
    *(float4*)(pr + (q)*Hdim) = make_float4(fl.x, fl.y, fh.x, fh.y); \
  }
  STORE_ROW(0, a0)
  STORE_ROW(1, a1)
  STORE_ROW(2, a2)
  STORE_ROW(3, a3)
  STORE_ROW(4, a4)
  STORE_ROW(5, a5)
  STORE_ROW(6, a6)
  STORE_ROW(7, a7)
#undef STORE_ROW
}

// Epilogue: combine NZ K-split partials and route per MODE. block 192.
// MODE 0: +bias -> agg_z (X2) / zrow (X3 cols 768..); MODE 1: -> nrep (X3);
// MODE 2: scatter valid rows to out[(i+1)].
template <int NZ, int NROWS, int MODE>
__global__ void k_epi(const float* __restrict__ bias, float* __restrict__ outp) {
  int r = blockIdx.x;
  if (MODE == 2 && !g_valid[r]) return;
  int h = threadIdx.x * 4;
  float4 v = make_float4(0.f, 0.f, 0.f, 0.f);
#pragma unroll
  for (int zz = 0; zz < NZ; ++zz) {
    const float4 p = *(const float4*)(g_P + (size_t)(zz * NROWS + r) * Hdim + h);
    v.x += p.x;
    v.y += p.y;
    v.z += p.z;
    v.w += p.w;
  }
  if (MODE == 0) {
    const float4 bb = *(const float4*)(bias + h);
    v.x += bb.x;
    v.y += bb.y;
    v.z += bb.z;
    v.w += bb.w;
    if (r < NSLOT)
      *(float4*)(g_X2 + (size_t)r * (Hdim + Ddim) + h) = v;  // agg_z
    else
      *(float4*)(g_X3 + (size_t)(r - NSLOT) * (2 * Hdim) + Hdim + h) = v;  // zrow
  } else if (MODE == 1) {
    *(float4*)(g_X3 + (size_t)r * (2 * Hdim) + h) = v;  // nrep
  } else {
    int bb = r >> 3;
    int o = (g_rowi[r] + 1) & (Sdim - 1);
    *(float4*)(outp + ((size_t)(bb * Sdim + o)) * Hdim + h) = v;
  }
}

extern "C" void kernel_launch(void* const* d_in, const int* in_sizes, int n_in,
                              void* d_out, int out_size) {
  const float* bert = (const float*)d_in[0];
  const float* dta = (const float*)d_in[1];
  const int* deprel = (const int*)d_in[2];
  const int* asp_s = (const int*)d_in[3];
  const int* asp_e = (const int*)d_in[4];
  const float* Wz = (const float*)d_in[5];
  const float* bz = (const float*)d_in[6];
  const float* watt = (const float*)d_in[7];
  const float* batt = (const float*)d_in[8];
  const float* Wf = (const float*)d_in[9];
  const float* Wh = (const float*)d_in[10];
  float* out = (float*)d_out;

  float* P;
  float* X1;
  float* X2;
  float* X3;
  cudaGetSymbolAddress((void**)&P, g_P);
  cudaGetSymbolAddress((void**)&X1, g_X1);
  cudaGetSymbolAddress((void**)&X2, g_X2);
  cudaGetSymbolAddress((void**)&X3, g_X3);

  k_pre<<<769, 256>>>(Wz, bz, watt);
  k_t2<<<(Bdim * Sdim) / 8, 256>>>(bert, out);  // also bulk-copies bert -> out
  k_main<<<dim3(Bdim, 8), 256>>>(bert, dta, deprel, asp_s, asp_e, watt, batt);

  // mode 0: [v; bert_next](256 x 768) @ Wz   K=768 split 12 -> 288 blocks
  k_sgemm<64, Hdim, 2, 256><<<dim3(12, 2, 12), 256>>>(X1, Wz, P);
  k_epi<12, 256, 0><<<256, 192>>>(bz, nullptr);
  // mode 1: X2(128 x 832) @ Wf   K=832 split 26 -> 312 blocks
  k_sgemm<32, Hdim + Ddim, 1, 128><<<dim3(12, 1, 26), 256>>>(X2, Wf, P);
  k_epi<26, 128, 1><<<128, 192>>>(nullptr, nullptr);
  // mode 2: X3(128 x 1536) @ Wh   K=1536 split 24 -> 288 blocks
  k_sgemm<64, 2 * Hdim, 2, 128><<<dim3(12, 1, 24), 256>>>(X3, Wh, P);
  k_epi<24, 128, 2><<<128, 192>>>(nullptr, out);
}

// round 9
// speedup vs baseline: 3.7603x; 1.0118x over previous
#include <cuda_runtime.h>
#include <cstdint>

#define Bdim 16
#define Sdim 256
#define Hdim 768
#define Ddim 64
#define NSLOT 128  // 16 batches * 8 slots (max aspect span is 6 rows)
#define H4 (Hdim / 4)

// Scratch (device globals; no allocation allowed)
__device__ __align__(16) float g_u1[Hdim];              // Wz @ w1
__device__ __align__(16) float g_u2[Hdim];              // Wz @ w2
__device__ float g_c[2];                                // bz.w1, bz.w2
__device__ __align__(16) float g_t2[Bdim * Sdim];       // (z @ w2)[b,j]
__device__ __align__(16) float g_X1[2 * NSLOT * Hdim];  // rows 0..127: v; 128..255: bert_next
__device__ __align__(16) float g_X2[NSLOT * (Hdim + Ddim)];  // [agg_z | agg_d]
__device__ __align__(16) float g_X3[NSLOT * (2 * Hdim)];     // [nrep | zrow]
__device__ __align__(16) float g_P[3328 * Hdim];             // K-split partial sums
__device__ int g_valid[NSLOT];
__device__ int g_rowi[NSLOT];

// Host-side stream/event resources, created once at load time (no device memory).
static cudaStream_t g_s2;
static cudaEvent_t g_evFork, g_evCopy;
namespace {
struct HostInit {
  HostInit() {
    cudaStreamCreateWithFlags(&g_s2, cudaStreamNonBlocking);
    cudaEventCreateWithFlags(&g_evFork, cudaEventDisableTiming);
    cudaEventCreateWithFlags(&g_evCopy, cudaEventDisableTiming);
  }
};
HostInit g_hostInit;
}  // namespace

__device__ __forceinline__ float warpReduceSum(float v) {
#pragma unroll
  for (int o = 16; o > 0; o >>= 1) v += __shfl_down_sync(0xffffffffu, v, o);
  return v;
}

__device__ __forceinline__ float blockReduceSum(float v, float* sm) {
  v = warpReduceSum(v);
  int w = threadIdx.x >> 5;
  if ((threadIdx.x & 31) == 0) sm[w] = v;
  __syncthreads();
  if (threadIdx.x < 8) {
    float x = sm[threadIdx.x];
#pragma unroll
    for (int o = 4; o > 0; o >>= 1) x += __shfl_down_sync(0xffu, x, o);
    if (threadIdx.x == 0) sm[0] = x;
  }
  __syncthreads();
  float r = sm[0];
  __syncthreads();
  return r;
}

__device__ __forceinline__ float blockReduceMax(float v, float* sm) {
#pragma unroll
  for (int o = 16; o > 0; o >>= 1) v = fmaxf(v, __shfl_down_sync(0xffffffffu, v, o));
  int w = threadIdx.x >> 5;
  if ((threadIdx.x & 31) == 0) sm[w] = v;
  __syncthreads();
  if (threadIdx.x < 8) {
    float x = sm[threadIdx.x];
#pragma unroll
    for (int o = 4; o > 0; o >>= 1) x = fmaxf(x, __shfl_down_sync(0xffu, x, o));
    if (threadIdx.x == 0) sm[0] = x;
  }
  __syncthreads();
  float r = sm[0];
  __syncthreads();
  return r;
}

// ---- packed f32x2 helpers (FFMA2 only reachable via PTX on sm_103a) ----
__device__ __forceinline__ unsigned long long splat2(float x) {
  unsigned long long r;
  asm("mov.b64 %0, {%1, %2};" : "=l"(r) : "f"(x), "f"(x));
  return r;
}
__device__ __forceinline__ void ffma2(unsigned long long& a, unsigned long long x,
                                      unsigned long long w) {
  asm("fma.rn.f32x2 %0, %1, %2, %0;" : "+l"(a) : "l"(x), "l"(w));
}
__device__ __forceinline__ float2 u2f(unsigned long long v) {
  float2 f;
  asm("mov.b64 {%0, %1}, %2;" : "=f"(f.x), "=f"(f.y) : "l"(v));
  return f;
}

// ---- cp.async helpers ----
__device__ __forceinline__ unsigned int saddr_of(const void* p) {
  return (unsigned int)__cvta_generic_to_shared(p);
}
__device__ __forceinline__ void cpasync16(unsigned int saddr, const void* g) {
  asm volatile("cp.async.ca.shared.global [%0], [%1], 16;" ::"r"(saddr), "l"(g));
}
__device__ __forceinline__ void cpasync_commit() {
  asm volatile("cp.async.commit_group;" ::: "memory");
}
__device__ __forceinline__ void cpasync_wait1() {
  asm volatile("cp.async.wait_group 1;" ::: "memory");
}
__device__ __forceinline__ void cpasync_wait0() {
  asm volatile("cp.async.wait_group 0;" ::: "memory");
}

// Pure streaming copy bert -> out (independent of all other work).
__global__ void k_copy(const float4* __restrict__ src, float4* __restrict__ dst) {
  int i = blockIdx.x * 256 + threadIdx.x;
  dst[i] = src[i];
}

// u1 = Wz @ w1, u2 = Wz @ w2, c = (bz.w1, bz.w2). grid 769, block 256.
__global__ void k_pre(const float* __restrict__ Wz, const float* __restrict__ bz,
                      const float* __restrict__ watt) {
  __shared__ float sm[8];
  int h = blockIdx.x, tid = threadIdx.x;
  float a1 = 0.f, a2 = 0.f;
  if (h < Hdim) {
    const float* wr = Wz + (size_t)h * Hdim;
    for (int k = tid; k < Hdim; k += 256) {
      float wv = wr[k];
      a1 = fmaf(wv, watt[k], a1);
      a2 = fmaf(wv, watt[Hdim + k], a2);
    }
  } else {
    for (int k = tid; k < Hdim; k += 256) {
      float bv = bz[k];
      a1 = fmaf(bv, watt[k], a1);
      a2 = fmaf(bv, watt[Hdim + k], a2);
    }
  }
  float r1 = blockReduceSum(a1, sm);
  float r2 = blockReduceSum(a2, sm);
  if (tid == 0) {
    if (h < Hdim) {
      g_u1[h] = r1;
      g_u2[h] = r2;
    } else {
      g_c[0] = r1;
      g_c[1] = r2;
    }
  }
}

// t2[r] = bert_row[r] @ u2 + bz.w2. grid 512, block 256 (one warp per row).
__global__ void k_t2d(const float* __restrict__ bert) {
  int r = blockIdx.x * 8 + (threadIdx.x >> 5);
  int lane = threadIdx.x & 31;
  const float4* br = (const float4*)(bert + (size_t)r * Hdim);
  const float4* u24 = (const float4*)g_u2;
  float a = 0.f;
#pragma unroll
  for (int k = lane; k < H4; k += 32) {
    float4 bv = br[k];
    float4 uv = u24[k];
    a = fmaf(bv.x, uv.x, a);
    a = fmaf(bv.y, uv.y, a);
    a = fmaf(bv.z, uv.z, a);
    a = fmaf(bv.w, uv.w, a);
  }
  a = warpReduceSum(a);
  if (lane == 0) g_t2[r] = a + g_c[1];
}

// Per needed row: logits + softmax + agg_d + v (attn-weighted bert) + bert_next.
// grid (16, 8), block 256.
__global__ void k_main(const float* __restrict__ bert, const float* __restrict__ dta,
                       const int* __restrict__ deprel, const int* __restrict__ asp_s,
                       const int* __restrict__ asp_e, const float* __restrict__ w_att,
                       const float* __restrict__ b_att) {
  int b = blockIdx.x, il = blockIdx.y;
  int slot = b * 8 + il;
  int tid = threadIdx.x;
  __shared__ float sm_s[Sdim];
  __shared__ float sm_p[Sdim];
  __shared__ float sm_red[8];
  int start = asp_s[b], endi = asp_e[b];
  int i = start + il;
  bool active = (i <= endi) && (i < Sdim);
  const int* deprow = deprel + (size_t)(b * Sdim + (active ? i : 0)) * Sdim;
  int hasn = 0;
  if (active) hasn = (deprow[tid] > 0);
  int any = __syncthreads_or(hasn);
  if (!active || !any) {
    for (int h = tid; h < Hdim; h += 256) {
      g_X1[slot * Hdim + h] = 0.f;
      g_X1[(NSLOT + slot) * Hdim + h] = 0.f;
    }
    if (tid < Ddim) g_X2[slot * (Hdim + Ddim) + Hdim + tid] = 0.f;
    if (tid == 0) {
      g_valid[slot] = 0;
      g_rowi[slot] = 0;
    }
    return;
  }

  int inext = (i + 1) & (Sdim - 1);
  const float* bi = bert + (size_t)(b * Sdim + inext) * Hdim;

  // s1 = (zs @ w1)[b,i] = bert[b,i+1] @ u1 + bz.w1
  float a = 0.f;
  for (int h = tid; h < Hdim; h += 256) a = fmaf(bi[h], g_u1[h], a);
  float s1 = blockReduceSum(a, sm_red);
  float base = s1 + g_c[0] + b_att[0];

  // logits: thread j computes dta[b,i,j,:] . w3 with 16 independent LDG.128
  const float* drow = dta + (size_t)(b * Sdim + i) * Sdim * Ddim;
  {
    int j = tid;
    const float4* dj = (const float4*)(drow + (size_t)j * Ddim);
    const float4* w34 = (const float4*)(w_att + 2 * Hdim);
    float acc = 0.f;
#pragma unroll
    for (int k = 0; k < 16; ++k) {
      float4 d = dj[k];
      float4 w = w34[k];
      acc = fmaf(d.x, w.x, acc);
      acc = fmaf(d.y, w.y, acc);
      acc = fmaf(d.z, w.z, acc);
      acc = fmaf(d.w, w.w, acc);
    }
    float s = base + g_t2[b * Sdim + ((j + 1) & (Sdim - 1))] + acc;
    s = (s >= 0.f) ? s : 0.01f * s;
    if (deprow[j] <= 0) s = -1e9f;
    sm_s[j] = s;
  }
  __syncthreads();

  // softmax over j
  float sv = sm_s[tid];
  float m = blockReduceMax(sv, sm_red);
  float e = expf(sv - m);
  float sum = blockReduceSum(e, sm_red);
  sm_p[tid] = e / sum;
  __syncthreads();

  // agg_d[d] = sum_j p[j] * dta[b,i,j,d]  (dta row is L2-hot from pass 1)
  {
    int d = tid & 63, part = tid >> 6;
    float ad = 0.f;
    const float* dp = drow + (size_t)(part * 64) * Ddim + d;
#pragma unroll 8
    for (int j = 0; j < 64; ++j) ad = fmaf(sm_p[part * 64 + j], dp[(size_t)j * Ddim], ad);
    sm_s[tid] = ad;
    __syncthreads();
    if (part == 0) {
      float t = sm_s[d] + sm_s[64 + d] + sm_s[128 + d] + sm_s[192 + d];
      g_X2[slot * (Hdim + Ddim) + Hdim + d] = t;
    }
  }

  // v[h] = sum_j p[j] * bert[b, (j+1)%S, h]  — float4, threads 0..191
  if (tid < H4) {
    const float4* bb4 = (const float4*)(bert + (size_t)b * Sdim * Hdim);
    float4 acc4 = make_float4(0.f, 0.f, 0.f, 0.f);
#pragma unroll 16
    for (int j = 0; j < Sdim; ++j) {
      float p = sm_p[j];
      float4 bv = bb4[(size_t)((j + 1) & (Sdim - 1)) * H4 + tid];
      acc4.x = fmaf(p, bv.x, acc4.x);
      acc4.y = fmaf(p, bv.y, acc4.y);
      acc4.z = fmaf(p, bv.z, acc4.z);
      acc4.w = fmaf(p, bv.w, acc4.w);
    }
    ((float4*)g_X1)[slot * H4 + tid] = acc4;
    ((float4*)g_X1)[(NSLOT + slot) * H4 + tid] = ((const float4*)bi)[tid];
  }
  if (tid == 0) {
    g_valid[slot] = 1;
    g_rowi[slot] = i;
  }
}

// One k-component into 4 accumulator rows: splat X rows, 2 FFMA2 (4 cols) each.
#define FMAK4(C, WV, A0, A1, A2, A3)  \
  do {                                \
    unsigned long long s;             \
    s = splat2(x0.C);                 \
    ffma2(A0##l, s, (WV).x);          \
    ffma2(A0##h, s, (WV).y);          \
    s = splat2(x1.C);                 \
    ffma2(A1##l, s, (WV).x);          \
    ffma2(A1##h, s, (WV).y);          \
    s = splat2(x2.C);                 \
    ffma2(A2##l, s, (WV).x);          \
    ffma2(A2##h, s, (WV).y);          \
    s = splat2(x3.C);                 \
    ffma2(A3##l, s, (WV).x);          \
    ffma2(A3##h, s, (WV).y);          \
  } while (0)

// cp.async smem-staged partial GEMM, packed f32x2, 4 cols x 8 rows per thread.
// Block 256 = 16 ct x 16 rt -> tile 64 cols x 128 rows. K-tile 32, double-buffered.
// grid = (Hdim/64, rows/128, ksplit); z writes partials to P[(z*NROWS + r)*Hdim + h].
template <int KS, int LDX, int NIT, int NROWS>
__global__ void __launch_bounds__(256) k_sgemm(const float* __restrict__ X,
                                               const float* __restrict__ W,
                                               float* __restrict__ P) {
  static_assert(KS == NIT * 32, "");
  __shared__ __align__(16) float sW[2][32 * 64];   // 16 KB
  __shared__ __align__(16) float sX[2][128 * 32];  // 32 KB

  int tid = threadIdx.x;
  int ct = tid & 15, rt = tid >> 4;
  int hb = blockIdx.x * 64;
  int rb = blockIdx.y * 128;
  int z = blockIdx.z;

  const float* Wg = W + (size_t)z * KS * Hdim + hb;
  const float* Xg = X + (size_t)rb * LDX + (size_t)z * KS;

  // stage loader: W tile 32x64 (512 float4, 2/thread), X tile 128x32 (1024 float4, 4/thread)
  int wi = tid >> 4, wj = (tid & 15) * 4;  // W row, first col
  int xi = tid >> 3, xj = (tid & 7) * 4;   // X row, col
  unsigned int sw0 = saddr_of(&sW[0][0]);
  unsigned int sx0 = saddr_of(&sX[0][0]);

#define LOAD_STAGE(stage, buf)                                                  \
  do {                                                                          \
    int k0 = (stage) * 32;                                                      \
    unsigned int swb = sw0 + (buf) * (32 * 64 * 4);                             \
    unsigned int sxb = sx0 + (buf) * (128 * 32 * 4);                            \
    cpasync16(swb + (wi * 64 + wj) * 4, Wg + (size_t)(k0 + wi) * Hdim + wj);    \
    cpasync16(swb + ((wi + 16) * 64 + wj) * 4,                                  \
              Wg + (size_t)(k0 + wi + 16) * Hdim + wj);                         \
    cpasync16(sxb + (xi * 32 + xj) * 4, Xg + (size_t)xi * LDX + k0 + xj);       \
    cpasync16(sxb + ((xi + 32) * 32 + xj) * 4,                                  \
              Xg + (size_t)(xi + 32) * LDX + k0 + xj);                          \
    cpasync16(sxb + ((xi + 64) * 32 + xj) * 4,                                  \
              Xg + (size_t)(xi + 64) * LDX + k0 + xj);                          \
    cpasync16(sxb + ((xi + 96) * 32 + xj) * 4,                                  \
              Xg + (size_t)(xi + 96) * LDX + k0 + xj);                          \
    cpasync_commit();                                                           \
  } while (0)

  LOAD_STAGE(0, 0);
  if (NIT > 1) LOAD_STAGE(1, 1);

  unsigned long long a0l = 0, a0h = 0, a1l = 0, a1h = 0;
  unsigned long long a2l = 0, a2h = 0, a3l = 0, a3h = 0;
  unsigned long long a4l = 0, a4h = 0, a5l = 0, a5h = 0;
  unsigned long long a6l = 0, a6h = 0, a7l = 0, a7h = 0;
  int r0 = rt * 8;

#pragma unroll 1
  for (int it = 0; it < NIT; ++it) {
    if (it < NIT - 1)
      cpasync_wait1();
    else
      cpasync_wait0();
    __syncthreads();
    int buf = it & 1;
    const float* xbase = &sX[buf][0];
    const float* wb = &sW[buf][ct * 4];
#pragma unroll
    for (int k4 = 0; k4 < 8; ++k4) {
      ulonglong2 w0 = *(const ulonglong2*)(wb + (k4 * 4 + 0) * 64);
      ulonglong2 w1 = *(const ulonglong2*)(wb + (k4 * 4 + 1) * 64);
      ulonglong2 w2 = *(const ulonglong2*)(wb + (k4 * 4 + 2) * 64);
      ulonglong2 w3 = *(const ulonglong2*)(wb + (k4 * 4 + 3) * 64);
      {
        float4 x0 = *(const float4*)(xbase + (r0 + 0) * 32 + k4 * 4);
        float4 x1 = *(const float4*)(xbase + (r0 + 1) * 32 + k4 * 4);
        float4 x2 = *(const float4*)(xbase + (r0 + 2) * 32 + k4 * 4);
        float4 x3 = *(const float4*)(xbase + (r0 + 3) * 32 + k4 * 4);
        FMAK4(x, w0, a0, a1, a2, a3);
        FMAK4(y, w1, a0, a1, a2, a3);
        FMAK4(z, w2, a0, a1, a2, a3);
        FMAK4(w, w3, a0, a1, a2, a3);
      }
      {
        float4 x0 = *(const float4*)(xbase + (r0 + 4) * 32 + k4 * 4);
        float4 x1 = *(const float4*)(xbase + (r0 + 5) * 32 + k4 * 4);
        float4 x2 = *(const float4*)(xbase + (r0 + 6) * 32 + k4 * 4);
        float4 x3 = *(const float4*)(xbase + (r0 + 7) * 32 + k4 * 4);
        FMAK4(x, w0, a4, a5, a6, a7);
        FMAK4(y, w1, a4, a5, a6, a7);
        FMAK4(z, w2, a4, a5, a6, a7);
        FMAK4(w, w3, a4, a5, a6, a7);
      }
    }
    __syncthreads();
    if (it + 2 < NIT) LOAD_STAGE(it + 2, buf);
  }
#undef LOAD_STAGE

  int r = rb + r0;
  float* pr = P + ((size_t)(z * NROWS + r)) * Hdim + hb + ct * 4;
#define STORE_ROW(q, A)                                 \
  {                                                     \
    float2 fl = u2f(A##l), fh = u2f(A##h);              \
    *(float4*)(pr + (q)*Hdim) = make_float4(fl.x, fl.y, fh.x, fh.y); \
  }
  STORE_ROW(0, a0)
  STORE_ROW(1, a1)
  STORE_ROW(2, a2)
  STORE_ROW(3, a3)
  STORE_ROW(4, a4)
  STORE_ROW(5, a5)
  STORE_ROW(6, a6)
  STORE_ROW(7, a7)
#undef STORE_ROW
}

// Epilogue: combine NZ K-split partials and route per MODE. block 192.
// MODE 0: +bias -> agg_z (X2) / zrow (X3 cols 768..); MODE 1: -> nrep (X3);
// MODE 2: scatter valid rows to out[(i+1)].
template <int NZ, int NROWS, int MODE>
__global__ void k_epi(const float* __restrict__ bias, float* __restrict__ outp) {
  int r = blockIdx.x;
  if (MODE == 2 && !g_valid[r]) return;
  int h = threadIdx.x * 4;
  float4 v = make_float4(0.f, 0.f, 0.f, 0.f);
#pragma unroll
  for (int zz = 0; zz < NZ; ++zz) {
    const float4 p = *(const float4*)(g_P + (size_t)(zz * NROWS + r) * Hdim + h);
    v.x += p.x;
    v.y += p.y;
    v.z += p.z;
    v.w += p.w;
  }
  if (MODE == 0) {
    const float4 bb = *(const float4*)(bias + h);
    v.x += bb.x;
    v.y += bb.y;
    v.z += bb.z;
    v.w += bb.w;
    if (r < NSLOT)
      *(float4*)(g_X2 + (size_t)r * (Hdim + Ddim) + h) = v;  // agg_z
    else
      *(float4*)(g_X3 + (size_t)(r - NSLOT) * (2 * Hdim) + Hdim + h) = v;  // zrow
  } else if (MODE == 1) {
    *(float4*)(g_X3 + (size_t)r * (2 * Hdim) + h) = v;  // nrep
  } else {
    int bb = r >> 3;
    int o = (g_rowi[r] + 1) & (Sdim - 1);
    *(float4*)(outp + ((size_t)(bb * Sdim + o)) * Hdim + h) = v;
  }
}

extern "C" void kernel_launch(void* const* d_in, const int* in_sizes, int n_in,
                              void* d_out, int out_size) {
  const float* bert = (const float*)d_in[0];
  const float* dta = (const float*)d_in[1];
  const int* deprel = (const int*)d_in[2];
  const int* asp_s = (const int*)d_in[3];
  const int* asp_e = (const int*)d_in[4];
  const float* Wz = (const float*)d_in[5];
  const float* bz = (const float*)d_in[6];
  const float* watt = (const float*)d_in[7];
  const float* batt = (const float*)d_in[8];
  const float* Wf = (const float*)d_in[9];
  const float* Wh = (const float*)d_in[10];
  float* out = (float*)d_out;

  float* P;
  float* X1;
  float* X2;
  float* X3;
  cudaGetSymbolAddress((void**)&P, g_P);
  cudaGetSymbolAddress((void**)&X1, g_X1);
  cudaGetSymbolAddress((void**)&X2, g_X2);
  cudaGetSymbolAddress((void**)&X3, g_X3);

  // Fork: independent bulk copy bert -> out on side stream (joined before epi2).
  cudaEventRecord(g_evFork, 0);
  cudaStreamWaitEvent(g_s2, g_evFork, 0);
  k_copy<<<(Bdim * Sdim * Hdim / 4) / 256, 256, 0, g_s2>>>((const float4*)bert,
                                                           (float4*)out);
  cudaEventRecord(g_evCopy, g_s2);

  k_pre<<<769, 256>>>(Wz, bz, watt);
  k_t2d<<<(Bdim * Sdim) / 8, 256>>>(bert);
  k_main<<<dim3(Bdim, 8), 256>>>(bert, dta, deprel, asp_s, asp_e, watt, batt);

  // mode 0: [v; bert_next](256 x 768) @ Wz   K=768 split 12 -> 288 blocks
  k_sgemm<64, Hdim, 2, 256><<<dim3(12, 2, 12), 256>>>(X1, Wz, P);
  k_epi<12, 256, 0><<<256, 192>>>(bz, nullptr);
  // mode 1: X2(128 x 832) @ Wf   K=832 split 13 -> 156 blocks
  k_sgemm<64, Hdim + Ddim, 2, 128><<<dim3(12, 1, 13), 256>>>(X2, Wf, P);
  k_epi<13, 128, 1><<<128, 192>>>(nullptr, nullptr);
  // mode 2: X3(128 x 1536) @ Wh   K=1536 split 24 -> 288 blocks
  k_sgemm<64, 2 * Hdim, 2, 128><<<dim3(12, 1, 24), 256>>>(X3, Wh, P);
  // Join: out rows must be pre-filled by k_copy before epi2 overwrites them.
  cudaStreamWaitEvent(0, g_evCopy, 0);
  k_epi<24, 128, 2><<<128, 192>>>(nullptr, out);
}

// round 10
// speedup vs baseline: 4.0687x; 1.0820x over previous
#include <cuda_runtime.h>
#include <cstdint>

#define Bdim 16
#define Sdim 256
#define Hdim 768
#define Ddim 64
#define NSLOT 128  // 16 batches * 8 slots (max aspect span is 6 rows)
#define H4 (Hdim / 4)

// Scratch (device globals; no allocation allowed)
__device__ __align__(16) float g_u1[Hdim];              // Wz @ w1
__device__ __align__(16) float g_u2[Hdim];              // Wz @ w2
__device__ float g_c[2];                                // bz.w1, bz.w2
__device__ __align__(16) float g_t2[Bdim * Sdim];       // (z @ w2)[b,j]
__device__ __align__(16) float g_X1[2 * NSLOT * Hdim];  // rows 0..127: v; 128..255: bert_next
__device__ __align__(16) float g_X2[NSLOT * (Hdim + Ddim)];  // [agg_z | agg_d]
__device__ __align__(16) float g_X3[NSLOT * (2 * Hdim)];     // [nrep | zrow]
__device__ __align__(16) float g_P[3328 * Hdim];             // K-split partial sums
__device__ int g_valid[NSLOT];
__device__ int g_rowi[NSLOT];

// Host-side stream/event resources, created once at load time (no device memory).
static cudaStream_t g_s2;
static cudaEvent_t g_evFork, g_evCopy;
namespace {
struct HostInit {
  HostInit() {
    cudaStreamCreateWithFlags(&g_s2, cudaStreamNonBlocking);
    cudaEventCreateWithFlags(&g_evFork, cudaEventDisableTiming);
    cudaEventCreateWithFlags(&g_evCopy, cudaEventDisableTiming);
  }
};
HostInit g_hostInit;
}  // namespace

__device__ __forceinline__ float warpReduceSum(float v) {
#pragma unroll
  for (int o = 16; o > 0; o >>= 1) v += __shfl_down_sync(0xffffffffu, v, o);
  return v;
}
__device__ __forceinline__ float warpReduceMax(float v) {
#pragma unroll
  for (int o = 16; o > 0; o >>= 1) v = fmaxf(v, __shfl_down_sync(0xffffffffu, v, o));
  return v;
}

// 256-thread (8-warp) block reductions
__device__ __forceinline__ float blockReduceSum(float v, float* sm) {
  v = warpReduceSum(v);
  int w = threadIdx.x >> 5;
  if ((threadIdx.x & 31) == 0) sm[w] = v;
  __syncthreads();
  if (threadIdx.x < 8) {
    float x = sm[threadIdx.x];
#pragma unroll
    for (int o = 4; o > 0; o >>= 1) x += __shfl_down_sync(0xffu, x, o);
    if (threadIdx.x == 0) sm[0] = x;
  }
  __syncthreads();
  float r = sm[0];
  __syncthreads();
  return r;
}

// 1024-thread (32-warp) block reductions
__device__ __forceinline__ float blockReduceSum32(float v, float* sm) {
  v = warpReduceSum(v);
  int w = threadIdx.x >> 5;
  if ((threadIdx.x & 31) == 0) sm[w] = v;
  __syncthreads();
  if (threadIdx.x < 32) {
    float x = warpReduceSum(sm[threadIdx.x]);
    if (threadIdx.x == 0) sm[0] = x;
  }
  __syncthreads();
  float r = sm[0];
  __syncthreads();
  return r;
}
__device__ __forceinline__ float blockReduceMax32(float v, float* sm) {
  v = warpReduceMax(v);
  int w = threadIdx.x >> 5;
  if ((threadIdx.x & 31) == 0) sm[w] = v;
  __syncthreads();
  if (threadIdx.x < 32) {
    float x = warpReduceMax(sm[threadIdx.x]);
    if (threadIdx.x == 0) sm[0] = x;
  }
  __syncthreads();
  float r = sm[0];
  __syncthreads();
  return r;
}

// ---- packed f32x2 helpers (FFMA2 only reachable via PTX on sm_103a) ----
__device__ __forceinline__ unsigned long long splat2(float x) {
  unsigned long long r;
  asm("mov.b64 %0, {%1, %2};" : "=l"(r) : "f"(x), "f"(x));
  return r;
}
__device__ __forceinline__ void ffma2(unsigned long long& a, unsigned long long x,
                                      unsigned long long w) {
  asm("fma.rn.f32x2 %0, %1, %2, %0;" : "+l"(a) : "l"(x), "l"(w));
}
__device__ __forceinline__ float2 u2f(unsigned long long v) {
  float2 f;
  asm("mov.b64 {%0, %1}, %2;" : "=f"(f.x), "=f"(f.y) : "l"(v));
  return f;
}

// ---- cp.async helpers ----
__device__ __forceinline__ unsigned int saddr_of(const void* p) {
  return (unsigned int)__cvta_generic_to_shared(p);
}
__device__ __forceinline__ void cpasync16(unsigned int saddr, const void* g) {
  asm volatile("cp.async.ca.shared.global [%0], [%1], 16;" ::"r"(saddr), "l"(g));
}
__device__ __forceinline__ void cpasync_commit() {
  asm volatile("cp.async.commit_group;" ::: "memory");
}
__device__ __forceinline__ void cpasync_wait1() {
  asm volatile("cp.async.wait_group 1;" ::: "memory");
}
__device__ __forceinline__ void cpasync_wait0() {
  asm volatile("cp.async.wait_group 0;" ::: "memory");
}

// Pure streaming copy bert -> out (independent of all other work).
__global__ void k_copy(const float4* __restrict__ src, float4* __restrict__ dst) {
  int i = blockIdx.x * 256 + threadIdx.x;
  dst[i] = src[i];
}

// u1 = Wz @ w1, u2 = Wz @ w2, c = (bz.w1, bz.w2). grid 769, block 256.
__global__ void k_pre(const float* __restrict__ Wz, const float* __restrict__ bz,
                      const float* __restrict__ watt) {
  __shared__ float sm[8];
  int h = blockIdx.x, tid = threadIdx.x;
  float a1 = 0.f, a2 = 0.f;
  if (h < Hdim) {
    const float* wr = Wz + (size_t)h * Hdim;
    for (int k = tid; k < Hdim; k += 256) {
      float wv = wr[k];
      a1 = fmaf(wv, watt[k], a1);
      a2 = fmaf(wv, watt[Hdim + k], a2);
    }
  } else {
    for (int k = tid; k < Hdim; k += 256) {
      float bv = bz[k];
      a1 = fmaf(bv, watt[k], a1);
      a2 = fmaf(bv, watt[Hdim + k], a2);
    }
  }
  float r1 = blockReduceSum(a1, sm);
  float r2 = blockReduceSum(a2, sm);
  if (tid == 0) {
    if (h < Hdim) {
      g_u1[h] = r1;
      g_u2[h] = r2;
    } else {
      g_c[0] = r1;
      g_c[1] = r2;
    }
  }
}

// t2[r] = bert_row[r] @ u2 + bz.w2. grid 512, block 256 (one warp per row).
__global__ void k_t2d(const float* __restrict__ bert) {
  int r = blockIdx.x * 8 + (threadIdx.x >> 5);
  int lane = threadIdx.x & 31;
  const float4* br = (const float4*)(bert + (size_t)r * Hdim);
  const float4* u24 = (const float4*)g_u2;
  float a = 0.f;
#pragma unroll
  for (int k = lane; k < H4; k += 32) {
    float4 bv = br[k];
    float4 uv = u24[k];
    a = fmaf(bv.x, uv.x, a);
    a = fmaf(bv.y, uv.y, a);
    a = fmaf(bv.z, uv.z, a);
    a = fmaf(bv.w, uv.w, a);
  }
  a = warpReduceSum(a);
  if (lane == 0) g_t2[r] = a + g_c[1];
}

// Per needed row: logits + softmax + agg_d + v (attn-weighted bert) + bert_next.
// grid (16, 8), block 1024 (32 warps — latency coverage).
__global__ void __launch_bounds__(1024) k_main(
    const float* __restrict__ bert, const float* __restrict__ dta,
    const int* __restrict__ deprel, const int* __restrict__ asp_s,
    const int* __restrict__ asp_e, const float* __restrict__ w_att,
    const float* __restrict__ b_att) {
  int b = blockIdx.x, il = blockIdx.y;
  int slot = b * 8 + il;
  int tid = threadIdx.x;
  __shared__ float sm_s[Sdim];
  __shared__ float sm_p[Sdim];
  __shared__ float sm_red[32];
  __shared__ float sm_agg[1024];
  __shared__ float4 sm_v[4][192];

  int start = asp_s[b], endi = asp_e[b];
  int i = start + il;
  bool active = (i <= endi) && (i < Sdim);
  const int* deprow = deprel + (size_t)(b * Sdim + (active ? i : 0)) * Sdim;
  int hasn = 0;
  if (active && tid < Sdim) hasn = (deprow[tid] > 0);
  int any = __syncthreads_or(hasn);
  if (!active || !any) {
    if (tid < Hdim) {
      g_X1[slot * Hdim + tid] = 0.f;
      g_X1[(NSLOT + slot) * Hdim + tid] = 0.f;
    }
    if (tid < Ddim) g_X2[slot * (Hdim + Ddim) + Hdim + tid] = 0.f;
    if (tid == 0) {
      g_valid[slot] = 0;
      g_rowi[slot] = 0;
    }
    return;
  }

  int inext = (i + 1) & (Sdim - 1);
  const float* bi = bert + (size_t)(b * Sdim + inext) * Hdim;

  // s1 = bert[b,i+1] @ u1 (one float per thread, 768 active)
  float a = (tid < Hdim) ? bi[tid] * g_u1[tid] : 0.f;
  float s1 = blockReduceSum32(a, sm_red);
  float base = s1 + g_c[0] + b_att[0];

  // logits: 4 threads per j, each 4 LDG.128, quad shfl reduce.
  const float* drow = dta + (size_t)(b * Sdim + i) * Sdim * Ddim;
  {
    int j = tid >> 2, q = tid & 3;
    const float4* dj = (const float4*)(drow + (size_t)j * Ddim) + q * 4;
    const float4* w34 = (const float4*)(w_att + 2 * Hdim) + q * 4;
    float acc = 0.f;
#pragma unroll
    for (int k = 0; k < 4; ++k) {
      float4 d = dj[k];
      float4 w = w34[k];
      acc = fmaf(d.x, w.x, acc);
      acc = fmaf(d.y, w.y, acc);
      acc = fmaf(d.z, w.z, acc);
      acc = fmaf(d.w, w.w, acc);
    }
    acc += __shfl_xor_sync(0xffffffffu, acc, 1);
    acc += __shfl_xor_sync(0xffffffffu, acc, 2);
    if (q == 0) {
      float s = base + g_t2[b * Sdim + ((j + 1) & (Sdim - 1))] + acc;
      s = (s >= 0.f) ? s : 0.01f * s;
      if (deprow[j] <= 0) s = -1e9f;
      sm_s[j] = s;
    }
  }
  __syncthreads();

  // softmax over 256 j (only tid<256 contribute)
  float sv = (tid < Sdim) ? sm_s[tid] : -1e30f;
  float m = blockReduceMax32(sv, sm_red);
  float e = (tid < Sdim) ? expf(sv - m) : 0.f;
  float sum = blockReduceSum32(e, sm_red);
  if (tid < Sdim) sm_p[tid] = e / sum;
  __syncthreads();

  // agg_d[d] = sum_j p[j] * dta[b,i,j,d] : 16 j-parts x 64 d
  {
    int d = tid & 63, part = tid >> 6;  // part 0..15
    float ad = 0.f;
    const float* dp = drow + (size_t)(part * 16) * Ddim + d;
#pragma unroll
    for (int jj = 0; jj < 16; ++jj)
      ad = fmaf(sm_p[part * 16 + jj], dp[(size_t)jj * Ddim], ad);
    sm_agg[tid] = ad;
    __syncthreads();
    if (tid < Ddim) {
      float t = 0.f;
#pragma unroll
      for (int p = 0; p < 16; ++p) t += sm_agg[p * 64 + tid];
      g_X2[slot * (Hdim + Ddim) + Hdim + tid] = t;
    }
  }

  // v[h] = sum_j p[j] * bert[b,(j+1)%S,h] : 4 j-groups x 192 float4 lanes
  {
    int g = tid >> 8, c = tid & 255;
    const float4* bb4 = (const float4*)(bert + (size_t)b * Sdim * Hdim);
    if (c < H4) {
      float4 acc4 = make_float4(0.f, 0.f, 0.f, 0.f);
#pragma unroll 8
      for (int jj = 0; jj < 64; ++jj) {
        int j = g * 64 + jj;
        float p = sm_p[j];
        float4 bv = bb4[(size_t)((j + 1) & (Sdim - 1)) * H4 + c];
        acc4.x = fmaf(p, bv.x, acc4.x);
        acc4.y = fmaf(p, bv.y, acc4.y);
        acc4.z = fmaf(p, bv.z, acc4.z);
        acc4.w = fmaf(p, bv.w, acc4.w);
      }
      sm_v[g][c] = acc4;
    }
    __syncthreads();
    if (tid < H4) {
      float4 v0 = sm_v[0][tid], v1 = sm_v[1][tid], v2 = sm_v[2][tid],
             v3 = sm_v[3][tid];
      float4 v = make_float4(v0.x + v1.x + v2.x + v3.x, v0.y + v1.y + v2.y + v3.y,
                             v0.z + v1.z + v2.z + v3.z, v0.w + v1.w + v2.w + v3.w);
      ((float4*)g_X1)[slot * H4 + tid] = v;
      ((float4*)g_X1)[(NSLOT + slot) * H4 + tid] = ((const float4*)bi)[tid];
    }
  }
  if (tid == 0) {
    g_valid[slot] = 1;
    g_rowi[slot] = i;
  }
}

// One k-component into 4 accumulator rows: splat X rows, 2 FFMA2 (4 cols) each.
#define FMAK4(C, WV, A0, A1, A2, A3)  \
  do {                                \
    unsigned long long s;             \
    s = splat2(x0.C);                 \
    ffma2(A0##l, s, (WV).x);          \
    ffma2(A0##h, s, (WV).y);          \
    s = splat2(x1.C);                 \
    ffma2(A1##l, s, (WV).x);          \
    ffma2(A1##h, s, (WV).y);          \
    s = splat2(x2.C);                 \
    ffma2(A2##l, s, (WV).x);          \
    ffma2(A2##h, s, (WV).y);          \
    s = splat2(x3.C);                 \
    ffma2(A3##l, s, (WV).x);          \
    ffma2(A3##h, s, (WV).y);          \
  } while (0)

// cp.async smem-staged partial GEMM, packed f32x2, 4 cols x 8 rows per thread.
// Block 256 = 16 ct x 16 rt -> tile 64 cols x 128 rows. K-tile 32, double-buffered.
template <int KS, int LDX, int NIT, int NROWS>
__global__ void __launch_bounds__(256) k_sgemm(const float* __restrict__ X,
                                               const float* __restrict__ W,
                                               float* __restrict__ P) {
  static_assert(KS == NIT * 32, "");
  __shared__ __align__(16) float sW[2][32 * 64];   // 16 KB
  __shared__ __align__(16) float sX[2][128 * 32];  // 32 KB

  int tid = threadIdx.x;
  int ct = tid & 15, rt = tid >> 4;
  int hb = blockIdx.x * 64;
  int rb = blockIdx.y * 128;
  int z = blockIdx.z;

  const float* Wg = W + (size_t)z * KS * Hdim + hb;
  const float* Xg = X + (size_t)rb * LDX + (size_t)z * KS;

  int wi = tid >> 4, wj = (tid & 15) * 4;
  int xi = tid >> 3, xj = (tid & 7) * 4;
  unsigned int sw0 = saddr_of(&sW[0][0]);
  unsigned int sx0 = saddr_of(&sX[0][0]);

#define LOAD_STAGE(stage, buf)                                                  \
  do {                                                                          \
    int k0 = (stage) * 32;                                                      \
    unsigned int swb = sw0 + (buf) * (32 * 64 * 4);                             \
    unsigned int sxb = sx0 + (buf) * (128 * 32 * 4);                            \
    cpasync16(swb + (wi * 64 + wj) * 4, Wg + (size_t)(k0 + wi) * Hdim + wj);    \
    cpasync16(swb + ((wi + 16) * 64 + wj) * 4,                                  \
              Wg + (size_t)(k0 + wi + 16) * Hdim + wj);                         \
    cpasync16(sxb + (xi * 32 + xj) * 4, Xg + (size_t)xi * LDX + k0 + xj);       \
    cpasync16(sxb + ((xi + 32) * 32 + xj) * 4,                                  \
              Xg + (size_t)(xi + 32) * LDX + k0 + xj);                          \
    cpasync16(sxb + ((xi + 64) * 32 + xj) * 4,                                  \
              Xg + (size_t)(xi + 64) * LDX + k0 + xj);                          \
    cpasync16(sxb + ((xi + 96) * 32 + xj) * 4,                                  \
              Xg + (size_t)(xi + 96) * LDX + k0 + xj);                          \
    cpasync_commit();                                                           \
  } while (0)

  LOAD_STAGE(0, 0);
  if (NIT > 1) LOAD_STAGE(1, 1);

  unsigned long long a0l = 0, a0h = 0, a1l = 0, a1h = 0;
  unsigned long long a2l = 0, a2h = 0, a3l = 0, a3h = 0;
  unsigned long long a4l = 0, a4h = 0, a5l = 0, a5h = 0;
  unsigned long long a6l = 0, a6h = 0, a7l = 0, a7h = 0;
  int r0 = rt * 8;

#pragma unroll 1
  for (int it = 0; it < NIT; ++it) {
    if (it < NIT - 1)
      cpasync_wait1();
    else
      cpasync_wait0();
    __syncthreads();
    int buf = it & 1;
    const float* xbase = &sX[buf][0];
    const float* wb = &sW[buf][ct * 4];
#pragma unroll
    for (int k4 = 0; k4 < 8; ++k4) {
      ulonglong2 w0 = *(const ulonglong2*)(wb + (k4 * 4 + 0) * 64);
      ulonglong2 w1 = *(const ulonglong2*)(wb + (k4 * 4 + 1) * 64);
      ulonglong2 w2 = *(const ulonglong2*)(wb + (k4 * 4 + 2) * 64);
      ulonglong2 w3 = *(const ulonglong2*)(wb + (k4 * 4 + 3) * 64);
      {
        float4 x0 = *(const float4*)(xbase + (r0 + 0) * 32 + k4 * 4);
        float4 x1 = *(const float4*)(xbase + (r0 + 1) * 32 + k4 * 4);
        float4 x2 = *(const float4*)(xbase + (r0 + 2) * 32 + k4 * 4);
        float4 x3 = *(const float4*)(xbase + (r0 + 3) * 32 + k4 * 4);
        FMAK4(x, w0, a0, a1, a2, a3);
        FMAK4(y, w1, a0, a1, a2, a3);
        FMAK4(z, w2, a0, a1, a2, a3);
        FMAK4(w, w3, a0, a1, a2, a3);
      }
      {
        float4 x0 = *(const float4*)(xbase + (r0 + 4) * 32 + k4 * 4);
        float4 x1 = *(const float4*)(xbase + (r0 + 5) * 32 + k4 * 4);
        float4 x2 = *(const float4*)(xbase + (r0 + 6) * 32 + k4 * 4);
        float4 x3 = *(const float4*)(xbase + (r0 + 7) * 32 + k4 * 4);
        FMAK4(x, w0, a4, a5, a6, a7);
        FMAK4(y, w1, a4, a5, a6, a7);
        FMAK4(z, w2, a4, a5, a6, a7);
        FMAK4(w, w3, a4, a5, a6, a7);
      }
    }
    __syncthreads();
    if (it + 2 < NIT) LOAD_STAGE(it + 2, buf);
  }
#undef LOAD_STAGE

  int r = rb + r0;
  float* pr = P + ((size_t)(z * NROWS + r)) * Hdim + hb + ct * 4;
#define STORE_ROW(q, A)                                 \
  {                                                     \
    float2 fl = u2f(A##l), fh = u2f(A##h);              \
    *(float4*)(pr + (q)*Hdim) = make_float4(fl.x, fl.y, fh.x, fh.y); \
  }
  STORE_ROW(0, a0)
  STORE_ROW(1, a1)
  STORE_ROW(2, a2)
  STORE_ROW(3, a3)
  STORE_ROW(4, a4)
  STORE_ROW(5, a5)
  STORE_ROW(6, a6)
  STORE_ROW(7, a7)
#undef STORE_ROW
}

// Epilogue: combine NZ K-split partials and route per MODE. block 192.
template <int NZ, int NROWS, int MODE>
__global__ void k_epi(const float* __restrict__ bias, float* __restrict__ outp) {
  int r = blockIdx.x;
  if (MODE == 2 && !g_valid[r]) return;
  int h = threadIdx.x * 4;
  float4 v = make_float4(0.f, 0.f, 0.f, 0.f);
#pragma unroll
  for (int zz = 0; zz < NZ; ++zz) {
    const float4 p = *(const float4*)(g_P + (size_t)(zz * NROWS + r) * Hdim + h);
    v.x += p.x;
    v.y += p.y;
    v.z += p.z;
    v.w += p.w;
  }
  if (MODE == 0) {
    const float4 bb = *(const float4*)(bias + h);
    v.x += bb.x;
    v.y += bb.y;
    v.z += bb.z;
    v.w += bb.w;
    if (r < NSLOT)
      *(float4*)(g_X2 + (size_t)r * (Hdim + Ddim) + h) = v;  // agg_z
    else
      *(float4*)(g_X3 + (size_t)(r - NSLOT) * (2 * Hdim) + Hdim + h) = v;  // zrow
  } else if (MODE == 1) {
    *(float4*)(g_X3 + (size_t)r * (2 * Hdim) + h) = v;  // nrep
  } else {
    int bb = r >> 3;
    int o = (g_rowi[r] + 1) & (Sdim - 1);
    *(float4*)(outp + ((size_t)(bb * Sdim + o)) * Hdim + h) = v;
  }
}

extern "C" void kernel_launch(void* const* d_in, const int* in_sizes, int n_in,
                              void* d_out, int out_size) {
  const float* bert = (const float*)d_in[0];
  const float* dta = (const float*)d_in[1];
  const int* deprel = (const int*)d_in[2];
  const int* asp_s = (const int*)d_in[3];
  const int* asp_e = (const int*)d_in[4];
  const float* Wz = (const float*)d_in[5];
  const float* bz = (const float*)d_in[6];
  const float* watt = (const float*)d_in[7];
  const float* batt = (const float*)d_in[8];
  const float* Wf = (const float*)d_in[9];
  const float* Wh = (const float*)d_in[10];
  float* out = (float*)d_out;

  float* P;
  float* X1;
  float* X2;
  float* X3;
  cudaGetSymbolAddress((void**)&P, g_P);
  cudaGetSymbolAddress((void**)&X1, g_X1);
  cudaGetSymbolAddress((void**)&X2, g_X2);
  cudaGetSymbolAddress((void**)&X3, g_X3);

  // Fork: independent bulk copy bert -> out on side stream (joined before epi2).
  cudaEventRecord(g_evFork, 0);
  cudaStreamWaitEvent(g_s2, g_evFork, 0);
  k_copy<<<(Bdim * Sdim * Hdim / 4) / 256, 256, 0, g_s2>>>((const float4*)bert,
                                                           (float4*)out);
  cudaEventRecord(g_evCopy, g_s2);

  k_pre<<<769, 256>>>(Wz, bz, watt);
  k_t2d<<<(Bdim * Sdim) / 8, 256>>>(bert);
  k_main<<<dim3(Bdim, 8), 1024>>>(bert, dta, deprel, asp_s, asp_e, watt, batt);

  // mode 0: [v; bert_next](256 x 768) @ Wz   K=768 split 12 -> 288 blocks
  k_sgemm<64, Hdim, 2, 256><<<dim3(12, 2, 12), 256>>>(X1, Wz, P);
  k_epi<12, 256, 0><<<256, 192>>>(bz, nullptr);
  // mode 1: X2(128 x 832) @ Wf   K=832 split 13 -> 156 blocks
  k_sgemm<64, Hdim + Ddim, 2, 128><<<dim3(12, 1, 13), 256>>>(X2, Wf, P);
  k_epi<13, 128, 1><<<128, 192>>>(nullptr, nullptr);
  // mode 2: X3(128 x 1536) @ Wh   K=1536 split 24 -> 288 blocks
  k_sgemm<64, 2 * Hdim, 2, 128><<<dim3(12, 1, 24), 256>>>(X3, Wh, P);
  // Join: out rows must be pre-filled by k_copy before epi2 overwrites them.
  cudaStreamWaitEvent(0, g_evCopy, 0);
  k_epi<24, 128, 2><<<128, 192>>>(nullptr, out);
}

// round 11
// speedup vs baseline: 4.2862x; 1.0535x over previous
#include <cuda_runtime.h>
#include <cstdint>

#define Bdim 16
#define Sdim 256
#define Hdim 768
#define Ddim 64
#define NSLOT 128  // 16 batches * 8 slots (max aspect span is 6 rows)
#define H4 (Hdim / 4)

// Scratch (device globals; no allocation allowed)
__device__ __align__(16) float g_u1[Hdim];              // Wz @ w1
__device__ __align__(16) float g_u2[Hdim];              // Wz @ w2
__device__ float g_c[2];                                // bz.w1, bz.w2
__device__ __align__(16) float g_t2[Bdim * Sdim];       // (z @ w2)[b,j]
__device__ __align__(16) float g_attn[NSLOT * Sdim];    // softmax probs per slot
__device__ __align__(16) float g_X1[2 * NSLOT * Hdim];  // rows 0..127: v; 128..255: bert_next
__device__ __align__(16) float g_X2[NSLOT * (Hdim + Ddim)];  // [agg_z | agg_d]
__device__ __align__(16) float g_X3[NSLOT * (2 * Hdim)];     // [nrep | zrow]
__device__ __align__(16) float g_P[3328 * Hdim];             // partial sums (v + K-split)
__device__ int g_valid[NSLOT];
__device__ int g_rowi[NSLOT];

// k_att dynamic smem layout (floats): [0,68*256) staged dta row; then s(256),
// p(256), red(32), agg(1024).
#define ATT_SMEM_FLOATS (68 * 256 + 256 + 256 + 32 + 1024)

__global__ void __launch_bounds__(1024) k_att(const float*, const float*,
                                              const int*, const int*, const int*,
                                              const float*, const float*);

// Host-side stream/event resources, created once at load time (no device memory).
static cudaStream_t g_s2;
static cudaEvent_t g_evFork, g_evCopy;
namespace {
struct HostInit {
  HostInit() {
    cudaStreamCreateWithFlags(&g_s2, cudaStreamNonBlocking);
    cudaEventCreateWithFlags(&g_evFork, cudaEventDisableTiming);
    cudaEventCreateWithFlags(&g_evCopy, cudaEventDisableTiming);
    cudaFuncSetAttribute(k_att, cudaFuncAttributeMaxDynamicSharedMemorySize,
                         ATT_SMEM_FLOATS * 4);
  }
};
HostInit g_hostInit;
}  // namespace

__device__ __forceinline__ float warpReduceSum(float v) {
#pragma unroll
  for (int o = 16; o > 0; o >>= 1) v += __shfl_down_sync(0xffffffffu, v, o);
  return v;
}
__device__ __forceinline__ float warpReduceMax(float v) {
#pragma unroll
  for (int o = 16; o > 0; o >>= 1) v = fmaxf(v, __shfl_down_sync(0xffffffffu, v, o));
  return v;
}

// 256-thread (8-warp) block reductions
__device__ __forceinline__ float blockReduceSum(float v, float* sm) {
  v = warpReduceSum(v);
  int w = threadIdx.x >> 5;
  if ((threadIdx.x & 31) == 0) sm[w] = v;
  __syncthreads();
  if (threadIdx.x < 8) {
    float x = sm[threadIdx.x];
#pragma unroll
    for (int o = 4; o > 0; o >>= 1) x += __shfl_down_sync(0xffu, x, o);
    if (threadIdx.x == 0) sm[0] = x;
  }
  __syncthreads();
  float r = sm[0];
  __syncthreads();
  return r;
}

// 1024-thread (32-warp) block reductions
__device__ __forceinline__ float blockReduceSum32(float v, float* sm) {
  v = warpReduceSum(v);
  int w = threadIdx.x >> 5;
  if ((threadIdx.x & 31) == 0) sm[w] = v;
  __syncthreads();
  if (threadIdx.x < 32) {
    float x = warpReduceSum(sm[threadIdx.x]);
    if (threadIdx.x == 0) sm[0] = x;
  }
  __syncthreads();
  float r = sm[0];
  __syncthreads();
  return r;
}
__device__ __forceinline__ float blockReduceMax32(float v, float* sm) {
  v = warpReduceMax(v);
  int w = threadIdx.x >> 5;
  if ((threadIdx.x & 31) == 0) sm[w] = v;
  __syncthreads();
  if (threadIdx.x < 32) {
    float x = warpReduceMax(sm[threadIdx.x]);
    if (threadIdx.x == 0) sm[0] = x;
  }
  __syncthreads();
  float r = sm[0];
  __syncthreads();
  return r;
}

// ---- packed f32x2 helpers (FFMA2 only reachable via PTX on sm_103a) ----
__device__ __forceinline__ unsigned long long splat2(float x) {
  unsigned long long r;
  asm("mov.b64 %0, {%1, %2};" : "=l"(r) : "f"(x), "f"(x));
  return r;
}
__device__ __forceinline__ void ffma2(unsigned long long& a, unsigned long long x,
                                      unsigned long long w) {
  asm("fma.rn.f32x2 %0, %1, %2, %0;" : "+l"(a) : "l"(x), "l"(w));
}
__device__ __forceinline__ float2 u2f(unsigned long long v) {
  float2 f;
  asm("mov.b64 {%0, %1}, %2;" : "=f"(f.x), "=f"(f.y) : "l"(v));
  return f;
}

// ---- cp.async helpers ----
__device__ __forceinline__ unsigned int saddr_of(const void* p) {
  return (unsigned int)__cvta_generic_to_shared(p);
}
__device__ __forceinline__ void cpasync16(unsigned int saddr, const void* g) {
  asm volatile("cp.async.ca.shared.global [%0], [%1], 16;" ::"r"(saddr), "l"(g));
}
__device__ __forceinline__ void cpasync_commit() {
  asm volatile("cp.async.commit_group;" ::: "memory");
}
__device__ __forceinline__ void cpasync_wait1() {
  asm volatile("cp.async.wait_group 1;" ::: "memory");
}
__device__ __forceinline__ void cpasync_wait0() {
  asm volatile("cp.async.wait_group 0;" ::: "memory");
}

// Pure streaming copy bert -> out (independent of all other work).
__global__ void k_copy(const float4* __restrict__ src, float4* __restrict__ dst) {
  int i = blockIdx.x * 256 + threadIdx.x;
  dst[i] = src[i];
}

// u1 = Wz @ w1, u2 = Wz @ w2, c = (bz.w1, bz.w2). grid 769, block 256.
__global__ void k_pre(const float* __restrict__ Wz, const float* __restrict__ bz,
                      const float* __restrict__ watt) {
  __shared__ float sm[8];
  int h = blockIdx.x, tid = threadIdx.x;
  float a1 = 0.f, a2 = 0.f;
  if (h < Hdim) {
    const float* wr = Wz + (size_t)h * Hdim;
    for (int k = tid; k < Hdim; k += 256) {
      float wv = wr[k];
      a1 = fmaf(wv, watt[k], a1);
      a2 = fmaf(wv, watt[Hdim + k], a2);
    }
  } else {
    for (int k = tid; k < Hdim; k += 256) {
      float bv = bz[k];
      a1 = fmaf(bv, watt[k], a1);
      a2 = fmaf(bv, watt[Hdim + k], a2);
    }
  }
  float r1 = blockReduceSum(a1, sm);
  float r2 = blockReduceSum(a2, sm);
  if (tid == 0) {
    if (h < Hdim) {
      g_u1[h] = r1;
      g_u2[h] = r2;
    } else {
      g_c[0] = r1;
      g_c[1] = r2;
    }
  }
}

// t2[r] = bert_row[r] @ u2 + bz.w2. grid 512, block 256 (one warp per row).
__global__ void k_t2d(const float* __restrict__ bert) {
  int r = blockIdx.x * 8 + (threadIdx.x >> 5);
  int lane = threadIdx.x & 31;
  const float4* br = (const float4*)(bert + (size_t)r * Hdim);
  const float4* u24 = (const float4*)g_u2;
  float a = 0.f;
#pragma unroll
  for (int k = lane; k < H4; k += 32) {
    float4 bv = br[k];
    float4 uv = u24[k];
    a = fmaf(bv.x, uv.x, a);
    a = fmaf(bv.y, uv.y, a);
    a = fmaf(bv.z, uv.z, a);
    a = fmaf(bv.w, uv.w, a);
  }
  a = warpReduceSum(a);
  if (lane == 0) g_t2[r] = a + g_c[1];
}

// Attention per needed row: cp.async-stage the 64KB dta row into smem
// (overlapped with s1), then logits + softmax + agg_d entirely from smem.
// grid (16, 8), block 1024, ~76KB dynamic smem.
__global__ void __launch_bounds__(1024) k_att(
    const float* __restrict__ bert, const float* __restrict__ dta,
    const int* __restrict__ deprel, const int* __restrict__ asp_s,
    const int* __restrict__ asp_e, const float* __restrict__ w_att,
    const float* __restrict__ b_att) {
  extern __shared__ float dyns[];
  float* sD = dyns;                    // 256 rows x 68 floats (padded dta row)
  float* sm_s = dyns + 68 * 256;       // 256
  float* sm_p = sm_s + 256;            // 256
  float* sm_red = sm_p + 256;          // 32
  float* sm_agg = sm_red + 32;         // 1024

  int b = blockIdx.x, il = blockIdx.y;
  int slot = b * 8 + il;
  int tid = threadIdx.x;

  int start = asp_s[b], endi = asp_e[b];
  int i = start + il;
  bool active = (i <= endi) && (i < Sdim);
  const int* deprow = deprel + (size_t)(b * Sdim + (active ? i : 0)) * Sdim;
  int hasn = 0;
  if (active && tid < Sdim) hasn = (deprow[tid] > 0);
  int any = __syncthreads_or(hasn);
  if (!active || !any) {
    if (tid < Sdim) g_attn[slot * Sdim + tid] = 0.f;
    if (tid < Ddim) g_X2[slot * (Hdim + Ddim) + Hdim + tid] = 0.f;
    if (tid == 0) {
      g_valid[slot] = 0;
      g_rowi[slot] = 0;
    }
    return;
  }

  // stage dta row (4096 float4 -> padded smem rows of 17 float4)
  const float4* drow4 = (const float4*)(dta + (size_t)(b * Sdim + i) * Sdim * Ddim);
#pragma unroll
  for (int t = tid; t < 4096; t += 1024) {
    int j = t >> 4, q = t & 15;
    cpasync16(saddr_of(sD + j * 68 + q * 4), drow4 + t);
  }
  cpasync_commit();

  int inext = (i + 1) & (Sdim - 1);
  const float* bi = bert + (size_t)(b * Sdim + inext) * Hdim;

  // s1 = bert[b,i+1] @ u1 (overlapped with the cp.async stage)
  float a = (tid < Hdim) ? bi[tid] * g_u1[tid] : 0.f;
  float s1 = blockReduceSum32(a, sm_red);
  float base = s1 + g_c[0] + b_att[0];

  cpasync_wait0();
  __syncthreads();

  // logits from smem: 4 threads per j
  {
    int j = tid >> 2, q = tid & 3;
    const float4* dj = (const float4*)(sD + j * 68) + q * 4;
    const float4* w34 = (const float4*)(w_att + 2 * Hdim) + q * 4;
    float acc = 0.f;
#pragma unroll
    for (int k = 0; k < 4; ++k) {
      float4 d = dj[k];
      float4 w = w34[k];
      acc = fmaf(d.x, w.x, acc);
      acc = fmaf(d.y, w.y, acc);
      acc = fmaf(d.z, w.z, acc);
      acc = fmaf(d.w, w.w, acc);
    }
    acc += __shfl_xor_sync(0xffffffffu, acc, 1);
    acc += __shfl_xor_sync(0xffffffffu, acc, 2);
    if (q == 0) {
      float s = base + g_t2[b * Sdim + ((j + 1) & (Sdim - 1))] + acc;
      s = (s >= 0.f) ? s : 0.01f * s;
      if (deprow[j] <= 0) s = -1e9f;
      sm_s[j] = s;
    }
  }
  __syncthreads();

  // softmax
  float sv = (tid < Sdim) ? sm_s[tid] : -1e30f;
  float m = blockReduceMax32(sv, sm_red);
  float e = (tid < Sdim) ? expf(sv - m) : 0.f;
  float sum = blockReduceSum32(e, sm_red);
  if (tid < Sdim) {
    float p = e / sum;
    sm_p[tid] = p;
    g_attn[slot * Sdim + tid] = p;
  }
  __syncthreads();

  // agg_d from smem: 16 j-parts x 64 d
  {
    int d = tid & 63, part = tid >> 6;
    float ad = 0.f;
    const float* dp = sD + (size_t)(part * 16) * 68 + d;
#pragma unroll
    for (int jj = 0; jj < 16; ++jj) ad = fmaf(sm_p[part * 16 + jj], dp[jj * 68], ad);
    sm_agg[tid] = ad;
    __syncthreads();
    if (tid < Ddim) {
      float t = 0.f;
#pragma unroll
      for (int p = 0; p < 16; ++p) t += sm_agg[p * 64 + tid];
      g_X2[slot * (Hdim + Ddim) + Hdim + tid] = t;
    }
  }
  if (tid == 0) {
    g_valid[slot] = 1;
    g_rowi[slot] = i;
  }
}

// v partials: block (slot, g) accumulates sum over 32 j's of p[j]*bert[b,j+1,:].
// grid (128, 8), block 192 (float4 lanes). Partials into g_P[(g*128+slot)].
__global__ void __launch_bounds__(192) k_v(const float* __restrict__ bert) {
  int slot = blockIdx.x, g = blockIdx.y;
  int b = slot >> 3;
  int tid = threadIdx.x;
  __shared__ float sp[32];
  if (tid < 32) sp[tid] = g_attn[slot * Sdim + g * 32 + tid];
  __syncthreads();
  const float4* bb4 = (const float4*)(bert + (size_t)b * Sdim * Hdim);
  float4 acc = make_float4(0.f, 0.f, 0.f, 0.f);
#pragma unroll 8
  for (int jj = 0; jj < 32; ++jj) {
    int j = g * 32 + jj;
    float p = sp[jj];
    float4 bv = bb4[(size_t)((j + 1) & (Sdim - 1)) * H4 + tid];
    acc.x = fmaf(p, bv.x, acc.x);
    acc.y = fmaf(p, bv.y, acc.y);
    acc.z = fmaf(p, bv.z, acc.z);
    acc.w = fmaf(p, bv.w, acc.w);
  }
  ((float4*)g_P)[(size_t)(g * NSLOT + slot) * H4 + tid] = acc;
}

// Sum the 8 v-partials -> X1[slot]; also write bert_next -> X1[NSLOT+slot].
// grid 128, block 192.
__global__ void __launch_bounds__(192) k_vsum(const float* __restrict__ bert) {
  int slot = blockIdx.x;
  int tid = threadIdx.x;
  float4 v = make_float4(0.f, 0.f, 0.f, 0.f);
#pragma unroll
  for (int g = 0; g < 8; ++g) {
    float4 p = ((const float4*)g_P)[(size_t)(g * NSLOT + slot) * H4 + tid];
    v.x += p.x;
    v.y += p.y;
    v.z += p.z;
    v.w += p.w;
  }
  ((float4*)g_X1)[slot * H4 + tid] = v;
  int b = slot >> 3;
  int inext = (g_rowi[slot] + 1) & (Sdim - 1);
  ((float4*)g_X1)[(NSLOT + slot) * H4 + tid] =
      ((const float4*)(bert + (size_t)(b * Sdim + inext) * Hdim))[tid];
}

// One k-component into 4 accumulator rows: splat X rows, 2 FFMA2 (4 cols) each.
#define FMAK4(C, WV, A0, A1, A2, A3)  \
  do {                                \
    unsigned long long s;             \
    s = splat2(x0.C);                 \
    ffma2(A0##l, s, (WV).x);          \
    ffma2(A0##h, s, (WV).y);          \
    s = splat2(x1.C);                 \
    ffma2(A1##l, s, (WV).x);          \
    ffma2(A1##h, s, (WV).y);          \
    s = splat2(x2.C);                 \
    ffma2(A2##l, s, (WV).x);          \
    ffma2(A2##h, s, (WV).y);          \
    s = splat2(x3.C);                 \
    ffma2(A3##l, s, (WV).x);          \
    ffma2(A3##h, s, (WV).y);          \
  } while (0)

// cp.async smem-staged partial GEMM, packed f32x2, 4 cols x 8 rows per thread.
// Block 256 = 16 ct x 16 rt -> tile 64 cols x 128 rows. K-tile 32, double-buffered.
template <int KS, int LDX, int NIT, int NROWS>
__global__ void __launch_bounds__(256) k_sgemm(const float* __restrict__ X,
                                               const float* __restrict__ W,
                                               float* __restrict__ P) {
  static_assert(KS == NIT * 32, "");
  __shared__ __align__(16) float sW[2][32 * 64];   // 16 KB
  __shared__ __align__(16) float sX[2][128 * 32];  // 32 KB

  int tid = threadIdx.x;
  int ct = tid & 15, rt = tid >> 4;
  int hb = blockIdx.x * 64;
  int rb = blockIdx.y * 128;
  int z = blockIdx.z;

  const float* Wg = W + (size_t)z * KS * Hdim + hb;
  const float* Xg = X + (size_t)rb * LDX + (size_t)z * KS;

  int wi = tid >> 4, wj = (tid & 15) * 4;
  int xi = tid >> 3, xj = (tid & 7) * 4;
  unsigned int sw0 = saddr_of(&sW[0][0]);
  unsigned int sx0 = saddr_of(&sX[0][0]);

#define LOAD_STAGE(stage, buf)                                                  \
  do {                                                                          \
    int k0 = (stage) * 32;                                                      \
    unsigned int swb = sw0 + (buf) * (32 * 64 * 4);                             \
    unsigned int sxb = sx0 + (buf) * (128 * 32 * 4);                            \
    cpasync16(swb + (wi * 64 + wj) * 4, Wg + (size_t)(k0 + wi) * Hdim + wj);    \
    cpasync16(swb + ((wi + 16) * 64 + wj) * 4,                                  \
              Wg + (size_t)(k0 + wi + 16) * Hdim + wj);                         \
    cpasync16(sxb + (xi * 32 + xj) * 4, Xg + (size_t)xi * LDX + k0 + xj);       \
    cpasync16(sxb + ((xi + 32) * 32 + xj) * 4,                                  \
              Xg + (size_t)(xi + 32) * LDX + k0 + xj);                          \
    cpasync16(sxb + ((xi + 64) * 32 + xj) * 4,                                  \
              Xg + (size_t)(xi + 64) * LDX + k0 + xj);                          \
    cpasync16(sxb + ((xi + 96) * 32 + xj) * 4,                                  \
              Xg + (size_t)(xi + 96) * LDX + k0 + xj);                          \
    cpasync_commit();                                                           \
  } while (0)

  LOAD_STAGE(0, 0);
  if (NIT > 1) LOAD_STAGE(1, 1);

  unsigned long long a0l = 0, a0h = 0, a1l = 0, a1h = 0;
  unsigned long long a2l = 0, a2h = 0, a3l = 0, a3h = 0;
  unsigned long long a4l = 0, a4h = 0, a5l = 0, a5h = 0;
  unsigned long long a6l = 0, a6h = 0, a7l = 0, a7h = 0;
  int r0 = rt * 8;

#pragma unroll 1
  for (int it = 0; it < NIT; ++it) {
    if (it < NIT - 1)
      cpasync_wait1();
    else
      cpasync_wait0();
    __syncthreads();
    int buf = it & 1;
    const float* xbase = &sX[buf][0];
    const float* wb = &sW[buf][ct * 4];
#pragma unroll
    for (int k4 = 0; k4 < 8; ++k4) {
      ulonglong2 w0 = *(const ulonglong2*)(wb + (k4 * 4 + 0) * 64);
      ulonglong2 w1 = *(const ulonglong2*)(wb + (k4 * 4 + 1) * 64);
      ulonglong2 w2 = *(const ulonglong2*)(wb + (k4 * 4 + 2) * 64);
      ulonglong2 w3 = *(const ulonglong2*)(wb + (k4 * 4 + 3) * 64);
      {
        float4 x0 = *(const float4*)(xbase + (r0 + 0) * 32 + k4 * 4);
        float4 x1 = *(const float4*)(xbase + (r0 + 1) * 32 + k4 * 4);
        float4 x2 = *(const float4*)(xbase + (r0 + 2) * 32 + k4 * 4);
        float4 x3 = *(const float4*)(xbase + (r0 + 3) * 32 + k4 * 4);
        FMAK4(x, w0, a0, a1, a2, a3);
        FMAK4(y, w1, a0, a1, a2, a3);
        FMAK4(z, w2, a0, a1, a2, a3);
        FMAK4(w, w3, a0, a1, a2, a3);
      }
      {
        float4 x0 = *(const float4*)(xbase + (r0 + 4) * 32 + k4 * 4);
        float4 x1 = *(const float4*)(xbase + (r0 + 5) * 32 + k4 * 4);
        float4 x2 = *(const float4*)(xbase + (r0 + 6) * 32 + k4 * 4);
        float4 x3 = *(const float4*)(xbase + (r0 + 7) * 32 + k4 * 4);
        FMAK4(x, w0, a4, a5, a6, a7);
        FMAK4(y, w1, a4, a5, a6, a7);
        FMAK4(z, w2, a4, a5, a6, a7);
        FMAK4(w, w3, a4, a5, a6, a7);
      }
    }
    __syncthreads();
    if (it + 2 < NIT) LOAD_STAGE(it + 2, buf);
  }
#undef LOAD_STAGE

  int r = rb + r0;
  float* pr = P + ((size_t)(z * NROWS + r)) * Hdim + hb + ct * 4;
#define STORE_ROW(q, A)                                 \
  {                                                     \
    float2 fl = u2f(A##l), fh = u2f(A##h);              \
    *(float4*)(pr + (q)*Hdim) = make_float4(fl.x, fl.y, fh.x, fh.y); \
  }
  STORE_ROW(0, a0)
  STORE_ROW(1, a1)
  STORE_ROW(2, a2)
  STORE_ROW(3, a3)
  STORE_ROW(4, a4)
  STORE_ROW(5, a5)
  STORE_ROW(6, a6)
  STORE_ROW(7, a7)
#undef STORE_ROW
}

// Epilogue: combine NZ K-split partials and route per MODE. block 192.
template <int NZ, int NROWS, int MODE>
__global__ void k_epi(const float* __restrict__ bias, float* __restrict__ outp) {
  int r = blockIdx.x;
  if (MODE == 2 && !g_valid[r]) return;
  int h = threadIdx.x * 4;
  float4 v = make_float4(0.f, 0.f, 0.f, 0.f);
#pragma unroll
  for (int zz = 0; zz < NZ; ++zz) {
    const float4 p = *(const float4*)(g_P + (size_t)(zz * NROWS + r) * Hdim + h);
    v.x += p.x;
    v.y += p.y;
    v.z += p.z;
    v.w += p.w;
  }
  if (MODE == 0) {
    const float4 bb = *(const float4*)(bias + h);
    v.x += bb.x;
    v.y += bb.y;
    v.z += bb.z;
    v.w += bb.w;
    if (r < NSLOT)
      *(float4*)(g_X2 + (size_t)r * (Hdim + Ddim) + h) = v;  // agg_z
    else
      *(float4*)(g_X3 + (size_t)(r - NSLOT) * (2 * Hdim) + Hdim + h) = v;  // zrow
  } else if (MODE == 1) {
    *(float4*)(g_X3 + (size_t)r * (2 * Hdim) + h) = v;  // nrep
  } else {
    int bb = r >> 3;
    int o = (g_rowi[r] + 1) & (Sdim - 1);
    *(float4*)(outp + ((size_t)(bb * Sdim + o)) * Hdim + h) = v;
  }
}

extern "C" void kernel_launch(void* const* d_in, const int* in_sizes, int n_in,
                              void* d_out, int out_size) {
  const float* bert = (const float*)d_in[0];
  const float* dta = (const float*)d_in[1];
  const int* deprel = (const int*)d_in[2];
  const int* asp_s = (const int*)d_in[3];
  const int* asp_e = (const int*)d_in[4];
  const float* Wz = (const float*)d_in[5];
  const float* bz = (const float*)d_in[6];
  const float* watt = (const float*)d_in[7];
  const float* batt = (const float*)d_in[8];
  const float* Wf = (const float*)d_in[9];
  const float* Wh = (const float*)d_in[10];
  float* out = (float*)d_out;

  float* P;
  float* X1;
  float* X2;
  float* X3;
  cudaGetSymbolAddress((void**)&P, g_P);
  cudaGetSymbolAddress((void**)&X1, g_X1);
  cudaGetSymbolAddress((void**)&X2, g_X2);
  cudaGetSymbolAddress((void**)&X3, g_X3);

  // Fork: independent bulk copy bert -> out on side stream (joined before epi2).
  cudaEventRecord(g_evFork, 0);
  cudaStreamWaitEvent(g_s2, g_evFork, 0);
  k_copy<<<(Bdim * Sdim * Hdim / 4) / 256, 256, 0, g_s2>>>((const float4*)bert,
                                                           (float4*)out);
  cudaEventRecord(g_evCopy, g_s2);

  k_pre<<<769, 256>>>(Wz, bz, watt);
  k_t2d<<<(Bdim * Sdim) / 8, 256>>>(bert);
  k_att<<<dim3(Bdim, 8), 1024, ATT_SMEM_FLOATS * 4>>>(bert, dta, deprel, asp_s,
                                                      asp_e, watt, batt);
  k_v<<<dim3(NSLOT, 8), 192>>>(bert);
  k_vsum<<<NSLOT, 192>>>(bert);

  // mode 0: [v; bert_next](256 x 768) @ Wz   K=768 split 12 -> 288 blocks
  k_sgemm<64, Hdim, 2, 256><<<dim3(12, 2, 12), 256>>>(X1, Wz, P);
  k_epi<12, 256, 0><<<256, 192>>>(bz, nullptr);
  // mode 1: X2(128 x 832) @ Wf   K=832 split 13 -> 156 blocks
  k_sgemm<64, Hdim + Ddim, 2, 128><<<dim3(12, 1, 13), 256>>>(X2, Wf, P);
  k_epi<13, 128, 1><<<128, 192>>>(nullptr, nullptr);
  // mode 2: X3(128 x 1536) @ Wh   K=1536 split 24 -> 288 blocks
  k_sgemm<64, 2 * Hdim, 2, 128><<<dim3(12, 1, 24), 256>>>(X3, Wh, P);
  // Join: out rows must be pre-filled by k_copy before epi2 overwrites them.
  cudaStreamWaitEvent(0, g_evCopy, 0);
  k_epi<24, 128, 2><<<128, 192>>>(nullptr, out);
}